// round 1
// baseline (speedup 1.0000x reference)
#include <cuda_runtime.h>
#include <math.h>

#define BB 2
#define LL 2048
#define DD 256
#define PP 32
#define NTOK (BB*LL)

// ---------------- scratch (no malloc allowed) ----------------
__device__ float d_cq[NTOK*PP];
__device__ float d_sq[NTOK*PP];
__device__ float d_g [NTOK];
__device__ float d_gc[NTOK];
__device__ float d_vg[NTOK*DD];
__device__ float d_ret[NTOK*DD];
__device__ float d_G1[NTOK*DD];
__device__ float d_h [NTOK*DD];
__device__ float d_t1[NTOK*2*DD];
__device__ float d_t2[NTOK*DD];
__device__ float d_n2[NTOK*DD];

__device__ __forceinline__ float gelu_f(float x){
    return 0.5f*x*(1.0f+erff(x*0.7071067811865476f));
}

// ---------------- zero accumulator ----------------
__global__ void zero_ret_kernel(){
    int i = blockIdx.x*blockDim.x + threadIdx.x;
    if (i < NTOK*DD) d_ret[i] = 0.0f;
}

// ---------------- phases: cq,sq = cos/sin(tanh(x@Wk+bk)*pi) ----------------
__global__ void phases_kernel(const float* __restrict__ x,
                              const float* __restrict__ Wk,
                              const float* __restrict__ bk){
    int tok = blockIdx.x*8 + (threadIdx.x>>5);
    int p   = threadIdx.x & 31;
    const float* xr = x + tok*DD;
    float s = bk[p];
    #pragma unroll 8
    for (int k = 0; k < DD; k++) s += xr[k]*Wk[k*PP + p];
    float ph = tanhf(s)*3.14159265358979323846f;
    float sn, cs;
    sincosf(ph, &sn, &cs);
    d_cq[tok*PP + p] = cs;
    d_sq[tok*PP + p] = sn;
}

// ---------------- generic tiled fp32 GEMM: C = epi(A@W + bias) ----------------
// BM=64, BN=64, BK=16, 256 threads, 4x4 micro-tile per thread.
#define A_PLAIN  0
#define A_CONCAT 1   // A = [x, shift(x)] : K=512
#define E_NONE 0
#define E_GELU 1
#define E_VG   2     // * d_g[row]
#define E_OUT  3     // + extra[row*256+n]  (residual x)

template<int AMODE, int EPI>
__global__ void gemm_kernel(const float* __restrict__ A,
                            const float* __restrict__ W,
                            const float* __restrict__ bias,
                            float* __restrict__ C,
                            const float* __restrict__ extra,
                            int M, int N, int K)
{
    __shared__ __align__(16) float As[64*20];   // [m][k], pitch 20
    __shared__ __align__(16) float Ws[16*64];   // [k][n]

    const int tid = threadIdx.x;
    const int n0 = blockIdx.x*64;
    const int m0 = blockIdx.y*64;
    const int tx = tid & 15;     // n dir
    const int ty = tid >> 4;     // m dir

    float acc[4][4];
    #pragma unroll
    for (int i=0;i<4;i++)
        #pragma unroll
        for (int j=0;j<4;j++) acc[i][j]=0.f;

    const int am = tid >> 2;            // 0..63 (row for A load)
    const int ak = (tid & 3)*4;         // 0,4,8,12
    const int wk = tid >> 4;            // 0..15
    const int wn = (tid & 15)*4;        // 0..60

    for (int k0 = 0; k0 < K; k0 += 16){
        // load A tile (64 x 16)
        {
            int m = m0 + am;
            int kg = k0 + ak;
            float4 v;
            if (AMODE == A_PLAIN){
                v = *(const float4*)&A[(size_t)m*K + kg];
            } else {
                if (kg < DD){
                    v = *(const float4*)&A[(size_t)m*DD + kg];
                } else {
                    int l = m & (LL-1);
                    if (l == 0) v = make_float4(0.f,0.f,0.f,0.f);
                    else        v = *(const float4*)&A[(size_t)(m-1)*DD + (kg-DD)];
                }
            }
            *(float4*)&As[am*20 + ak] = v;
        }
        // load W tile (16 x 64)
        {
            float4 v = *(const float4*)&W[(size_t)(k0+wk)*N + n0 + wn];
            *(float4*)&Ws[wk*64 + wn] = v;
        }
        __syncthreads();

        #pragma unroll
        for (int k = 0; k < 16; k++){
            float a0 = As[(ty*4+0)*20 + k];
            float a1 = As[(ty*4+1)*20 + k];
            float a2 = As[(ty*4+2)*20 + k];
            float a3 = As[(ty*4+3)*20 + k];
            float4 w = *(float4*)&Ws[k*64 + tx*4];
            acc[0][0]+=a0*w.x; acc[0][1]+=a0*w.y; acc[0][2]+=a0*w.z; acc[0][3]+=a0*w.w;
            acc[1][0]+=a1*w.x; acc[1][1]+=a1*w.y; acc[1][2]+=a1*w.z; acc[1][3]+=a1*w.w;
            acc[2][0]+=a2*w.x; acc[2][1]+=a2*w.y; acc[2][2]+=a2*w.z; acc[2][3]+=a2*w.w;
            acc[3][0]+=a3*w.x; acc[3][1]+=a3*w.y; acc[3][2]+=a3*w.z; acc[3][3]+=a3*w.w;
        }
        __syncthreads();
    }

    #pragma unroll
    for (int i=0;i<4;i++){
        int m = m0 + ty*4 + i;
        float4 r;
        float* rp = &r.x;
        #pragma unroll
        for (int j=0;j<4;j++){
            int n = n0 + tx*4 + j;
            float v = acc[i][j] + bias[n];
            if (EPI == E_GELU) v = gelu_f(v);
            if (EPI == E_VG)   v *= extra[m];
            if (EPI == E_OUT)  v += extra[(size_t)m*DD + n];
            rp[j] = v;
        }
        *(float4*)&C[(size_t)m*N + n0 + tx*4] = r;
    }
}

// ---------------- gate2: g = sigmoid(G1 . Wg2 + bg2) ----------------
__global__ void gate2_kernel(const float* __restrict__ Wg2,
                             const float* __restrict__ bg2){
    int tok  = blockIdx.x*8 + (threadIdx.x>>5);
    int lane = threadIdx.x & 31;
    const float* r = d_G1 + (size_t)tok*DD;
    float s = 0.f;
    #pragma unroll
    for (int k = lane; k < DD; k += 32) s += r[k]*Wg2[k];
    #pragma unroll
    for (int o = 16; o; o >>= 1) s += __shfl_xor_sync(0xffffffffu, s, o);
    if (lane == 0) d_g[tok] = 1.f/(1.f + expf(-(s + bg2[0])));
}

// ---------------- per-batch inclusive cumsum of g ----------------
__global__ void cumsum_kernel(){
    int b = blockIdx.x;
    int tid = threadIdx.x;            // 256 threads, 8 elems each
    __shared__ float tot[256];
    float v[8]; float run = 0.f;
    const float* gp = d_g + b*LL + tid*8;
    #pragma unroll
    for (int i=0;i<8;i++){ run += gp[i]; v[i] = run; }
    tot[tid] = run;
    __syncthreads();
    for (int ofs=1; ofs<256; ofs<<=1){
        float t = (tid >= ofs) ? tot[tid-ofs] : 0.f;
        __syncthreads();
        tot[tid] += t;
        __syncthreads();
    }
    float off = tot[tid] - run;   // exclusive prefix
    float* gc = d_gc + b*LL + tid*8;
    #pragma unroll
    for (int i=0;i<8;i++) gc[i] = v[i] + off;
}

// ---------------- causal linear attention ----------------
// grid (64 qtiles, 4 ksplits, B). 32 query rows x 64-key chunks, split-K 512,
// atomicAdd partials into d_ret.
#define TQ 32
#define TK 64
#define KSPLIT 512

__global__ void attn_kernel(){
    extern __shared__ float sm[];
    float* sQ = sm;                 // 32*64
    float* sK = sQ + 32*64;         // 64*65 (padded rows)
    float* sS = sK + 64*65;         // 32*64
    float* sV = sS + 32*64;         // 64*256

    const int qt = blockIdx.x, split = blockIdx.y, b = blockIdx.z;
    const int q0 = qt*TQ;
    const int kstart = split*KSPLIT;
    const int kend = min(kstart + KSPLIT, q0 + TQ);
    if (kstart >= kend) return;

    const int tid = threadIdx.x;
    // load Q~ = [cos | sin] for 32 rows
    for (int i = tid; i < 32*64; i += 256){
        int r = i>>6, c = i&63;
        int tok = b*LL + q0 + r;
        sQ[i] = (c < 32) ? d_cq[tok*PP + c] : d_sq[tok*PP + c - 32];
    }

    float4 acc[8];
    #pragma unroll
    for (int i=0;i<8;i++) acc[i] = make_float4(0.f,0.f,0.f,0.f);

    const int rgrp = tid >> 5;      // 0..7 : rows rgrp*4..+3 (scores)
    const int kg   = tid & 31;      // keys kg*2, kg*2+1      (scores)
    const int dq   = tid & 63;      // d columns dq*4..+3     (AV)
    const int rg   = tid >> 6;      // rows rg*8..+7          (AV)

    const float4* vg4 = (const float4*)d_vg;
    float4* sV4 = (float4*)sV;

    for (int kc0 = kstart; kc0 < kend; kc0 += TK){
        const int nk = min(TK, kend - kc0);
        // load K~ (shifted phasors): sK[t][c], pitch 65
        for (int i = tid; i < 64*64; i += 256){
            int t = i>>6, c = i&63;
            float v = 0.f;
            int kt = kc0 + t;
            if (t < nk && kt >= 1){
                int tok = b*LL + kt - 1;
                v = (c < 32) ? d_cq[tok*PP + c] : d_sq[tok*PP + c - 32];
            }
            sK[t*65 + c] = v;
        }
        // load Vg chunk
        for (int i = tid; i < 64*64; i += 256){
            int t = i>>6, c4 = i&63;
            float4 v = make_float4(0.f,0.f,0.f,0.f);
            if (t < nk) v = vg4[(size_t)(b*LL + kc0 + t)*64 + c4];
            sV4[t*64 + c4] = v;
        }
        __syncthreads();

        // scores: 4 rows x 2 keys per thread over 64 dims
        float s[4][2];
        #pragma unroll
        for (int i=0;i<4;i++){ s[i][0]=0.f; s[i][1]=0.f; }
        const int r0 = rgrp*4, k0 = kg*2;
        #pragma unroll 8
        for (int c = 0; c < 64; c++){
            float kA = sK[k0*65 + c];
            float kB = sK[(k0+1)*65 + c];
            float q0v = sQ[(r0+0)*64 + c];
            float q1v = sQ[(r0+1)*64 + c];
            float q2v = sQ[(r0+2)*64 + c];
            float q3v = sQ[(r0+3)*64 + c];
            s[0][0]+=q0v*kA; s[0][1]+=q0v*kB;
            s[1][0]+=q1v*kA; s[1][1]+=q1v*kB;
            s[2][0]+=q2v*kA; s[2][1]+=q2v*kB;
            s[3][0]+=q3v*kA; s[3][1]+=q3v*kB;
        }
        #pragma unroll
        for (int i=0;i<4;i++){
            int row = q0 + r0 + i;
            #pragma unroll
            for (int j=0;j<2;j++){
                int kt = kc0 + k0 + j;
                sS[(r0+i)*64 + k0 + j] = (kt <= row) ? s[i][j] : 0.f;
            }
        }
        __syncthreads();

        // AV: acc[r8] += S[row][t] * Vg[t][dq*4..+3]
        #pragma unroll 4
        for (int t = 0; t < 64; t++){
            float4 v = sV4[t*64 + dq];
            #pragma unroll
            for (int r8 = 0; r8 < 8; r8++){
                float sv = sS[(rg*8 + r8)*64 + t];
                acc[r8].x += sv*v.x;
                acc[r8].y += sv*v.y;
                acc[r8].z += sv*v.z;
                acc[r8].w += sv*v.w;
            }
        }
        __syncthreads();
    }

    #pragma unroll
    for (int r8 = 0; r8 < 8; r8++){
        int tok = b*LL + q0 + rg*8 + r8;
        float* o = d_ret + (size_t)tok*DD + dq*4;
        atomicAdd(o+0, acc[r8].x);
        atomicAdd(o+1, acc[r8].y);
        atomicAdd(o+2, acc[r8].z);
        atomicAdd(o+3, acc[r8].w);
    }
}

// ---------------- LayerNorm (optionally with retrieval scaling) ----------------
__global__ void ln_kernel(const float* __restrict__ in,
                          const float* __restrict__ gamma,
                          const float* __restrict__ beta,
                          float* __restrict__ out, int scaled){
    int tok = blockIdx.x;
    int d = threadIdx.x;
    __shared__ float red[256];
    __shared__ float mv[2];
    float v = in[(size_t)tok*DD + d];
    if (scaled){
        float gcv = fmaxf(d_gc[tok], 1.0f);
        v *= rsqrtf(gcv) * 0.17677669529663687f;   // 1/sqrt(P)
    }
    red[d] = v; __syncthreads();
    #pragma unroll
    for (int o=128;o;o>>=1){ if (d<o) red[d]+=red[d+o]; __syncthreads(); }
    if (d==0) mv[0] = red[0]*(1.f/256.f);
    __syncthreads();
    float m = mv[0];
    float dv = v - m;
    red[d] = dv*dv; __syncthreads();
    #pragma unroll
    for (int o=128;o;o>>=1){ if (d<o) red[d]+=red[d+o]; __syncthreads(); }
    if (d==0) mv[1] = red[0]*(1.f/256.f);
    __syncthreads();
    float var = mv[1];
    out[(size_t)tok*DD + d] = dv*rsqrtf(var + 1e-5f)*gamma[d] + beta[d];
}

// ---------------- launch ----------------
extern "C" void kernel_launch(void* const* d_in, const int* in_sizes, int n_in,
                              void* d_out, int out_size)
{
    const float* x    = (const float*)d_in[0];
    const float* Wk   = (const float*)d_in[1];
    const float* bk   = (const float*)d_in[2];
    const float* Wv   = (const float*)d_in[3];
    const float* bv   = (const float*)d_in[4];
    const float* Wg1  = (const float*)d_in[5];
    const float* bg1  = (const float*)d_in[6];
    const float* Wg2  = (const float*)d_in[7];
    const float* bg2  = (const float*)d_in[8];
    const float* ln1g = (const float*)d_in[9];
    const float* ln1b = (const float*)d_in[10];
    const float* Wr1  = (const float*)d_in[11];
    const float* br1  = (const float*)d_in[12];
    const float* Wr2  = (const float*)d_in[13];
    const float* br2  = (const float*)d_in[14];
    const float* ln2g = (const float*)d_in[15];
    const float* ln2b = (const float*)d_in[16];
    const float* Wo   = (const float*)d_in[17];
    const float* bo   = (const float*)d_in[18];
    float* out = (float*)d_out;

    // device-global scratch pointers
    float *p_vg, *p_ret, *p_G1, *p_h, *p_t1, *p_t2, *p_n2;
    cudaGetSymbolAddress((void**)&p_vg,  d_vg);
    cudaGetSymbolAddress((void**)&p_ret, d_ret);
    cudaGetSymbolAddress((void**)&p_G1,  d_G1);
    cudaGetSymbolAddress((void**)&p_h,   d_h);
    cudaGetSymbolAddress((void**)&p_t1,  d_t1);
    cudaGetSymbolAddress((void**)&p_t2,  d_t2);
    cudaGetSymbolAddress((void**)&p_n2,  d_n2);
    float *p_g;
    cudaGetSymbolAddress((void**)&p_g, d_g);

    const int ATTN_SMEM = (32*64 + 64*65 + 32*64 + 64*256)*(int)sizeof(float);
    cudaFuncSetAttribute(attn_kernel, cudaFuncAttributeMaxDynamicSharedMemorySize, ATTN_SMEM);

    zero_ret_kernel<<<(NTOK*DD + 255)/256, 256>>>();
    phases_kernel<<<NTOK/8, 256>>>(x, Wk, bk);
    gemm_kernel<A_CONCAT, E_GELU><<<dim3(DD/64, NTOK/64), 256>>>(x, Wg1, bg1, p_G1, nullptr, NTOK, DD, 2*DD);
    gate2_kernel<<<NTOK/8, 256>>>(Wg2, bg2);
    cumsum_kernel<<<BB, 256>>>();
    gemm_kernel<A_PLAIN, E_VG><<<dim3(DD/64, NTOK/64), 256>>>(x, Wv, bv, p_vg, p_g, NTOK, DD, DD);
    attn_kernel<<<dim3(LL/TQ, 4, BB), 256, ATTN_SMEM>>>();
    ln_kernel<<<NTOK, 256>>>(p_ret, ln1g, ln1b, p_h, 1);
    gemm_kernel<A_PLAIN, E_GELU><<<dim3(2*DD/64, NTOK/64), 256>>>(p_h, Wr1, br1, p_t1, nullptr, NTOK, 2*DD, DD);
    gemm_kernel<A_PLAIN, E_NONE><<<dim3(DD/64, NTOK/64), 256>>>(p_t1, Wr2, br2, p_t2, nullptr, NTOK, DD, 2*DD);
    ln_kernel<<<NTOK, 256>>>(p_t2, ln2g, ln2b, p_n2, 0);
    gemm_kernel<A_PLAIN, E_OUT><<<dim3(DD/64, NTOK/64), 256>>>(p_n2, Wo, bo, out, x, NTOK, DD, DD);
    (void)in_sizes; (void)n_in; (void)out_size;
}

// round 3
// speedup vs baseline: 1.7257x; 1.7257x over previous
#include <cuda_runtime.h>
#include <math.h>
#include <stdint.h>

#define BB 2
#define LL 2048
#define DD 256
#define PP 32
#define NTOK (BB*LL)
#define NCH 16          // chunks per sequence
#define CH 128          // chunk length

// ---------------- scratch (no malloc allowed) ----------------
__device__ float d_cq[NTOK*PP];
__device__ float d_sq[NTOK*PP];
__device__ float d_g [NTOK];
__device__ float d_gc[NTOK];
__device__ float d_vg[NTOK*DD];
__device__ float d_ret[NTOK*DD];
__device__ float d_G1[NTOK*DD];
__device__ float d_h [NTOK*DD];
__device__ float d_t1[NTOK*2*DD];
__device__ float d_t2[NTOK*DD];
__device__ float d_n2[NTOK*DD];
__device__ float d_state[BB*NCH*64*DD];   // per-chunk K~^T Vg  (64 x 256)
__device__ float d_pref [BB*NCH*64*DD];   // exclusive prefix of states
__device__ float d_sc   [BB*NCH*CH*CH];   // intra-chunk causal scores

__device__ __forceinline__ float gelu_f(float x){
    return 0.5f*x*(1.0f+erff(x*0.7071067811865476f));
}

__device__ __forceinline__ float phasor(int b, int tok, int c){
    int t = b*LL + tok;
    return (c < 32) ? d_cq[t*PP + c] : d_sq[t*PP + c - 32];
}

__device__ __forceinline__ uint32_t f2tf(float f){
    uint32_t r; asm("cvt.rna.tf32.f32 %0, %1;" : "=r"(r) : "f"(f)); return r;
}

__device__ __forceinline__ void mma_tf32(float* c, const uint32_t* a, const uint32_t* b){
    asm volatile(
      "mma.sync.aligned.m16n8k8.row.col.f32.tf32.tf32.f32 "
      "{%0,%1,%2,%3}, {%4,%5,%6,%7}, {%8,%9}, {%0,%1,%2,%3};\n"
      : "+f"(c[0]), "+f"(c[1]), "+f"(c[2]), "+f"(c[3])
      : "r"(a[0]), "r"(a[1]), "r"(a[2]), "r"(a[3]), "r"(b[0]), "r"(b[1]));
}

// ---------------- phases: cq,sq = cos/sin(tanh(x@Wk+bk)*pi) ----------------
__global__ void phases_kernel(const float* __restrict__ x,
                              const float* __restrict__ Wk,
                              const float* __restrict__ bk){
    int tok = blockIdx.x*8 + (threadIdx.x>>5);
    int p   = threadIdx.x & 31;
    const float* xr = x + tok*DD;
    float s = bk[p];
    #pragma unroll 8
    for (int k = 0; k < DD; k++) s += xr[k]*Wk[k*PP + p];
    float ph = tanhf(s)*3.14159265358979323846f;
    float sn, cs;
    sincosf(ph, &sn, &cs);
    d_cq[tok*PP + p] = cs;
    d_sq[tok*PP + p] = sn;
}

// ---------------- tf32 tensor-core GEMM: C = epi(A@W + bias) ----------------
// BM=128, BN=64, BK=32; 8 warps (4x2), each warp 32x32 via m16n8k8 tiles.
#define A_PLAIN  0
#define A_CONCAT 1   // A = [x, shift(x)] : K=512
#define E_NONE 0
#define E_GELU 1
#define E_VG   2     // * extra[row]
#define E_OUT  3     // + extra[row*256+n]

#define APITCH 36
#define WPITCH 72

template<int AMODE, int EPI>
__global__ void __launch_bounds__(256)
gemm_tf32_kernel(const float* __restrict__ A,
                 const float* __restrict__ W,
                 const float* __restrict__ bias,
                 float* __restrict__ C,
                 const float* __restrict__ extra,
                 int M, int N, int K)
{
    __shared__ __align__(16) float As[128*APITCH];
    __shared__ __align__(16) float Ws[32*WPITCH];

    const int tid = threadIdx.x;
    const int wid = tid >> 5;
    const int lane = tid & 31;
    const int grp = lane >> 2;     // 0..7
    const int tig = lane & 3;      // 0..3
    const int wm = wid >> 1;       // 0..3
    const int wn = wid & 1;        // 0..1
    const int n0 = blockIdx.x*64;
    const int m0 = blockIdx.y*128;

    float acc[2][4][4];
    #pragma unroll
    for (int mt=0;mt<2;mt++)
        #pragma unroll
        for (int nt=0;nt<4;nt++)
            #pragma unroll
            for (int i=0;i<4;i++) acc[mt][nt][i]=0.f;

    for (int k0 = 0; k0 < K; k0 += 32){
        // ---- load A tile (128 x 32) ----
        #pragma unroll
        for (int it = 0; it < 4; it++){
            int linear = tid + it*256;
            int row = linear >> 3;
            int kq  = (linear & 7)*4;
            int m = m0 + row;
            int kg = k0 + kq;
            float4 v;
            if (AMODE == A_PLAIN){
                v = *(const float4*)&A[(size_t)m*K + kg];
            } else {
                if (kg < DD){
                    v = *(const float4*)&A[(size_t)m*DD + kg];
                } else {
                    int l = m & (LL-1);
                    if (l == 0) v = make_float4(0.f,0.f,0.f,0.f);
                    else        v = *(const float4*)&A[(size_t)(m-1)*DD + (kg-DD)];
                }
            }
            *(float4*)&As[row*APITCH + kq] = v;
        }
        // ---- load W tile (32 x 64) ----
        #pragma unroll
        for (int it = 0; it < 2; it++){
            int linear = tid + it*256;
            int row = linear >> 4;
            int wnq = (linear & 15)*4;
            float4 v = *(const float4*)&W[(size_t)(k0+row)*N + n0 + wnq];
            *(float4*)&Ws[row*WPITCH + wnq] = v;
        }
        __syncthreads();

        #pragma unroll
        for (int ks = 0; ks < 32; ks += 8){
            uint32_t afr[2][4], bfr[4][2];
            #pragma unroll
            for (int mt=0; mt<2; mt++){
                int rb = wm*32 + mt*16 + grp;
                afr[mt][0] = f2tf(As[(rb  )*APITCH + ks + tig    ]);
                afr[mt][1] = f2tf(As[(rb+8)*APITCH + ks + tig    ]);
                afr[mt][2] = f2tf(As[(rb  )*APITCH + ks + tig + 4]);
                afr[mt][3] = f2tf(As[(rb+8)*APITCH + ks + tig + 4]);
            }
            #pragma unroll
            for (int nt=0; nt<4; nt++){
                int cb = wn*32 + nt*8 + grp;
                bfr[nt][0] = f2tf(Ws[(ks + tig    )*WPITCH + cb]);
                bfr[nt][1] = f2tf(Ws[(ks + tig + 4)*WPITCH + cb]);
            }
            #pragma unroll
            for (int mt=0; mt<2; mt++)
                #pragma unroll
                for (int nt=0; nt<4; nt++)
                    mma_tf32(acc[mt][nt], afr[mt], bfr[nt]);
        }
        __syncthreads();
    }

    // ---- epilogue ----
    #pragma unroll
    for (int mt=0; mt<2; mt++){
        #pragma unroll
        for (int nt=0; nt<4; nt++){
            int r0 = m0 + wm*32 + mt*16 + grp;
            int cb = n0 + wn*32 + nt*8 + 2*tig;
            float b0 = bias[cb], b1 = bias[cb+1];
            #pragma unroll
            for (int half = 0; half < 2; half++){
                int r = r0 + half*8;
                float v0 = acc[mt][nt][half*2+0] + b0;
                float v1 = acc[mt][nt][half*2+1] + b1;
                if (EPI == E_GELU){ v0 = gelu_f(v0); v1 = gelu_f(v1); }
                if (EPI == E_VG)  { float g = extra[r]; v0 *= g; v1 *= g; }
                if (EPI == E_OUT) { v0 += extra[(size_t)r*DD + cb];
                                    v1 += extra[(size_t)r*DD + cb + 1]; }
                float2 o = make_float2(v0, v1);
                *(float2*)&C[(size_t)r*N + cb] = o;
            }
        }
    }
}

// ---------------- gate2: g = sigmoid(G1 . Wg2 + bg2) ----------------
__global__ void gate2_kernel(const float* __restrict__ Wg2,
                             const float* __restrict__ bg2){
    int tok  = blockIdx.x*8 + (threadIdx.x>>5);
    int lane = threadIdx.x & 31;
    const float* r = d_G1 + (size_t)tok*DD;
    float s = 0.f;
    #pragma unroll
    for (int k = lane; k < DD; k += 32) s += r[k]*Wg2[k];
    #pragma unroll
    for (int o = 16; o; o >>= 1) s += __shfl_xor_sync(0xffffffffu, s, o);
    if (lane == 0) d_g[tok] = 1.f/(1.f + expf(-(s + bg2[0])));
}

// ---------------- per-batch inclusive cumsum of g ----------------
__global__ void cumsum_kernel(){
    int b = blockIdx.x;
    int tid = threadIdx.x;
    __shared__ float tot[256];
    float v[8]; float run = 0.f;
    const float* gp = d_g + b*LL + tid*8;
    #pragma unroll
    for (int i=0;i<8;i++){ run += gp[i]; v[i] = run; }
    tot[tid] = run;
    __syncthreads();
    for (int ofs=1; ofs<256; ofs<<=1){
        float t = (tid >= ofs) ? tot[tid-ofs] : 0.f;
        __syncthreads();
        tot[tid] += t;
        __syncthreads();
    }
    float off = tot[tid] - run;
    float* gc = d_gc + b*LL + tid*8;
    #pragma unroll
    for (int i=0;i<8;i++) gc[i] = v[i] + off;
}

// ---------------- chunk state: S_c = K~_chunk^T @ Vg_chunk (64 x 256) ----------------
__global__ void __launch_bounds__(256) chunk_state_kernel(){
    __shared__ float sK[16*64];
    __shared__ float sV[16*256];
    const int cc = blockIdx.x, b = blockIdx.y;
    const int tid = threadIdx.x;
    const int pr  = (tid >> 4)*4;   // 4 p rows
    const int dcb = tid & 15;       // d cols: dcb + 16*i

    float acc[4][16];
    #pragma unroll
    for (int j=0;j<4;j++)
        #pragma unroll
        for (int i=0;i<16;i++) acc[j][i]=0.f;

    for (int tile = 0; tile < CH/16; tile++){
        int t0 = cc*CH + tile*16;
        #pragma unroll
        for (int i = tid; i < 16*64; i += 256){
            int t = i>>6, c = i&63;
            int gt = t0 + t;
            sK[i] = (gt >= 1) ? phasor(b, gt-1, c) : 0.f;
        }
        #pragma unroll
        for (int i = tid; i < 16*256; i += 256){
            int t = i>>8, c = i&255;
            sV[i] = d_vg[((size_t)(b*LL + t0 + t))*DD + c];
        }
        __syncthreads();
        #pragma unroll
        for (int t = 0; t < 16; t++){
            float kv[4];
            #pragma unroll
            for (int j=0;j<4;j++) kv[j] = sK[t*64 + pr + j];
            #pragma unroll
            for (int i=0;i<16;i++){
                float v = sV[t*256 + dcb + 16*i];
                #pragma unroll
                for (int j=0;j<4;j++) acc[j][i] += kv[j]*v;
            }
        }
        __syncthreads();
    }
    size_t base = ((size_t)(b*NCH + cc))*64*DD;
    #pragma unroll
    for (int j=0;j<4;j++)
        #pragma unroll
        for (int i=0;i<16;i++)
            d_state[base + (size_t)(pr+j)*DD + dcb + 16*i] = acc[j][i];
}

// ---------------- exclusive prefix of states over chunks ----------------
__global__ void chunk_prefix_kernel(){
    int b = blockIdx.x, gs = blockIdx.y;
    int off = gs*1024 + threadIdx.x*4;
    float4 run = make_float4(0.f,0.f,0.f,0.f);
    for (int c = 0; c < NCH; c++){
        size_t base = ((size_t)(b*NCH + c))*16384 + off;
        float4 v = *(const float4*)&d_state[base];
        *(float4*)&d_pref[base] = run;
        run.x += v.x; run.y += v.y; run.z += v.z; run.w += v.w;
    }
}

// ---------------- intra-chunk causal scores (128 x 128) ----------------
__global__ void __launch_bounds__(256) chunk_scores_kernel(){
    extern __shared__ float sm[];
    float* sQ = sm;            // 128*65
    float* sK = sQ + 128*65;   // 128*65
    const int cc = blockIdx.x, b = blockIdx.y;
    const int tid = threadIdx.x;

    for (int i = tid; i < CH*64; i += 256){
        int r = i>>6, c = i&63;
        sQ[r*65 + c] = phasor(b, cc*CH + r, c);
        int gt = cc*CH + r;
        sK[r*65 + c] = (gt >= 1) ? phasor(b, gt-1, c) : 0.f;
    }
    __syncthreads();

    const int rb  = (tid >> 3)*4;    // 4 rows
    const int cbb = tid & 7;         // cols: cbb + 8*i
    float acc[4][16];
    #pragma unroll
    for (int j=0;j<4;j++)
        #pragma unroll
        for (int i=0;i<16;i++) acc[j][i]=0.f;

    #pragma unroll 4
    for (int c = 0; c < 64; c++){
        float q[4];
        #pragma unroll
        for (int j=0;j<4;j++) q[j] = sQ[(rb+j)*65 + c];
        #pragma unroll
        for (int i=0;i<16;i++){
            float kv = sK[(cbb + 8*i)*65 + c];
            #pragma unroll
            for (int j=0;j<4;j++) acc[j][i] += q[j]*kv;
        }
    }

    size_t base = ((size_t)(b*NCH + cc))*CH*CH;
    #pragma unroll
    for (int j=0;j<4;j++){
        int ll = rb + j;
        #pragma unroll
        for (int i=0;i<16;i++){
            int tt = cbb + 8*i;
            d_sc[base + (size_t)ll*CH + tt] = (tt <= ll) ? acc[j][i] : 0.f;
        }
    }
}

// ---------------- chunk output: ret = S@Vg + Q~@P_prefix ----------------
// grid (NCH, 4 dsplits, BB), 256 threads. Warp w -> rows w*16..+15, lane -> 2 d-cols.
__global__ void __launch_bounds__(256) chunk_out_kernel(){
    extern __shared__ float sm[];
    float* sS = sm;              // 128*128
    float* sV = sS + 16384;      // 128*68
    float* sP = sV + 128*68;     // 64*68
    float* sQ = sP + 64*68;      // 128*65
    const int cc = blockIdx.x, ds = blockIdx.y, b = blockIdx.z;
    const int tid = threadIdx.x;
    const int w = tid >> 5, lane = tid & 31;

    size_t scbase = ((size_t)(b*NCH + cc))*CH*CH;
    for (int i = tid*4; i < CH*CH; i += 1024)
        *(float4*)&sS[i] = *(const float4*)&d_sc[scbase + i];
    for (int i = tid; i < CH*16; i += 256){
        int t = i>>4, c4 = (i&15)*4;
        *(float4*)&sV[t*68 + c4] =
            *(const float4*)&d_vg[((size_t)(b*LL + cc*CH + t))*DD + ds*64 + c4];
    }
    size_t pbase = ((size_t)(b*NCH + cc))*64*DD;
    for (int i = tid; i < 64*16; i += 256){
        int p = i>>4, c4 = (i&15)*4;
        *(float4*)&sP[p*68 + c4] =
            *(const float4*)&d_pref[pbase + (size_t)p*DD + ds*64 + c4];
    }
    for (int i = tid; i < CH*64; i += 256){
        int r = i>>6, c = i&63;
        sQ[r*65 + c] = phasor(b, cc*CH + r, c);
    }
    __syncthreads();

    float acc[16][2];
    #pragma unroll
    for (int r=0;r<16;r++){ acc[r][0]=0.f; acc[r][1]=0.f; }

    const int tmax = w*16 + 16;   // sS is zero above the diagonal
    for (int t = 0; t < tmax; t++){
        float2 v = *(float2*)&sV[t*68 + lane*2];
        #pragma unroll
        for (int r=0;r<16;r++){
            float s = sS[(w*16 + r)*CH + t];
            acc[r][0] += s*v.x;
            acc[r][1] += s*v.y;
        }
    }
    #pragma unroll 2
    for (int p = 0; p < 64; p++){
        float2 v = *(float2*)&sP[p*68 + lane*2];
        #pragma unroll
        for (int r=0;r<16;r++){
            float q = sQ[(w*16 + r)*65 + p];
            acc[r][0] += q*v.x;
            acc[r][1] += q*v.y;
        }
    }

    #pragma unroll
    for (int r=0;r<16;r++){
        int ll = cc*CH + w*16 + r;
        float2 o = make_float2(acc[r][0], acc[r][1]);
        *(float2*)&d_ret[((size_t)(b*LL + ll))*DD + ds*64 + lane*2] = o;
    }
}

// ---------------- LayerNorm (optionally with retrieval scaling) ----------------
__global__ void ln_kernel(const float* __restrict__ in,
                          const float* __restrict__ gamma,
                          const float* __restrict__ beta,
                          float* __restrict__ out, int scaled){
    int tok = blockIdx.x;
    int d = threadIdx.x;
    __shared__ float red[256];
    __shared__ float mv[2];
    float v = in[(size_t)tok*DD + d];
    if (scaled){
        float gcv = fmaxf(d_gc[tok], 1.0f);
        v *= rsqrtf(gcv) * 0.17677669529663687f;   // 1/sqrt(P)
    }
    red[d] = v; __syncthreads();
    #pragma unroll
    for (int o=128;o;o>>=1){ if (d<o) red[d]+=red[d+o]; __syncthreads(); }
    if (d==0) mv[0] = red[0]*(1.f/256.f);
    __syncthreads();
    float m = mv[0];
    float dv = v - m;
    red[d] = dv*dv; __syncthreads();
    #pragma unroll
    for (int o=128;o;o>>=1){ if (d<o) red[d]+=red[d+o]; __syncthreads(); }
    if (d==0) mv[1] = red[0]*(1.f/256.f);
    __syncthreads();
    float var = mv[1];
    out[(size_t)tok*DD + d] = dv*rsqrtf(var + 1e-5f)*gamma[d] + beta[d];
}

// ---------------- launch ----------------
extern "C" void kernel_launch(void* const* d_in, const int* in_sizes, int n_in,
                              void* d_out, int out_size)
{
    const float* x    = (const float*)d_in[0];
    const float* Wk   = (const float*)d_in[1];
    const float* bk   = (const float*)d_in[2];
    const float* Wv   = (const float*)d_in[3];
    const float* bv   = (const float*)d_in[4];
    const float* Wg1  = (const float*)d_in[5];
    const float* bg1  = (const float*)d_in[6];
    const float* Wg2  = (const float*)d_in[7];
    const float* bg2  = (const float*)d_in[8];
    const float* ln1g = (const float*)d_in[9];
    const float* ln1b = (const float*)d_in[10];
    const float* Wr1  = (const float*)d_in[11];
    const float* br1  = (const float*)d_in[12];
    const float* Wr2  = (const float*)d_in[13];
    const float* br2  = (const float*)d_in[14];
    const float* ln2g = (const float*)d_in[15];
    const float* ln2b = (const float*)d_in[16];
    const float* Wo   = (const float*)d_in[17];
    const float* bo   = (const float*)d_in[18];
    float* out = (float*)d_out;

    float *p_vg, *p_ret, *p_G1, *p_h, *p_t1, *p_t2, *p_n2, *p_g;
    cudaGetSymbolAddress((void**)&p_vg,  d_vg);
    cudaGetSymbolAddress((void**)&p_ret, d_ret);
    cudaGetSymbolAddress((void**)&p_G1,  d_G1);
    cudaGetSymbolAddress((void**)&p_h,   d_h);
    cudaGetSymbolAddress((void**)&p_t1,  d_t1);
    cudaGetSymbolAddress((void**)&p_t2,  d_t2);
    cudaGetSymbolAddress((void**)&p_n2,  d_n2);
    cudaGetSymbolAddress((void**)&p_g,   d_g);

    const int SCORES_SMEM = 2*128*65*(int)sizeof(float);
    const int OUT_SMEM = (16384 + 128*68 + 64*68 + 128*65)*(int)sizeof(float);
    cudaFuncSetAttribute(chunk_scores_kernel, cudaFuncAttributeMaxDynamicSharedMemorySize, SCORES_SMEM);
    cudaFuncSetAttribute(chunk_out_kernel, cudaFuncAttributeMaxDynamicSharedMemorySize, OUT_SMEM);

    phases_kernel<<<NTOK/8, 256>>>(x, Wk, bk);
    gemm_tf32_kernel<A_CONCAT, E_GELU><<<dim3(DD/64, NTOK/128), 256>>>(x, Wg1, bg1, p_G1, nullptr, NTOK, DD, 2*DD);
    gate2_kernel<<<NTOK/8, 256>>>(Wg2, bg2);
    cumsum_kernel<<<BB, 256>>>();
    gemm_tf32_kernel<A_PLAIN, E_VG><<<dim3(DD/64, NTOK/128), 256>>>(x, Wv, bv, p_vg, p_g, NTOK, DD, DD);
    chunk_state_kernel<<<dim3(NCH, BB), 256>>>();
    chunk_prefix_kernel<<<dim3(BB, 16), 256>>>();
    chunk_scores_kernel<<<dim3(NCH, BB), 256, SCORES_SMEM>>>();
    chunk_out_kernel<<<dim3(NCH, 4, BB), 256, OUT_SMEM>>>();
    ln_kernel<<<NTOK, 256>>>(p_ret, ln1g, ln1b, p_h, 1);
    gemm_tf32_kernel<A_PLAIN, E_GELU><<<dim3(2*DD/64, NTOK/128), 256>>>(p_h, Wr1, br1, p_t1, nullptr, NTOK, 2*DD, DD);
    gemm_tf32_kernel<A_PLAIN, E_NONE><<<dim3(DD/64, NTOK/128), 256>>>(p_t1, Wr2, br2, p_t2, nullptr, NTOK, DD, 2*DD);
    ln_kernel<<<NTOK, 256>>>(p_t2, ln2g, ln2b, p_n2, 0);
    gemm_tf32_kernel<A_PLAIN, E_OUT><<<dim3(DD/64, NTOK/128), 256>>>(p_n2, Wo, bo, out, x, NTOK, DD, DD);
    (void)in_sizes; (void)n_in; (void)out_size;
}

// round 5
// speedup vs baseline: 2.2860x; 1.3247x over previous
#include <cuda_runtime.h>
#include <math.h>
#include <stdint.h>

#define BB 2
#define LL 2048
#define DD 256
#define PP 32
#define NTOK (BB*LL)
#define NCH 16          // chunks per sequence
#define CH 128          // chunk length

// ---------------- scratch (no malloc allowed) ----------------
__device__ float d_cq[NTOK*PP];
__device__ float d_sq[NTOK*PP];
__device__ float d_g [NTOK];
__device__ float d_gc[NTOK];
__device__ float d_vg[NTOK*DD];
__device__ float d_ret[NTOK*DD];
__device__ float d_G1[NTOK*DD];
__device__ float d_h [NTOK*DD];
__device__ float d_t1[NTOK*2*DD];
__device__ float d_t2[NTOK*DD];
__device__ float d_n2[NTOK*DD];
__device__ float d_state[BB*NCH*64*DD];   // per-chunk K~^T Vg  (64 x 256)
__device__ float d_pref [BB*NCH*64*DD];   // exclusive prefix of states
__device__ float d_sc   [BB*NCH*CH*CH];   // intra-chunk causal scores

__device__ __forceinline__ float gelu_f(float x){
    return 0.5f*x*(1.0f+erff(x*0.7071067811865476f));
}

__device__ __forceinline__ float phasor(int b, int tok, int c){
    int t = b*LL + tok;
    return (c < 32) ? d_cq[t*PP + c] : d_sq[t*PP + c - 32];
}

__device__ __forceinline__ uint32_t f2tf(float f){
    uint32_t r; asm("cvt.rna.tf32.f32 %0, %1;" : "=r"(r) : "f"(f)); return r;
}
__device__ __forceinline__ uint32_t fb(float f){ return __float_as_uint(f); }
// tf32-round a float (RNA), keep as float bits
__device__ __forceinline__ float f2tf_as_f(float f){
    uint32_t r = f2tf(f); return __uint_as_float(r);
}

__device__ __forceinline__ void mma_tf32(float* c, const uint32_t* a, const uint32_t* b){
    asm volatile(
      "mma.sync.aligned.m16n8k8.row.col.f32.tf32.tf32.f32 "
      "{%0,%1,%2,%3}, {%4,%5,%6,%7}, {%8,%9}, {%0,%1,%2,%3};\n"
      : "+f"(c[0]), "+f"(c[1]), "+f"(c[2]), "+f"(c[3])
      : "r"(a[0]), "r"(a[1]), "r"(a[2]), "r"(a[3]), "r"(b[0]), "r"(b[1]));
}

__device__ __forceinline__ void cp16(uint32_t dst, const void* src, int sz){
    asm volatile("cp.async.cg.shared.global [%0], [%1], 16, %2;\n"
                 :: "r"(dst), "l"(src), "r"(sz));
}
__device__ __forceinline__ void cp_commit(){ asm volatile("cp.async.commit_group;\n"); }
__device__ __forceinline__ void cp_wait1(){ asm volatile("cp.async.wait_group 1;\n"); }

// ---------------- phases: cq,sq = cos/sin(tanh(x@Wk+bk)*pi) ----------------
__global__ void phases_kernel(const float* __restrict__ x,
                              const float* __restrict__ Wk,
                              const float* __restrict__ bk){
    int tok = blockIdx.x*8 + (threadIdx.x>>5);
    int p   = threadIdx.x & 31;
    const float* xr = x + tok*DD;
    float s = bk[p];
    #pragma unroll 8
    for (int k = 0; k < DD; k++) s += xr[k]*Wk[k*PP + p];
    float ph = tanhf(s)*3.14159265358979323846f;
    float sn, cs;
    sincosf(ph, &sn, &cs);
    d_cq[tok*PP + p] = cs;
    d_sq[tok*PP + p] = sn;
}

// ---------------- tf32 tensor-core GEMM v2: cp.async double-buffered ----------------
// BM=128, BN=64, BK=32; 8 warps (4x2), each warp 32x32 via m16n8k8 tiles.
#define A_PLAIN  0
#define A_CONCAT 1   // A = [x, shift(x)] : K=512
#define E_NONE 0
#define E_GELU 1
#define E_VG   2     // * extra[row]
#define E_OUT  3     // + extra[row*256+n]

#define APITCH 36
#define WPITCH 72
#define GEMM_SMEM ((2*128*APITCH + 2*32*WPITCH)*(int)sizeof(float))

template<int AMODE, int EPI>
__global__ void __launch_bounds__(256)
gemm_tf32_kernel(const float* __restrict__ A,
                 const float* __restrict__ W,
                 const float* __restrict__ bias,
                 float* __restrict__ C,
                 const float* __restrict__ extra,
                 int M, int N, int K)
{
    extern __shared__ __align__(16) float smem[];
    float* Asm = smem;                        // 2 x 128*APITCH
    float* Wsm = smem + 2*128*APITCH;         // 2 x 32*WPITCH

    const int tid = threadIdx.x;
    const int wid = tid >> 5;
    const int lane = tid & 31;
    const int grp = lane >> 2;     // 0..7
    const int tig = lane & 3;      // 0..3
    const int wm = wid >> 1;       // 0..3
    const int wn = wid & 1;        // 0..1
    const int n0 = blockIdx.x*64;
    const int m0 = blockIdx.y*128;

    float acc[2][4][4];
    #pragma unroll
    for (int mt=0;mt<2;mt++)
        #pragma unroll
        for (int nt=0;nt<4;nt++)
            #pragma unroll
            for (int i=0;i<4;i++) acc[mt][nt][i]=0.f;

    auto load_tiles = [&](int buf, int k0){
        float* As = Asm + buf*128*APITCH;
        float* Ws = Wsm + buf*32*WPITCH;
        #pragma unroll
        for (int it = 0; it < 4; it++){
            int linear = tid + it*256;
            int row = linear >> 3;
            int kq  = (linear & 7)*4;
            int m = m0 + row;
            int kg = k0 + kq;
            const float* src; int sz = 16;
            if (AMODE == A_PLAIN){
                src = A + (size_t)m*K + kg;
            } else {
                if (kg < DD) src = A + (size_t)m*DD + kg;
                else {
                    int l = m & (LL-1);
                    if (l == 0){ sz = 0; src = A; }
                    else src = A + (size_t)(m-1)*DD + (kg-DD);
                }
            }
            cp16((uint32_t)__cvta_generic_to_shared(&As[row*APITCH + kq]), src, sz);
        }
        #pragma unroll
        for (int it = 0; it < 2; it++){
            int linear = tid + it*256;
            int row = linear >> 4;
            int wnq = (linear & 15)*4;
            const float* src = W + (size_t)(k0+row)*N + n0 + wnq;
            cp16((uint32_t)__cvta_generic_to_shared(&Ws[row*WPITCH + wnq]), src, 16);
        }
    };

    const int ntiles = K >> 5;
    load_tiles(0, 0);
    cp_commit();

    for (int kt = 0; kt < ntiles; kt++){
        int buf = kt & 1;
        if (kt+1 < ntiles) load_tiles(buf^1, (kt+1)*32);
        cp_commit();
        cp_wait1();
        __syncthreads();

        const float* As = Asm + buf*128*APITCH;
        const float* Ws = Wsm + buf*32*WPITCH;
        #pragma unroll
        for (int ks = 0; ks < 32; ks += 8){
            uint32_t afr[2][4], bfr[4][2];
            #pragma unroll
            for (int mt=0; mt<2; mt++){
                int rb = wm*32 + mt*16 + grp;
                afr[mt][0] = fb(As[(rb  )*APITCH + ks + tig    ]);
                afr[mt][1] = fb(As[(rb+8)*APITCH + ks + tig    ]);
                afr[mt][2] = fb(As[(rb  )*APITCH + ks + tig + 4]);
                afr[mt][3] = fb(As[(rb+8)*APITCH + ks + tig + 4]);
            }
            #pragma unroll
            for (int nt=0; nt<4; nt++){
                int cb = wn*32 + nt*8 + grp;
                bfr[nt][0] = fb(Ws[(ks + tig    )*WPITCH + cb]);
                bfr[nt][1] = fb(Ws[(ks + tig + 4)*WPITCH + cb]);
            }
            #pragma unroll
            for (int mt=0; mt<2; mt++)
                #pragma unroll
                for (int nt=0; nt<4; nt++)
                    mma_tf32(acc[mt][nt], afr[mt], bfr[nt]);
        }
        __syncthreads();
    }

    // ---- epilogue ----
    #pragma unroll
    for (int mt=0; mt<2; mt++){
        #pragma unroll
        for (int nt=0; nt<4; nt++){
            int r0 = m0 + wm*32 + mt*16 + grp;
            int cb = n0 + wn*32 + nt*8 + 2*tig;
            float b0 = bias[cb], b1 = bias[cb+1];
            #pragma unroll
            for (int half = 0; half < 2; half++){
                int r = r0 + half*8;
                float v0 = acc[mt][nt][half*2+0] + b0;
                float v1 = acc[mt][nt][half*2+1] + b1;
                if (EPI == E_GELU){ v0 = gelu_f(v0); v1 = gelu_f(v1); }
                if (EPI == E_VG)  { float g = extra[r]; v0 *= g; v1 *= g; }
                if (EPI == E_OUT) { v0 += extra[(size_t)r*DD + cb];
                                    v1 += extra[(size_t)r*DD + cb + 1]; }
                *(float2*)&C[(size_t)r*N + cb] = make_float2(v0, v1);
            }
        }
    }
}

// ---------------- gate2: g = sigmoid(G1 . Wg2 + bg2) ----------------
__global__ void gate2_kernel(const float* __restrict__ Wg2,
                             const float* __restrict__ bg2){
    int tok  = blockIdx.x*8 + (threadIdx.x>>5);
    int lane = threadIdx.x & 31;
    const float* r = d_G1 + (size_t)tok*DD;
    float s = 0.f;
    #pragma unroll
    for (int k = lane; k < DD; k += 32) s += r[k]*Wg2[k];
    #pragma unroll
    for (int o = 16; o; o >>= 1) s += __shfl_xor_sync(0xffffffffu, s, o);
    if (lane == 0) d_g[tok] = 1.f/(1.f + expf(-(s + bg2[0])));
}

// ---------------- per-batch inclusive cumsum of g (shfl scan) ----------------
__global__ void cumsum_kernel(){
    int b = blockIdx.x;
    int tid = threadIdx.x;
    int lane = tid & 31, warp = tid >> 5;
    __shared__ float wtot[8];
    float v[8]; float run = 0.f;
    const float* gp = d_g + b*LL + tid*8;
    #pragma unroll
    for (int i=0;i<8;i++){ run += gp[i]; v[i] = run; }
    float x = run;
    #pragma unroll
    for (int o=1;o<32;o<<=1){
        float y = __shfl_up_sync(0xffffffffu, x, o);
        if (lane >= o) x += y;
    }
    if (lane == 31) wtot[warp] = x;
    __syncthreads();
    if (warp == 0 && lane < 8){
        float t = wtot[lane];
        #pragma unroll
        for (int o=1;o<8;o<<=1){
            float z = __shfl_up_sync(0xffu, t, o);
            if (lane >= o) t += z;
        }
        wtot[lane] = t;
    }
    __syncthreads();
    float off = (x - run) + (warp ? wtot[warp-1] : 0.f);
    float* gc = d_gc + b*LL + tid*8;
    #pragma unroll
    for (int i=0;i<8;i++) gc[i] = v[i] + off;
}

// ---------------- chunk state (MMA): S_c = K~^T @ Vg, M=64 N=256 K=128 ----------------
__global__ void __launch_bounds__(256) chunk_state_kernel(){
    __shared__ float sA[64*36];     // [p][t] tile
    __shared__ float sB[32*264];    // [t][d]
    const int cc = blockIdx.x, b = blockIdx.y;
    const int tid = threadIdx.x;
    const int wid = tid >> 5, lane = tid & 31;
    const int grp = lane >> 2, tig = lane & 3;
    const int wm = wid >> 2;        // 0..1  (rows 32)
    const int wn = wid & 3;         // 0..3  (cols 64)

    float acc[2][8][4];
    #pragma unroll
    for (int mt=0;mt<2;mt++)
        #pragma unroll
        for (int nt=0;nt<8;nt++)
            #pragma unroll
            for (int i=0;i<4;i++) acc[mt][nt][i]=0.f;

    for (int tile = 0; tile < 4; tile++){
        int t0 = cc*CH + tile*32;
        for (int i = tid; i < 64*32; i += 256){
            int p = i>>5, t = i&31;
            int gt = t0 + t;
            sA[p*36 + t] = (gt >= 1) ? f2tf_as_f(phasor(b, gt-1, p)) : 0.f;
        }
        for (int i = tid; i < 32*64; i += 256){
            int t = i>>6, c4 = (i&63)*4;
            float4 v = *(const float4*)&d_vg[((size_t)(b*LL + t0 + t))*DD + c4];
            v.x = f2tf_as_f(v.x); v.y = f2tf_as_f(v.y);
            v.z = f2tf_as_f(v.z); v.w = f2tf_as_f(v.w);
            *(float4*)&sB[t*264 + c4] = v;
        }
        __syncthreads();
        #pragma unroll
        for (int ks = 0; ks < 32; ks += 8){
            uint32_t afr[2][4], bfr[8][2];
            #pragma unroll
            for (int mt=0; mt<2; mt++){
                int rb = wm*32 + mt*16 + grp;
                afr[mt][0] = fb(sA[(rb  )*36 + ks + tig    ]);
                afr[mt][1] = fb(sA[(rb+8)*36 + ks + tig    ]);
                afr[mt][2] = fb(sA[(rb  )*36 + ks + tig + 4]);
                afr[mt][3] = fb(sA[(rb+8)*36 + ks + tig + 4]);
            }
            #pragma unroll
            for (int nt=0; nt<8; nt++){
                int cb = wn*64 + nt*8 + grp;
                bfr[nt][0] = fb(sB[(ks + tig    )*264 + cb]);
                bfr[nt][1] = fb(sB[(ks + tig + 4)*264 + cb]);
            }
            #pragma unroll
            for (int mt=0; mt<2; mt++)
                #pragma unroll
                for (int nt=0; nt<8; nt++)
                    mma_tf32(acc[mt][nt], afr[mt], bfr[nt]);
        }
        __syncthreads();
    }
    size_t base = ((size_t)(b*NCH + cc))*64*DD;
    #pragma unroll
    for (int mt=0; mt<2; mt++)
        #pragma unroll
        for (int nt=0; nt<8; nt++)
            #pragma unroll
            for (int half=0; half<2; half++){
                int row = wm*32 + mt*16 + grp + half*8;
                int col = wn*64 + nt*8 + 2*tig;
                *(float2*)&d_state[base + (size_t)row*DD + col] =
                    make_float2(acc[mt][nt][half*2], acc[mt][nt][half*2+1]);
            }
}

// ---------------- exclusive prefix of states over chunks ----------------
__global__ void chunk_prefix_kernel(){
    int b = blockIdx.x, gs = blockIdx.y;
    int off = gs*1024 + threadIdx.x*4;
    float4 run = make_float4(0.f,0.f,0.f,0.f);
    for (int c = 0; c < NCH; c++){
        size_t base = ((size_t)(b*NCH + c))*16384 + off;
        float4 v = *(const float4*)&d_state[base];
        *(float4*)&d_pref[base] = run;
        run.x += v.x; run.y += v.y; run.z += v.z; run.w += v.w;
    }
}

// ---------------- intra-chunk causal scores (MMA): 128x128, K=64 ----------------
__global__ void __launch_bounds__(256) chunk_scores_kernel(){
    extern __shared__ __align__(16) float sm[];
    float* sQ  = sm;             // 128 x 68  (A-side)
    float* sKT = sm + 128*68;    // 64 x 136  (B-side, [c][t])
    const int cc = blockIdx.x, b = blockIdx.y;
    const int tid = threadIdx.x;
    const int wid = tid >> 5, lane = tid & 31;
    const int grp = lane >> 2, tig = lane & 3;
    const int wm = wid >> 1;     // 0..3 rows 32
    const int wn = wid & 1;      // 0..1 cols 64

    for (int i = tid; i < CH*64; i += 256){
        int r = i>>6, c = i&63;
        sQ[r*68 + c] = f2tf_as_f(phasor(b, cc*CH + r, c));
    }
    for (int i = tid; i < CH*64; i += 256){
        int t = i>>6, c = i&63;
        int gt = cc*CH + t;
        sKT[c*136 + t] = (gt >= 1) ? f2tf_as_f(phasor(b, gt-1, c)) : 0.f;
    }
    __syncthreads();

    float acc[2][8][4];
    #pragma unroll
    for (int mt=0;mt<2;mt++)
        #pragma unroll
        for (int nt=0;nt<8;nt++)
            #pragma unroll
            for (int i=0;i<4;i++) acc[mt][nt][i]=0.f;

    #pragma unroll
    for (int ks = 0; ks < 64; ks += 8){
        uint32_t afr[2][4], bfr[8][2];
        #pragma unroll
        for (int mt=0; mt<2; mt++){
            int rb = wm*32 + mt*16 + grp;
            afr[mt][0] = fb(sQ[(rb  )*68 + ks + tig    ]);
            afr[mt][1] = fb(sQ[(rb+8)*68 + ks + tig    ]);
            afr[mt][2] = fb(sQ[(rb  )*68 + ks + tig + 4]);
            afr[mt][3] = fb(sQ[(rb+8)*68 + ks + tig + 4]);
        }
        #pragma unroll
        for (int nt=0; nt<8; nt++){
            int cb = wn*64 + nt*8 + grp;
            bfr[nt][0] = fb(sKT[(ks + tig    )*136 + cb]);
            bfr[nt][1] = fb(sKT[(ks + tig + 4)*136 + cb]);
        }
        #pragma unroll
        for (int mt=0; mt<2; mt++)
            #pragma unroll
            for (int nt=0; nt<8; nt++)
                mma_tf32(acc[mt][nt], afr[mt], bfr[nt]);
    }

    size_t base = ((size_t)(b*NCH + cc))*CH*CH;
    #pragma unroll
    for (int mt=0; mt<2; mt++)
        #pragma unroll
        for (int nt=0; nt<8; nt++)
            #pragma unroll
            for (int half=0; half<2; half++){
                int row = wm*32 + mt*16 + grp + half*8;
                int col = wn*64 + nt*8 + 2*tig;
                float v0 = (col   <= row) ? acc[mt][nt][half*2  ] : 0.f;
                float v1 = (col+1 <= row) ? acc[mt][nt][half*2+1] : 0.f;
                *(float2*)&d_sc[base + (size_t)row*CH + col] = make_float2(v0, v1);
            }
}

// ---------------- chunk output (MMA): ret = S@Vg + Q~@P, per 64-d split ----------------
#define OUT_SMEM ((128*132 + 128*72 + 64*72 + 128*68)*(int)sizeof(float))
__global__ void __launch_bounds__(256) chunk_out_kernel(){
    extern __shared__ __align__(16) float sm[];
    float* sS = sm;               // 128 x 132 (A)
    float* sV = sS + 128*132;     // 128 x 72  (B)
    float* sP = sV + 128*72;      // 64 x 72   (B)
    float* sQ = sP + 64*72;       // 128 x 68  (A)
    const int cc = blockIdx.x, ds = blockIdx.y, b = blockIdx.z;
    const int tid = threadIdx.x;
    const int wid = tid >> 5, lane = tid & 31;
    const int grp = lane >> 2, tig = lane & 3;
    const int wm = wid >> 1;      // 0..3 rows 32
    const int wn = wid & 1;       // 0..1 cols 32

    size_t scbase = ((size_t)(b*NCH + cc))*CH*CH;
    for (int i = tid; i < 128*32; i += 256){
        int row = i>>5, c4 = (i&31)*4;
        float4 v = *(const float4*)&d_sc[scbase + (size_t)row*CH + c4];
        v.x = f2tf_as_f(v.x); v.y = f2tf_as_f(v.y);
        v.z = f2tf_as_f(v.z); v.w = f2tf_as_f(v.w);
        *(float4*)&sS[row*132 + c4] = v;
    }
    for (int i = tid; i < 128*16; i += 256){
        int t = i>>4, c4 = (i&15)*4;
        float4 v = *(const float4*)&d_vg[((size_t)(b*LL + cc*CH + t))*DD + ds*64 + c4];
        v.x = f2tf_as_f(v.x); v.y = f2tf_as_f(v.y);
        v.z = f2tf_as_f(v.z); v.w = f2tf_as_f(v.w);
        *(float4*)&sV[t*72 + c4] = v;
    }
    size_t pbase = ((size_t)(b*NCH + cc))*64*DD;
    for (int i = tid; i < 64*16; i += 256){
        int p = i>>4, c4 = (i&15)*4;
        float4 v = *(const float4*)&d_pref[pbase + (size_t)p*DD + ds*64 + c4];
        v.x = f2tf_as_f(v.x); v.y = f2tf_as_f(v.y);
        v.z = f2tf_as_f(v.z); v.w = f2tf_as_f(v.w);
        *(float4*)&sP[p*72 + c4] = v;
    }
    for (int i = tid; i < 128*64; i += 256){
        int r = i>>6, c = i&63;
        sQ[r*68 + c] = f2tf_as_f(phasor(b, cc*CH + r, c));
    }
    __syncthreads();

    float acc[2][4][4];
    #pragma unroll
    for (int mt=0;mt<2;mt++)
        #pragma unroll
        for (int nt=0;nt<4;nt++)
            #pragma unroll
            for (int i=0;i<4;i++) acc[mt][nt][i]=0.f;

    // phase 1: S @ V over t = 0..127
    #pragma unroll 4
    for (int ks = 0; ks < 128; ks += 8){
        uint32_t afr[2][4], bfr[4][2];
        #pragma unroll
        for (int mt=0; mt<2; mt++){
            int rb = wm*32 + mt*16 + grp;
            afr[mt][0] = fb(sS[(rb  )*132 + ks + tig    ]);
            afr[mt][1] = fb(sS[(rb+8)*132 + ks + tig    ]);
            afr[mt][2] = fb(sS[(rb  )*132 + ks + tig + 4]);
            afr[mt][3] = fb(sS[(rb+8)*132 + ks + tig + 4]);
        }
        #pragma unroll
        for (int nt=0; nt<4; nt++){
            int cb = wn*32 + nt*8 + grp;
            bfr[nt][0] = fb(sV[(ks + tig    )*72 + cb]);
            bfr[nt][1] = fb(sV[(ks + tig + 4)*72 + cb]);
        }
        #pragma unroll
        for (int mt=0; mt<2; mt++)
            #pragma unroll
            for (int nt=0; nt<4; nt++)
                mma_tf32(acc[mt][nt], afr[mt], bfr[nt]);
    }
    // phase 2: Q~ @ P over p = 0..63
    #pragma unroll
    for (int ks = 0; ks < 64; ks += 8){
        uint32_t afr[2][4], bfr[4][2];
        #pragma unroll
        for (int mt=0; mt<2; mt++){
            int rb = wm*32 + mt*16 + grp;
            afr[mt][0] = fb(sQ[(rb  )*68 + ks + tig    ]);
            afr[mt][1] = fb(sQ[(rb+8)*68 + ks + tig    ]);
            afr[mt][2] = fb(sQ[(rb  )*68 + ks + tig + 4]);
            afr[mt][3] = fb(sQ[(rb+8)*68 + ks + tig + 4]);
        }
        #pragma unroll
        for (int nt=0; nt<4; nt++){
            int cb = wn*32 + nt*8 + grp;
            bfr[nt][0] = fb(sP[(ks + tig    )*72 + cb]);
            bfr[nt][1] = fb(sP[(ks + tig + 4)*72 + cb]);
        }
        #pragma unroll
        for (int mt=0; mt<2; mt++)
            #pragma unroll
            for (int nt=0; nt<4; nt++)
                mma_tf32(acc[mt][nt], afr[mt], bfr[nt]);
    }

    #pragma unroll
    for (int mt=0; mt<2; mt++)
        #pragma unroll
        for (int nt=0; nt<4; nt++)
            #pragma unroll
            for (int half=0; half<2; half++){
                int row = wm*32 + mt*16 + grp + half*8;
                int col = wn*32 + nt*8 + 2*tig;
                *(float2*)&d_ret[((size_t)(b*LL + cc*CH + row))*DD + ds*64 + col] =
                    make_float2(acc[mt][nt][half*2], acc[mt][nt][half*2+1]);
            }
}

// ---------------- LayerNorm (optionally with retrieval scaling) ----------------
__global__ void ln_kernel(const float* __restrict__ in,
                          const float* __restrict__ gamma,
                          const float* __restrict__ beta,
                          float* __restrict__ out, int scaled){
    int tok = blockIdx.x;
    int d = threadIdx.x;
    __shared__ float red[256];
    __shared__ float mv[2];
    float v = in[(size_t)tok*DD + d];
    if (scaled){
        float gcv = fmaxf(d_gc[tok], 1.0f);
        v *= rsqrtf(gcv) * 0.17677669529663687f;   // 1/sqrt(P)
    }
    red[d] = v; __syncthreads();
    #pragma unroll
    for (int o=128;o;o>>=1){ if (d<o) red[d]+=red[d+o]; __syncthreads(); }
    if (d==0) mv[0] = red[0]*(1.f/256.f);
    __syncthreads();
    float m = mv[0];
    float dv = v - m;
    red[d] = dv*dv; __syncthreads();
    #pragma unroll
    for (int o=128;o;o>>=1){ if (d<o) red[d]+=red[d+o]; __syncthreads(); }
    if (d==0) mv[1] = red[0]*(1.f/256.f);
    __syncthreads();
    float var = mv[1];
    out[(size_t)tok*DD + d] = dv*rsqrtf(var + 1e-5f)*gamma[d] + beta[d];
}

// ---------------- launch ----------------
extern "C" void kernel_launch(void* const* d_in, const int* in_sizes, int n_in,
                              void* d_out, int out_size)
{
    const float* x    = (const float*)d_in[0];
    const float* Wk   = (const float*)d_in[1];
    const float* bk   = (const float*)d_in[2];
    const float* Wv   = (const float*)d_in[3];
    const float* bv   = (const float*)d_in[4];
    const float* Wg1  = (const float*)d_in[5];
    const float* bg1  = (const float*)d_in[6];
    const float* Wg2  = (const float*)d_in[7];
    const float* bg2  = (const float*)d_in[8];
    const float* ln1g = (const float*)d_in[9];
    const float* ln1b = (const float*)d_in[10];
    const float* Wr1  = (const float*)d_in[11];
    const float* br1  = (const float*)d_in[12];
    const float* Wr2  = (const float*)d_in[13];
    const float* br2  = (const float*)d_in[14];
    const float* ln2g = (const float*)d_in[15];
    const float* ln2b = (const float*)d_in[16];
    const float* Wo   = (const float*)d_in[17];
    const float* bo   = (const float*)d_in[18];
    float* out = (float*)d_out;

    float *p_vg, *p_ret, *p_G1, *p_h, *p_t1, *p_t2, *p_n2, *p_g;
    cudaGetSymbolAddress((void**)&p_vg,  d_vg);
    cudaGetSymbolAddress((void**)&p_ret, d_ret);
    cudaGetSymbolAddress((void**)&p_G1,  d_G1);
    cudaGetSymbolAddress((void**)&p_h,   d_h);
    cudaGetSymbolAddress((void**)&p_t1,  d_t1);
    cudaGetSymbolAddress((void**)&p_t2,  d_t2);
    cudaGetSymbolAddress((void**)&p_n2,  d_n2);
    cudaGetSymbolAddress((void**)&p_g,   d_g);

    const int SCORES_SMEM = (128*68 + 64*136)*(int)sizeof(float);
    cudaFuncSetAttribute(gemm_tf32_kernel<A_CONCAT,E_GELU>, cudaFuncAttributeMaxDynamicSharedMemorySize, GEMM_SMEM);
    cudaFuncSetAttribute(gemm_tf32_kernel<A_PLAIN,E_VG>,    cudaFuncAttributeMaxDynamicSharedMemorySize, GEMM_SMEM);
    cudaFuncSetAttribute(gemm_tf32_kernel<A_PLAIN,E_GELU>,  cudaFuncAttributeMaxDynamicSharedMemorySize, GEMM_SMEM);
    cudaFuncSetAttribute(gemm_tf32_kernel<A_PLAIN,E_NONE>,  cudaFuncAttributeMaxDynamicSharedMemorySize, GEMM_SMEM);
    cudaFuncSetAttribute(gemm_tf32_kernel<A_PLAIN,E_OUT>,   cudaFuncAttributeMaxDynamicSharedMemorySize, GEMM_SMEM);
    cudaFuncSetAttribute(chunk_scores_kernel, cudaFuncAttributeMaxDynamicSharedMemorySize, SCORES_SMEM);
    cudaFuncSetAttribute(chunk_out_kernel,    cudaFuncAttributeMaxDynamicSharedMemorySize, OUT_SMEM);

    phases_kernel<<<NTOK/8, 256>>>(x, Wk, bk);
    gemm_tf32_kernel<A_CONCAT, E_GELU><<<dim3(DD/64, NTOK/128), 256, GEMM_SMEM>>>(x, Wg1, bg1, p_G1, nullptr, NTOK, DD, 2*DD);
    gate2_kernel<<<NTOK/8, 256>>>(Wg2, bg2);
    cumsum_kernel<<<BB, 256>>>();
    gemm_tf32_kernel<A_PLAIN, E_VG><<<dim3(DD/64, NTOK/128), 256, GEMM_SMEM>>>(x, Wv, bv, p_vg, p_g, NTOK, DD, DD);
    chunk_state_kernel<<<dim3(NCH, BB), 256>>>();
    chunk_prefix_kernel<<<dim3(BB, 16), 256>>>();
    chunk_scores_kernel<<<dim3(NCH, BB), 256, SCORES_SMEM>>>();
    chunk_out_kernel<<<dim3(NCH, 4, BB), 256, OUT_SMEM>>>();
    ln_kernel<<<NTOK, 256>>>(p_ret, ln1g, ln1b, p_h, 1);
    gemm_tf32_kernel<A_PLAIN, E_GELU><<<dim3(2*DD/64, NTOK/128), 256, GEMM_SMEM>>>(p_h, Wr1, br1, p_t1, nullptr, NTOK, 2*DD, DD);
    gemm_tf32_kernel<A_PLAIN, E_NONE><<<dim3(DD/64, NTOK/128), 256, GEMM_SMEM>>>(p_t1, Wr2, br2, p_t2, nullptr, NTOK, DD, 2*DD);
    ln_kernel<<<NTOK, 256>>>(p_t2, ln2g, ln2b, p_n2, 0);
    gemm_tf32_kernel<A_PLAIN, E_OUT><<<dim3(DD/64, NTOK/128), 256, GEMM_SMEM>>>(p_n2, Wo, bo, out, x, NTOK, DD, DD);
    (void)in_sizes; (void)n_in; (void)out_size;
}

// round 6
// speedup vs baseline: 2.3475x; 1.0269x over previous
#include <cuda_runtime.h>
#include <math.h>
#include <stdint.h>

#define BB 2
#define LL 2048
#define DD 256
#define PP 32
#define NTOK (BB*LL)
#define NCH 16          // chunks per sequence
#define CH 128          // chunk length

// ---------------- scratch (no malloc allowed) ----------------
__device__ float d_cq[NTOK*PP];
__device__ float d_sq[NTOK*PP];
__device__ float d_g [NTOK];
__device__ float d_gc[NTOK];
__device__ float d_v [NTOK*DD];           // ungated values (x@Wv + bv)
__device__ float d_ret[NTOK*DD];
__device__ float d_G1[NTOK*DD];
__device__ float d_h [NTOK*DD];
__device__ float d_t1[NTOK*2*DD];
__device__ float d_t2[NTOK*DD];
__device__ float d_n2[NTOK*DD];
__device__ float d_state[BB*NCH*64*DD];   // per-chunk K~^T Vg  (64 x 256)
__device__ float d_pref [BB*NCH*64*DD];   // exclusive prefix of states

__device__ __forceinline__ float gelu_f(float x){
    return 0.5f*x*(1.0f+erff(x*0.7071067811865476f));
}

__device__ __forceinline__ float phasor(int b, int tok, int c){
    int t = b*LL + tok;
    return (c < 32) ? d_cq[t*PP + c] : d_sq[t*PP + c - 32];
}

__device__ __forceinline__ uint32_t f2tf(float f){
    uint32_t r; asm("cvt.rna.tf32.f32 %0, %1;" : "=r"(r) : "f"(f)); return r;
}
__device__ __forceinline__ uint32_t fb(float f){ return __float_as_uint(f); }
__device__ __forceinline__ float f2tf_as_f(float f){
    uint32_t r = f2tf(f); return __uint_as_float(r);
}

__device__ __forceinline__ void mma_tf32(float* c, const uint32_t* a, const uint32_t* b){
    asm volatile(
      "mma.sync.aligned.m16n8k8.row.col.f32.tf32.tf32.f32 "
      "{%0,%1,%2,%3}, {%4,%5,%6,%7}, {%8,%9}, {%0,%1,%2,%3};\n"
      : "+f"(c[0]), "+f"(c[1]), "+f"(c[2]), "+f"(c[3])
      : "r"(a[0]), "r"(a[1]), "r"(a[2]), "r"(a[3]), "r"(b[0]), "r"(b[1]));
}

__device__ __forceinline__ void cp16(uint32_t dst, const void* src, int sz){
    asm volatile("cp.async.cg.shared.global [%0], [%1], 16, %2;\n"
                 :: "r"(dst), "l"(src), "r"(sz));
}
__device__ __forceinline__ void cp_commit(){ asm volatile("cp.async.commit_group;\n"); }
__device__ __forceinline__ void cp_wait1(){ asm volatile("cp.async.wait_group 1;\n"); }

// ---------------- phases: cq,sq = cos/sin(tanh(x@Wk+bk)*pi) ----------------
__global__ void phases_kernel(const float* __restrict__ x,
                              const float* __restrict__ Wk,
                              const float* __restrict__ bk){
    int tok = blockIdx.x*8 + (threadIdx.x>>5);
    int p   = threadIdx.x & 31;
    const float* xr = x + tok*DD;
    float s = bk[p];
    #pragma unroll 8
    for (int k = 0; k < DD; k++) s += xr[k]*Wk[k*PP + p];
    float ph = tanhf(s)*3.14159265358979323846f;
    float sn, cs;
    sincosf(ph, &sn, &cs);
    d_cq[tok*PP + p] = cs;
    d_sq[tok*PP + p] = sn;
}

// ---------------- tf32 tensor-core GEMM: cp.async double-buffered ----------------
#define A_PLAIN  0
#define A_CONCAT 1
#define E_NONE 0
#define E_GELU 1
#define E_OUT  3

#define APITCH 36
#define WPITCH 72
#define GEMM_SMEM ((2*128*APITCH + 2*32*WPITCH)*(int)sizeof(float))

template<int AMODE, int EPI>
__global__ void __launch_bounds__(256)
gemm_tf32_kernel(const float* __restrict__ A,
                 const float* __restrict__ W,
                 const float* __restrict__ bias,
                 float* __restrict__ C,
                 const float* __restrict__ extra,
                 int M, int N, int K)
{
    extern __shared__ __align__(16) float smem[];
    float* Asm = smem;
    float* Wsm = smem + 2*128*APITCH;

    const int tid = threadIdx.x;
    const int wid = tid >> 5;
    const int lane = tid & 31;
    const int grp = lane >> 2;
    const int tig = lane & 3;
    const int wm = wid >> 1;
    const int wn = wid & 1;
    const int n0 = blockIdx.x*64;
    const int m0 = blockIdx.y*128;

    float acc[2][4][4];
    #pragma unroll
    for (int mt=0;mt<2;mt++)
        #pragma unroll
        for (int nt=0;nt<4;nt++)
            #pragma unroll
            for (int i=0;i<4;i++) acc[mt][nt][i]=0.f;

    auto load_tiles = [&](int buf, int k0){
        float* As = Asm + buf*128*APITCH;
        float* Ws = Wsm + buf*32*WPITCH;
        #pragma unroll
        for (int it = 0; it < 4; it++){
            int linear = tid + it*256;
            int row = linear >> 3;
            int kq  = (linear & 7)*4;
            int m = m0 + row;
            int kg = k0 + kq;
            const float* src; int sz = 16;
            if (AMODE == A_PLAIN){
                src = A + (size_t)m*K + kg;
            } else {
                if (kg < DD) src = A + (size_t)m*DD + kg;
                else {
                    int l = m & (LL-1);
                    if (l == 0){ sz = 0; src = A; }
                    else src = A + (size_t)(m-1)*DD + (kg-DD);
                }
            }
            cp16((uint32_t)__cvta_generic_to_shared(&As[row*APITCH + kq]), src, sz);
        }
        #pragma unroll
        for (int it = 0; it < 2; it++){
            int linear = tid + it*256;
            int row = linear >> 4;
            int wnq = (linear & 15)*4;
            const float* src = W + (size_t)(k0+row)*N + n0 + wnq;
            cp16((uint32_t)__cvta_generic_to_shared(&Ws[row*WPITCH + wnq]), src, 16);
        }
    };

    const int ntiles = K >> 5;
    load_tiles(0, 0);
    cp_commit();

    for (int kt = 0; kt < ntiles; kt++){
        int buf = kt & 1;
        if (kt+1 < ntiles) load_tiles(buf^1, (kt+1)*32);
        cp_commit();
        cp_wait1();
        __syncthreads();

        const float* As = Asm + buf*128*APITCH;
        const float* Ws = Wsm + buf*32*WPITCH;
        #pragma unroll
        for (int ks = 0; ks < 32; ks += 8){
            uint32_t afr[2][4], bfr[4][2];
            #pragma unroll
            for (int mt=0; mt<2; mt++){
                int rb = wm*32 + mt*16 + grp;
                afr[mt][0] = fb(As[(rb  )*APITCH + ks + tig    ]);
                afr[mt][1] = fb(As[(rb+8)*APITCH + ks + tig    ]);
                afr[mt][2] = fb(As[(rb  )*APITCH + ks + tig + 4]);
                afr[mt][3] = fb(As[(rb+8)*APITCH + ks + tig + 4]);
            }
            #pragma unroll
            for (int nt=0; nt<4; nt++){
                int cb = wn*32 + nt*8 + grp;
                bfr[nt][0] = fb(Ws[(ks + tig    )*WPITCH + cb]);
                bfr[nt][1] = fb(Ws[(ks + tig + 4)*WPITCH + cb]);
            }
            #pragma unroll
            for (int mt=0; mt<2; mt++)
                #pragma unroll
                for (int nt=0; nt<4; nt++)
                    mma_tf32(acc[mt][nt], afr[mt], bfr[nt]);
        }
        __syncthreads();
    }

    #pragma unroll
    for (int mt=0; mt<2; mt++){
        #pragma unroll
        for (int nt=0; nt<4; nt++){
            int r0 = m0 + wm*32 + mt*16 + grp;
            int cb = n0 + wn*32 + nt*8 + 2*tig;
            float b0 = bias[cb], b1 = bias[cb+1];
            #pragma unroll
            for (int half = 0; half < 2; half++){
                int r = r0 + half*8;
                float v0 = acc[mt][nt][half*2+0] + b0;
                float v1 = acc[mt][nt][half*2+1] + b1;
                if (EPI == E_GELU){ v0 = gelu_f(v0); v1 = gelu_f(v1); }
                if (EPI == E_OUT) { v0 += extra[(size_t)r*DD + cb];
                                    v1 += extra[(size_t)r*DD + cb + 1]; }
                *(float2*)&C[(size_t)r*N + cb] = make_float2(v0, v1);
            }
        }
    }
}

// ---------------- gate2: g = sigmoid(G1 . Wg2 + bg2) ----------------
__global__ void gate2_kernel(const float* __restrict__ Wg2,
                             const float* __restrict__ bg2){
    int tok  = blockIdx.x*8 + (threadIdx.x>>5);
    int lane = threadIdx.x & 31;
    const float* r = d_G1 + (size_t)tok*DD;
    float s = 0.f;
    #pragma unroll
    for (int k = lane; k < DD; k += 32) s += r[k]*Wg2[k];
    #pragma unroll
    for (int o = 16; o; o >>= 1) s += __shfl_xor_sync(0xffffffffu, s, o);
    if (lane == 0) d_g[tok] = 1.f/(1.f + expf(-(s + bg2[0])));
}

// ---------------- per-batch inclusive cumsum of g (shfl scan) ----------------
__global__ void cumsum_kernel(){
    int b = blockIdx.x;
    int tid = threadIdx.x;
    int lane = tid & 31, warp = tid >> 5;
    __shared__ float wtot[8];
    float v[8]; float run = 0.f;
    const float* gp = d_g + b*LL + tid*8;
    #pragma unroll
    for (int i=0;i<8;i++){ run += gp[i]; v[i] = run; }
    float x = run;
    #pragma unroll
    for (int o=1;o<32;o<<=1){
        float y = __shfl_up_sync(0xffffffffu, x, o);
        if (lane >= o) x += y;
    }
    if (lane == 31) wtot[warp] = x;
    __syncthreads();
    if (warp == 0 && lane < 8){
        float t = wtot[lane];
        #pragma unroll
        for (int o=1;o<8;o<<=1){
            float z = __shfl_up_sync(0xffu, t, o);
            if (lane >= o) t += z;
        }
        wtot[lane] = t;
    }
    __syncthreads();
    float off = (x - run) + (warp ? wtot[warp-1] : 0.f);
    float* gc = d_gc + b*LL + tid*8;
    #pragma unroll
    for (int i=0;i<8;i++) gc[i] = v[i] + off;
}

// ---------------- chunk state (MMA): S_c = K~^T @ (v*g), M=64 N=256 K=128 ----------------
__global__ void __launch_bounds__(256) chunk_state_kernel(){
    __shared__ float sA[64*36];
    __shared__ float sB[32*264];
    const int cc = blockIdx.x, b = blockIdx.y;
    const int tid = threadIdx.x;
    const int wid = tid >> 5, lane = tid & 31;
    const int grp = lane >> 2, tig = lane & 3;
    const int wm = wid >> 2;
    const int wn = wid & 3;

    float acc[2][8][4];
    #pragma unroll
    for (int mt=0;mt<2;mt++)
        #pragma unroll
        for (int nt=0;nt<8;nt++)
            #pragma unroll
            for (int i=0;i<4;i++) acc[mt][nt][i]=0.f;

    for (int tile = 0; tile < 4; tile++){
        int t0 = cc*CH + tile*32;
        for (int i = tid; i < 64*32; i += 256){
            int p = i>>5, t = i&31;
            int gt = t0 + t;
            sA[p*36 + t] = (gt >= 1) ? f2tf_as_f(phasor(b, gt-1, p)) : 0.f;
        }
        for (int i = tid; i < 32*64; i += 256){
            int t = i>>6, c4 = (i&63)*4;
            float gv = d_g[b*LL + t0 + t];
            float4 v = *(const float4*)&d_v[((size_t)(b*LL + t0 + t))*DD + c4];
            v.x = f2tf_as_f(v.x*gv); v.y = f2tf_as_f(v.y*gv);
            v.z = f2tf_as_f(v.z*gv); v.w = f2tf_as_f(v.w*gv);
            *(float4*)&sB[t*264 + c4] = v;
        }
        __syncthreads();
        #pragma unroll
        for (int ks = 0; ks < 32; ks += 8){
            uint32_t afr[2][4], bfr[8][2];
            #pragma unroll
            for (int mt=0; mt<2; mt++){
                int rb = wm*32 + mt*16 + grp;
                afr[mt][0] = fb(sA[(rb  )*36 + ks + tig    ]);
                afr[mt][1] = fb(sA[(rb+8)*36 + ks + tig    ]);
                afr[mt][2] = fb(sA[(rb  )*36 + ks + tig + 4]);
                afr[mt][3] = fb(sA[(rb+8)*36 + ks + tig + 4]);
            }
            #pragma unroll
            for (int nt=0; nt<8; nt++){
                int cb = wn*64 + nt*8 + grp;
                bfr[nt][0] = fb(sB[(ks + tig    )*264 + cb]);
                bfr[nt][1] = fb(sB[(ks + tig + 4)*264 + cb]);
            }
            #pragma unroll
            for (int mt=0; mt<2; mt++)
                #pragma unroll
                for (int nt=0; nt<8; nt++)
                    mma_tf32(acc[mt][nt], afr[mt], bfr[nt]);
        }
        __syncthreads();
    }
    size_t base = ((size_t)(b*NCH + cc))*64*DD;
    #pragma unroll
    for (int mt=0; mt<2; mt++)
        #pragma unroll
        for (int nt=0; nt<8; nt++)
            #pragma unroll
            for (int half=0; half<2; half++){
                int row = wm*32 + mt*16 + grp + half*8;
                int col = wn*64 + nt*8 + 2*tig;
                *(float2*)&d_state[base + (size_t)row*DD + col] =
                    make_float2(acc[mt][nt][half*2], acc[mt][nt][half*2+1]);
            }
}

// ---------------- exclusive prefix of states over chunks ----------------
__global__ void chunk_prefix_kernel(){
    int b = blockIdx.x, gs = blockIdx.y;
    int off = gs*1024 + threadIdx.x*4;
    float4 run = make_float4(0.f,0.f,0.f,0.f);
    for (int c = 0; c < NCH; c++){
        size_t base = ((size_t)(b*NCH + c))*16384 + off;
        float4 v = *(const float4*)&d_state[base];
        *(float4*)&d_pref[base] = run;
        run.x += v.x; run.y += v.y; run.z += v.z; run.w += v.w;
    }
}

// ---------------- chunk output (MMA, fused scores): ret = mask(Q K^T) @ Vg + Q @ P ----------------
#define OUT_SMEM ((128*68 + 64*136 + 128*132 + 128*72 + 64*72)*(int)sizeof(float))
__global__ void __launch_bounds__(256) chunk_out_kernel(){
    extern __shared__ __align__(16) float sm[];
    float* sQ  = sm;                 // 128 x 68  (A side: Q phasors)
    float* sKT = sQ + 128*68;        // 64 x 136  (B side: K^T phasors)
    float* sS  = sKT + 64*136;       // 128 x 132 (A side: masked scores)
    float* sV  = sS + 128*132;       // 128 x 72  (B side: Vg, 64-col split)
    float* sP  = sV + 128*72;        // 64 x 72   (B side: prefix, 64-col split)
    const int cc = blockIdx.x, ds = blockIdx.y, b = blockIdx.z;
    const int tid = threadIdx.x;
    const int wid = tid >> 5, lane = tid & 31;
    const int grp = lane >> 2, tig = lane & 3;
    const int wm = wid >> 1;      // 0..3  rows 32
    const int wn = wid & 1;       // 0..1

    for (int i = tid; i < CH*64; i += 256){
        int r = i>>6, c = i&63;
        sQ[r*68 + c] = f2tf_as_f(phasor(b, cc*CH + r, c));
    }
    for (int i = tid; i < CH*64; i += 256){
        int t = i>>6, c = i&63;
        int gt = cc*CH + t;
        sKT[c*136 + t] = (gt >= 1) ? f2tf_as_f(phasor(b, gt-1, c)) : 0.f;
    }
    for (int i = tid; i < 128*16; i += 256){
        int t = i>>4, c4 = (i&15)*4;
        float gv = d_g[b*LL + cc*CH + t];
        float4 v = *(const float4*)&d_v[((size_t)(b*LL + cc*CH + t))*DD + ds*64 + c4];
        v.x = f2tf_as_f(v.x*gv); v.y = f2tf_as_f(v.y*gv);
        v.z = f2tf_as_f(v.z*gv); v.w = f2tf_as_f(v.w*gv);
        *(float4*)&sV[t*72 + c4] = v;
    }
    size_t pbase = ((size_t)(b*NCH + cc))*64*DD;
    for (int i = tid; i < 64*16; i += 256){
        int p = i>>4, c4 = (i&15)*4;
        float4 v = *(const float4*)&d_pref[pbase + (size_t)p*DD + ds*64 + c4];
        v.x = f2tf_as_f(v.x); v.y = f2tf_as_f(v.y);
        v.z = f2tf_as_f(v.z); v.w = f2tf_as_f(v.w);
        *(float4*)&sP[p*72 + c4] = v;
    }
    __syncthreads();

    // ---- scores: 128x128 = Q(128x64) @ K^T(64x128), masked, into sS ----
    {
        float acc2[2][8][4];
        #pragma unroll
        for (int mt=0;mt<2;mt++)
            #pragma unroll
            for (int nt=0;nt<8;nt++)
                #pragma unroll
                for (int i=0;i<4;i++) acc2[mt][nt][i]=0.f;
        #pragma unroll
        for (int ks = 0; ks < 64; ks += 8){
            uint32_t afr[2][4], bfr[8][2];
            #pragma unroll
            for (int mt=0; mt<2; mt++){
                int rb = wm*32 + mt*16 + grp;
                afr[mt][0] = fb(sQ[(rb  )*68 + ks + tig    ]);
                afr[mt][1] = fb(sQ[(rb+8)*68 + ks + tig    ]);
                afr[mt][2] = fb(sQ[(rb  )*68 + ks + tig + 4]);
                afr[mt][3] = fb(sQ[(rb+8)*68 + ks + tig + 4]);
            }
            #pragma unroll
            for (int nt=0; nt<8; nt++){
                int cb = wn*64 + nt*8 + grp;
                bfr[nt][0] = fb(sKT[(ks + tig    )*136 + cb]);
                bfr[nt][1] = fb(sKT[(ks + tig + 4)*136 + cb]);
            }
            #pragma unroll
            for (int mt=0; mt<2; mt++)
                #pragma unroll
                for (int nt=0; nt<8; nt++)
                    mma_tf32(acc2[mt][nt], afr[mt], bfr[nt]);
        }
        #pragma unroll
        for (int mt=0; mt<2; mt++)
            #pragma unroll
            for (int nt=0; nt<8; nt++)
                #pragma unroll
                for (int half=0; half<2; half++){
                    int row = wm*32 + mt*16 + grp + half*8;
                    int col = wn*64 + nt*8 + 2*tig;
                    sS[row*132 + col    ] = (col   <= row) ? acc2[mt][nt][half*2  ] : 0.f;
                    sS[row*132 + col + 1] = (col+1 <= row) ? acc2[mt][nt][half*2+1] : 0.f;
                }
    }
    __syncthreads();

    // ---- out: S(128x128)@V(128x64) + Q(128x64)@P(64x64) ----
    float acc[2][4][4];
    #pragma unroll
    for (int mt=0;mt<2;mt++)
        #pragma unroll
        for (int nt=0;nt<4;nt++)
            #pragma unroll
            for (int i=0;i<4;i++) acc[mt][nt][i]=0.f;

    #pragma unroll 4
    for (int ks = 0; ks < 128; ks += 8){
        uint32_t afr[2][4], bfr[4][2];
        #pragma unroll
        for (int mt=0; mt<2; mt++){
            int rb = wm*32 + mt*16 + grp;
            afr[mt][0] = fb(sS[(rb  )*132 + ks + tig    ]);
            afr[mt][1] = fb(sS[(rb+8)*132 + ks + tig    ]);
            afr[mt][2] = fb(sS[(rb  )*132 + ks + tig + 4]);
            afr[mt][3] = fb(sS[(rb+8)*132 + ks + tig + 4]);
        }
        #pragma unroll
        for (int nt=0; nt<4; nt++){
            int cb = wn*32 + nt*8 + grp;
            bfr[nt][0] = fb(sV[(ks + tig    )*72 + cb]);
            bfr[nt][1] = fb(sV[(ks + tig + 4)*72 + cb]);
        }
        #pragma unroll
        for (int mt=0; mt<2; mt++)
            #pragma unroll
            for (int nt=0; nt<4; nt++)
                mma_tf32(acc[mt][nt], afr[mt], bfr[nt]);
    }
    #pragma unroll
    for (int ks = 0; ks < 64; ks += 8){
        uint32_t afr[2][4], bfr[4][2];
        #pragma unroll
        for (int mt=0; mt<2; mt++){
            int rb = wm*32 + mt*16 + grp;
            afr[mt][0] = fb(sQ[(rb  )*68 + ks + tig    ]);
            afr[mt][1] = fb(sQ[(rb+8)*68 + ks + tig    ]);
            afr[mt][2] = fb(sQ[(rb  )*68 + ks + tig + 4]);
            afr[mt][3] = fb(sQ[(rb+8)*68 + ks + tig + 4]);
        }
        #pragma unroll
        for (int nt=0; nt<4; nt++){
            int cb = wn*32 + nt*8 + grp;
            bfr[nt][0] = fb(sP[(ks + tig    )*72 + cb]);
            bfr[nt][1] = fb(sP[(ks + tig + 4)*72 + cb]);
        }
        #pragma unroll
        for (int mt=0; mt<2; mt++)
            #pragma unroll
            for (int nt=0; nt<4; nt++)
                mma_tf32(acc[mt][nt], afr[mt], bfr[nt]);
    }

    #pragma unroll
    for (int mt=0; mt<2; mt++)
        #pragma unroll
        for (int nt=0; nt<4; nt++)
            #pragma unroll
            for (int half=0; half<2; half++){
                int row = wm*32 + mt*16 + grp + half*8;
                int col = wn*32 + nt*8 + 2*tig;
                *(float2*)&d_ret[((size_t)(b*LL + cc*CH + row))*DD + ds*64 + col] =
                    make_float2(acc[mt][nt][half*2], acc[mt][nt][half*2+1]);
            }
}

// ---------------- LayerNorm (optionally with retrieval scaling) ----------------
__global__ void ln_kernel(const float* __restrict__ in,
                          const float* __restrict__ gamma,
                          const float* __restrict__ beta,
                          float* __restrict__ out, int scaled){
    int tok = blockIdx.x;
    int d = threadIdx.x;
    __shared__ float red[256];
    __shared__ float mv[2];
    float v = in[(size_t)tok*DD + d];
    if (scaled){
        float gcv = fmaxf(d_gc[tok], 1.0f);
        v *= rsqrtf(gcv) * 0.17677669529663687f;   // 1/sqrt(P)
    }
    red[d] = v; __syncthreads();
    #pragma unroll
    for (int o=128;o;o>>=1){ if (d<o) red[d]+=red[d+o]; __syncthreads(); }
    if (d==0) mv[0] = red[0]*(1.f/256.f);
    __syncthreads();
    float m = mv[0];
    float dv = v - m;
    red[d] = dv*dv; __syncthreads();
    #pragma unroll
    for (int o=128;o;o>>=1){ if (d<o) red[d]+=red[d+o]; __syncthreads(); }
    if (d==0) mv[1] = red[0]*(1.f/256.f);
    __syncthreads();
    float var = mv[1];
    out[(size_t)tok*DD + d] = dv*rsqrtf(var + 1e-5f)*gamma[d] + beta[d];
}

// ---------------- launch ----------------
extern "C" void kernel_launch(void* const* d_in, const int* in_sizes, int n_in,
                              void* d_out, int out_size)
{
    const float* x    = (const float*)d_in[0];
    const float* Wk   = (const float*)d_in[1];
    const float* bk   = (const float*)d_in[2];
    const float* Wv   = (const float*)d_in[3];
    const float* bv   = (const float*)d_in[4];
    const float* Wg1  = (const float*)d_in[5];
    const float* bg1  = (const float*)d_in[6];
    const float* Wg2  = (const float*)d_in[7];
    const float* bg2  = (const float*)d_in[8];
    const float* ln1g = (const float*)d_in[9];
    const float* ln1b = (const float*)d_in[10];
    const float* Wr1  = (const float*)d_in[11];
    const float* br1  = (const float*)d_in[12];
    const float* Wr2  = (const float*)d_in[13];
    const float* br2  = (const float*)d_in[14];
    const float* ln2g = (const float*)d_in[15];
    const float* ln2b = (const float*)d_in[16];
    const float* Wo   = (const float*)d_in[17];
    const float* bo   = (const float*)d_in[18];
    float* out = (float*)d_out;

    float *p_v, *p_ret, *p_G1, *p_h, *p_t1, *p_t2, *p_n2;
    cudaGetSymbolAddress((void**)&p_v,   d_v);
    cudaGetSymbolAddress((void**)&p_ret, d_ret);
    cudaGetSymbolAddress((void**)&p_G1,  d_G1);
    cudaGetSymbolAddress((void**)&p_h,   d_h);
    cudaGetSymbolAddress((void**)&p_t1,  d_t1);
    cudaGetSymbolAddress((void**)&p_t2,  d_t2);
    cudaGetSymbolAddress((void**)&p_n2,  d_n2);

    // Resource-only static init (identical device work every call; created on
    // the pre-capture correctness invocation).
    static cudaStream_t sA = 0, sB = 0;
    static cudaEvent_t eRoot = 0, ePh = 0, eV = 0, eG = 0, eC = 0;
    if (!sA){
        cudaStreamCreateWithFlags(&sA, cudaStreamNonBlocking);
        cudaStreamCreateWithFlags(&sB, cudaStreamNonBlocking);
        cudaEventCreateWithFlags(&eRoot, cudaEventDisableTiming);
        cudaEventCreateWithFlags(&ePh,   cudaEventDisableTiming);
        cudaEventCreateWithFlags(&eV,    cudaEventDisableTiming);
        cudaEventCreateWithFlags(&eG,    cudaEventDisableTiming);
        cudaEventCreateWithFlags(&eC,    cudaEventDisableTiming);

        cudaFuncSetAttribute(gemm_tf32_kernel<A_CONCAT,E_GELU>, cudaFuncAttributeMaxDynamicSharedMemorySize, GEMM_SMEM);
        cudaFuncSetAttribute(gemm_tf32_kernel<A_PLAIN,E_NONE>,  cudaFuncAttributeMaxDynamicSharedMemorySize, GEMM_SMEM);
        cudaFuncSetAttribute(gemm_tf32_kernel<A_PLAIN,E_GELU>,  cudaFuncAttributeMaxDynamicSharedMemorySize, GEMM_SMEM);
        cudaFuncSetAttribute(gemm_tf32_kernel<A_PLAIN,E_OUT>,   cudaFuncAttributeMaxDynamicSharedMemorySize, GEMM_SMEM);
        cudaFuncSetAttribute(chunk_out_kernel, cudaFuncAttributeMaxDynamicSharedMemorySize, OUT_SMEM);
    }

    // fork roots
    cudaEventRecord(eRoot, 0);
    cudaStreamWaitEvent(sA, eRoot, 0);
    cudaStreamWaitEvent(sB, eRoot, 0);

    // branch A: phases (dep: x)
    phases_kernel<<<NTOK/8, 256, 0, sA>>>(x, Wk, bk);
    cudaEventRecord(ePh, sA);

    // branch B: values GEMM (dep: x)
    gemm_tf32_kernel<A_PLAIN, E_NONE><<<dim3(DD/64, NTOK/128), 256, GEMM_SMEM, sB>>>(x, Wv, bv, p_v, nullptr, NTOK, DD, DD);
    cudaEventRecord(eV, sB);

    // main: gate chain
    gemm_tf32_kernel<A_CONCAT, E_GELU><<<dim3(DD/64, NTOK/128), 256, GEMM_SMEM>>>(x, Wg1, bg1, p_G1, nullptr, NTOK, DD, 2*DD);
    gate2_kernel<<<NTOK/8, 256>>>(Wg2, bg2);
    cudaEventRecord(eG, 0);

    // branch B (cont.): cumsum after gate2
    cudaStreamWaitEvent(sB, eG, 0);
    cumsum_kernel<<<BB, 256, 0, sB>>>();
    cudaEventRecord(eC, sB);

    // main: attention chain (needs phases + values + g)
    cudaStreamWaitEvent(0, ePh, 0);
    cudaStreamWaitEvent(0, eV, 0);
    chunk_state_kernel<<<dim3(NCH, BB), 256>>>();
    chunk_prefix_kernel<<<dim3(BB, 16), 256>>>();
    chunk_out_kernel<<<dim3(NCH, 4, BB), 256, OUT_SMEM>>>();

    // join cumsum before scaled LN
    cudaStreamWaitEvent(0, eC, 0);
    ln_kernel<<<NTOK, 256>>>(p_ret, ln1g, ln1b, p_h, 1);
    gemm_tf32_kernel<A_PLAIN, E_GELU><<<dim3(2*DD/64, NTOK/128), 256, GEMM_SMEM>>>(p_h, Wr1, br1, p_t1, nullptr, NTOK, 2*DD, DD);
    gemm_tf32_kernel<A_PLAIN, E_NONE><<<dim3(DD/64, NTOK/128), 256, GEMM_SMEM>>>(p_t1, Wr2, br2, p_t2, nullptr, NTOK, DD, 2*DD);
    ln_kernel<<<NTOK, 256>>>(p_t2, ln2g, ln2b, p_n2, 0);
    gemm_tf32_kernel<A_PLAIN, E_OUT><<<dim3(DD/64, NTOK/128), 256, GEMM_SMEM>>>(p_n2, Wo, bo, out, x, NTOK, DD, DD);
    (void)in_sizes; (void)n_in; (void)out_size;
}

// round 7
// speedup vs baseline: 2.5640x; 1.0922x over previous
#include <cuda_runtime.h>
#include <math.h>
#include <stdint.h>

#define BB 2
#define LL 2048
#define DD 256
#define PP 32
#define NTOK (BB*LL)
#define NCH 16
#define CH 128

// ---------------- scratch ----------------
__device__ float d_cq[NTOK*PP];
__device__ float d_sq[NTOK*PP];
__device__ float d_g [NTOK];
__device__ float d_gc[NTOK];
__device__ float d_v [NTOK*DD];           // ungated values
__device__ float d_ret[NTOK*DD];          // scaled retrieval (LN1 input)
__device__ float d_t1[NTOK*2*DD];
__device__ float d_t2[NTOK*DD];           // refined (LN2 input)
__device__ float d_state[BB*NCH*64*DD];
__device__ float d_pref [BB*NCH*64*DD];
__device__ float d_gpart[8*NTOK];         // gate partial dots
__device__ float d_s1 [NTOK];             // LN1 row sums
__device__ float d_s2 [NTOK];             // LN1 row sumsq
__device__ float d_s1b[NTOK];             // LN2 row sums
__device__ float d_s2b[NTOK];             // LN2 row sumsq

__device__ __forceinline__ float gelu_f(float x){
    return 0.5f*x*(1.0f+erff(x*0.7071067811865476f));
}
__device__ __forceinline__ float phasor(int b, int tok, int c){
    int t = b*LL + tok;
    return (c < 32) ? d_cq[t*PP + c] : d_sq[t*PP + c - 32];
}
__device__ __forceinline__ uint32_t f2tf(float f){
    uint32_t r; asm("cvt.rna.tf32.f32 %0, %1;" : "=r"(r) : "f"(f)); return r;
}
__device__ __forceinline__ uint32_t fb(float f){ return __float_as_uint(f); }
__device__ __forceinline__ float f2tf_as_f(float f){
    uint32_t r = f2tf(f); return __uint_as_float(r);
}
__device__ __forceinline__ void mma_tf32(float* c, const uint32_t* a, const uint32_t* b){
    asm volatile(
      "mma.sync.aligned.m16n8k8.row.col.f32.tf32.tf32.f32 "
      "{%0,%1,%2,%3}, {%4,%5,%6,%7}, {%8,%9}, {%0,%1,%2,%3};\n"
      : "+f"(c[0]), "+f"(c[1]), "+f"(c[2]), "+f"(c[3])
      : "r"(a[0]), "r"(a[1]), "r"(a[2]), "r"(a[3]), "r"(b[0]), "r"(b[1]));
}
__device__ __forceinline__ void cp16(uint32_t dst, const void* src, int sz){
    asm volatile("cp.async.cg.shared.global [%0], [%1], 16, %2;\n"
                 :: "r"(dst), "l"(src), "r"(sz));
}
__device__ __forceinline__ void cp_commit(){ asm volatile("cp.async.commit_group;\n"); }
__device__ __forceinline__ void cp_wait1(){ asm volatile("cp.async.wait_group 1;\n"); }

// ---------------- phases ----------------
__global__ void phases_kernel(const float* __restrict__ x,
                              const float* __restrict__ Wk,
                              const float* __restrict__ bk){
    int tok = blockIdx.x*8 + (threadIdx.x>>5);
    int p   = threadIdx.x & 31;
    const float* xr = x + tok*DD;
    float s = bk[p];
    #pragma unroll 8
    for (int k = 0; k < DD; k++) s += xr[k]*Wk[k*PP + p];
    float ph = tanhf(s)*3.14159265358979323846f;
    float sn, cs;
    sincosf(ph, &sn, &cs);
    d_cq[tok*PP + p] = cs;
    d_sq[tok*PP + p] = sn;
}

// ---------------- fused tf32 GEMM ----------------
#define A_PLAIN  0
#define A_CONCAT 1   // A = [x, shift(x)]
#define A_LN     2   // LayerNorm(A) on the fly from moment stats
#define E_NONE 0
#define E_GELU 1
#define E_OUT  3     // + extra residual
#define E_GATE 4     // dot with gw -> gpart (no C write)
#define E_STAT 5     // write C + accumulate row stats

#define APITCH 36
#define WPITCH 72
#define GEMM_SMEM ((2*128*APITCH + 2*32*WPITCH)*(int)sizeof(float))

template<int AMODE, int EPI>
__global__ void __launch_bounds__(256)
gemm_tf32_kernel(const float* __restrict__ A,
                 const float* __restrict__ W,
                 const float* __restrict__ bias,
                 float* __restrict__ C,
                 const float* __restrict__ extra,
                 const float* __restrict__ lnS1, const float* __restrict__ lnS2,
                 const float* __restrict__ lnG,  const float* __restrict__ lnB,
                 float* __restrict__ oS1, float* __restrict__ oS2,
                 const float* __restrict__ gw, float* __restrict__ gpart,
                 int M, int N, int K)
{
    extern __shared__ __align__(16) float smem[];
    float* Asm = smem;
    float* Wsm = smem + 2*128*APITCH;

    const int tid = threadIdx.x;
    const int wid = tid >> 5;
    const int lane = tid & 31;
    const int grp = lane >> 2;
    const int tig = lane & 3;
    const int wm = wid >> 1;
    const int wn = wid & 1;
    const int n0 = blockIdx.x*64;
    const int m0 = blockIdx.y*128;

    float acc[2][4][4];
    #pragma unroll
    for (int mt=0;mt<2;mt++)
        #pragma unroll
        for (int nt=0;nt<4;nt++)
            #pragma unroll
            for (int i=0;i<4;i++) acc[mt][nt][i]=0.f;

    // A_LN state
    float4 areg[4]; float4 gv4, bv4;
    float mrow[4], rsrow[4];
    if (AMODE == A_LN){
        #pragma unroll
        for (int it=0; it<4; it++){
            int r = m0 + (tid>>3) + it*32;
            float sa = lnS1[r], sb = lnS2[r];
            float mean = sa*(1.f/256.f);
            float var = fmaxf(sb*(1.f/256.f) - mean*mean, 0.f);
            mrow[it] = mean;
            rsrow[it] = rsqrtf(var + 1e-5f);
        }
    }

    auto ldA_regs = [&](int k0){
        int kq = (tid & 7)*4;
        gv4 = *(const float4*)&lnG[k0+kq];
        bv4 = *(const float4*)&lnB[k0+kq];
        #pragma unroll
        for (int it=0; it<4; it++){
            int r = m0 + (tid>>3) + it*32;
            areg[it] = *(const float4*)&A[(size_t)r*K + k0 + kq];
        }
    };
    auto stA = [&](int buf){
        float* As = Asm + buf*128*APITCH;
        int kq = (tid & 7)*4;
        #pragma unroll
        for (int it=0; it<4; it++){
            int row = (tid>>3) + it*32;
            float4 v = areg[it];
            v.x = (v.x - mrow[it])*rsrow[it]*gv4.x + bv4.x;
            v.y = (v.y - mrow[it])*rsrow[it]*gv4.y + bv4.y;
            v.z = (v.z - mrow[it])*rsrow[it]*gv4.z + bv4.z;
            v.w = (v.w - mrow[it])*rsrow[it]*gv4.w + bv4.w;
            *(float4*)&As[row*APITCH + kq] = v;
        }
    };

    auto load_tiles = [&](int buf, int k0){
        float* As = Asm + buf*128*APITCH;
        float* Ws = Wsm + buf*32*WPITCH;
        if (AMODE != A_LN){
            #pragma unroll
            for (int it = 0; it < 4; it++){
                int linear = tid + it*256;
                int row = linear >> 3;
                int kq  = (linear & 7)*4;
                int m = m0 + row;
                int kg = k0 + kq;
                const float* src; int sz = 16;
                if (AMODE == A_PLAIN){
                    src = A + (size_t)m*K + kg;
                } else {
                    if (kg < DD) src = A + (size_t)m*DD + kg;
                    else {
                        int l = m & (LL-1);
                        if (l == 0){ sz = 0; src = A; }
                        else src = A + (size_t)(m-1)*DD + (kg-DD);
                    }
                }
                cp16((uint32_t)__cvta_generic_to_shared(&As[row*APITCH + kq]), src, sz);
            }
        }
        #pragma unroll
        for (int it = 0; it < 2; it++){
            int linear = tid + it*256;
            int row = linear >> 4;
            int wnq = (linear & 15)*4;
            const float* src = W + (size_t)(k0+row)*N + n0 + wnq;
            cp16((uint32_t)__cvta_generic_to_shared(&Ws[row*WPITCH + wnq]), src, 16);
        }
    };

    const int ntiles = K >> 5;
    if (AMODE == A_LN) ldA_regs(0);
    load_tiles(0, 0);
    cp_commit();
    if (AMODE == A_LN) stA(0);

    for (int kt = 0; kt < ntiles; kt++){
        int buf = kt & 1;
        if (kt+1 < ntiles){
            if (AMODE == A_LN) ldA_regs((kt+1)*32);
            load_tiles(buf^1, (kt+1)*32);
        }
        cp_commit();
        cp_wait1();
        __syncthreads();

        const float* As = Asm + buf*128*APITCH;
        const float* Ws = Wsm + buf*32*WPITCH;
        #pragma unroll
        for (int ks = 0; ks < 32; ks += 8){
            uint32_t afr[2][4], bfr[4][2];
            #pragma unroll
            for (int mt=0; mt<2; mt++){
                int rb = wm*32 + mt*16 + grp;
                afr[mt][0] = fb(As[(rb  )*APITCH + ks + tig    ]);
                afr[mt][1] = fb(As[(rb+8)*APITCH + ks + tig    ]);
                afr[mt][2] = fb(As[(rb  )*APITCH + ks + tig + 4]);
                afr[mt][3] = fb(As[(rb+8)*APITCH + ks + tig + 4]);
            }
            #pragma unroll
            for (int nt=0; nt<4; nt++){
                int cb = wn*32 + nt*8 + grp;
                bfr[nt][0] = fb(Ws[(ks + tig    )*WPITCH + cb]);
                bfr[nt][1] = fb(Ws[(ks + tig + 4)*WPITCH + cb]);
            }
            #pragma unroll
            for (int mt=0; mt<2; mt++)
                #pragma unroll
                for (int nt=0; nt<4; nt++)
                    mma_tf32(acc[mt][nt], afr[mt], bfr[nt]);
        }
        if (AMODE == A_LN && kt+1 < ntiles) stA(buf^1);
        __syncthreads();
    }

    // ---- epilogues ----
    if (EPI == E_GATE){
        #pragma unroll
        for (int mt=0; mt<2; mt++){
            #pragma unroll
            for (int half=0; half<2; half++){
                int r = m0 + wm*32 + mt*16 + grp + half*8;
                float part = 0.f;
                #pragma unroll
                for (int nt=0; nt<4; nt++){
                    int cb = n0 + wn*32 + nt*8 + 2*tig;
                    float v0 = gelu_f(acc[mt][nt][half*2+0] + bias[cb]);
                    float v1 = gelu_f(acc[mt][nt][half*2+1] + bias[cb+1]);
                    part += v0*gw[cb] + v1*gw[cb+1];
                }
                part += __shfl_xor_sync(0xffffffffu, part, 1);
                part += __shfl_xor_sync(0xffffffffu, part, 2);
                if (tig == 0)
                    gpart[(blockIdx.x*2 + wn)*M + r] = part;
            }
        }
        return;
    }

    #pragma unroll
    for (int mt=0; mt<2; mt++){
        #pragma unroll
        for (int half=0; half<2; half++){
            int r = m0 + wm*32 + mt*16 + grp + half*8;
            float s = 0.f, ss = 0.f;
            #pragma unroll
            for (int nt=0; nt<4; nt++){
                int cb = n0 + wn*32 + nt*8 + 2*tig;
                float v0 = acc[mt][nt][half*2+0] + bias[cb];
                float v1 = acc[mt][nt][half*2+1] + bias[cb+1];
                if (EPI == E_GELU){ v0 = gelu_f(v0); v1 = gelu_f(v1); }
                if (EPI == E_OUT) { v0 += extra[(size_t)r*DD + cb];
                                    v1 += extra[(size_t)r*DD + cb + 1]; }
                if (EPI == E_STAT){ s += v0 + v1; ss += v0*v0 + v1*v1; }
                *(float2*)&C[(size_t)r*N + cb] = make_float2(v0, v1);
            }
            if (EPI == E_STAT){
                s  += __shfl_xor_sync(0xffffffffu, s, 1);
                s  += __shfl_xor_sync(0xffffffffu, s, 2);
                ss += __shfl_xor_sync(0xffffffffu, ss, 1);
                ss += __shfl_xor_sync(0xffffffffu, ss, 2);
                if (tig == 0){
                    atomicAdd(&oS1[r], s);
                    atomicAdd(&oS2[r], ss);
                }
            }
        }
    }
}

// ---------------- cumsum: finalize gate + scan + zero stats ----------------
__global__ void cumsum_kernel(const float* __restrict__ bg2){
    int b = blockIdx.x;
    int tid = threadIdx.x;
    int lane = tid & 31, warp = tid >> 5;
    __shared__ float wtot[8];
    // zero LN stat buffers for this batch's tokens
    for (int i = tid; i < LL; i += 256){
        int tok = b*LL + i;
        d_s1[tok] = 0.f; d_s2[tok] = 0.f;
        d_s1b[tok] = 0.f; d_s2b[tok] = 0.f;
    }
    float bv = bg2[0];
    float v[8]; float run = 0.f;
    #pragma unroll
    for (int i=0;i<8;i++){
        int tok = b*LL + tid*8 + i;
        float s = bv;
        #pragma unroll
        for (int j=0;j<8;j++) s += d_gpart[j*NTOK + tok];
        float g = 1.f/(1.f + expf(-s));
        d_g[tok] = g;
        run += g; v[i] = run;
    }
    float x = run;
    #pragma unroll
    for (int o=1;o<32;o<<=1){
        float y = __shfl_up_sync(0xffffffffu, x, o);
        if (lane >= o) x += y;
    }
    if (lane == 31) wtot[warp] = x;
    __syncthreads();
    if (warp == 0 && lane < 8){
        float t = wtot[lane];
        #pragma unroll
        for (int o=1;o<8;o<<=1){
            float z = __shfl_up_sync(0xffu, t, o);
            if (lane >= o) t += z;
        }
        wtot[lane] = t;
    }
    __syncthreads();
    float off = (x - run) + (warp ? wtot[warp-1] : 0.f);
    float* gc = d_gc + b*LL + tid*8;
    #pragma unroll
    for (int i=0;i<8;i++) gc[i] = v[i] + off;
}

// ---------------- chunk state (MMA) ----------------
__global__ void __launch_bounds__(256) chunk_state_kernel(){
    __shared__ float sA[64*36];
    __shared__ float sB[32*264];
    const int cc = blockIdx.x, b = blockIdx.y;
    const int tid = threadIdx.x;
    const int wid = tid >> 5, lane = tid & 31;
    const int grp = lane >> 2, tig = lane & 3;
    const int wm = wid >> 2;
    const int wn = wid & 3;

    float acc[2][8][4];
    #pragma unroll
    for (int mt=0;mt<2;mt++)
        #pragma unroll
        for (int nt=0;nt<8;nt++)
            #pragma unroll
            for (int i=0;i<4;i++) acc[mt][nt][i]=0.f;

    for (int tile = 0; tile < 4; tile++){
        int t0 = cc*CH + tile*32;
        for (int i = tid; i < 64*32; i += 256){
            int p = i>>5, t = i&31;
            int gt = t0 + t;
            sA[p*36 + t] = (gt >= 1) ? f2tf_as_f(phasor(b, gt-1, p)) : 0.f;
        }
        for (int i = tid; i < 32*64; i += 256){
            int t = i>>6, c4 = (i&63)*4;
            float gv = d_g[b*LL + t0 + t];
            float4 v = *(const float4*)&d_v[((size_t)(b*LL + t0 + t))*DD + c4];
            v.x = f2tf_as_f(v.x*gv); v.y = f2tf_as_f(v.y*gv);
            v.z = f2tf_as_f(v.z*gv); v.w = f2tf_as_f(v.w*gv);
            *(float4*)&sB[t*264 + c4] = v;
        }
        __syncthreads();
        #pragma unroll
        for (int ks = 0; ks < 32; ks += 8){
            uint32_t afr[2][4], bfr[8][2];
            #pragma unroll
            for (int mt=0; mt<2; mt++){
                int rb = wm*32 + mt*16 + grp;
                afr[mt][0] = fb(sA[(rb  )*36 + ks + tig    ]);
                afr[mt][1] = fb(sA[(rb+8)*36 + ks + tig    ]);
                afr[mt][2] = fb(sA[(rb  )*36 + ks + tig + 4]);
                afr[mt][3] = fb(sA[(rb+8)*36 + ks + tig + 4]);
            }
            #pragma unroll
            for (int nt=0; nt<8; nt++){
                int cb = wn*64 + nt*8 + grp;
                bfr[nt][0] = fb(sB[(ks + tig    )*264 + cb]);
                bfr[nt][1] = fb(sB[(ks + tig + 4)*264 + cb]);
            }
            #pragma unroll
            for (int mt=0; mt<2; mt++)
                #pragma unroll
                for (int nt=0; nt<8; nt++)
                    mma_tf32(acc[mt][nt], afr[mt], bfr[nt]);
        }
        __syncthreads();
    }
    size_t base = ((size_t)(b*NCH + cc))*64*DD;
    #pragma unroll
    for (int mt=0; mt<2; mt++)
        #pragma unroll
        for (int nt=0; nt<8; nt++)
            #pragma unroll
            for (int half=0; half<2; half++){
                int row = wm*32 + mt*16 + grp + half*8;
                int col = wn*64 + nt*8 + 2*tig;
                *(float2*)&d_state[base + (size_t)row*DD + col] =
                    make_float2(acc[mt][nt][half*2], acc[mt][nt][half*2+1]);
            }
}

// ---------------- exclusive prefix over chunks ----------------
__global__ void chunk_prefix_kernel(){
    int b = blockIdx.x, gs = blockIdx.y;
    int off = gs*1024 + threadIdx.x*4;
    float4 run = make_float4(0.f,0.f,0.f,0.f);
    for (int c = 0; c < NCH; c++){
        size_t base = ((size_t)(b*NCH + c))*16384 + off;
        float4 v = *(const float4*)&d_state[base];
        *(float4*)&d_pref[base] = run;
        run.x += v.x; run.y += v.y; run.z += v.z; run.w += v.w;
    }
}

// ---------------- chunk output (MMA, fused scores + scale + LN1 stats) ----------------
#define OUT_SMEM ((128*68 + 64*136 + 128*132 + 128*72 + 64*72)*(int)sizeof(float))
__global__ void __launch_bounds__(256) chunk_out_kernel(){
    extern __shared__ __align__(16) float sm[];
    float* sQ  = sm;
    float* sKT = sQ + 128*68;
    float* sS  = sKT + 64*136;
    float* sV  = sS + 128*132;
    float* sP  = sV + 128*72;
    const int cc = blockIdx.x, ds = blockIdx.y, b = blockIdx.z;
    const int tid = threadIdx.x;
    const int wid = tid >> 5, lane = tid & 31;
    const int grp = lane >> 2, tig = lane & 3;
    const int wm = wid >> 1;
    const int wn = wid & 1;

    for (int i = tid; i < CH*64; i += 256){
        int r = i>>6, c = i&63;
        sQ[r*68 + c] = f2tf_as_f(phasor(b, cc*CH + r, c));
    }
    for (int i = tid; i < CH*64; i += 256){
        int t = i>>6, c = i&63;
        int gt = cc*CH + t;
        sKT[c*136 + t] = (gt >= 1) ? f2tf_as_f(phasor(b, gt-1, c)) : 0.f;
    }
    for (int i = tid; i < 128*16; i += 256){
        int t = i>>4, c4 = (i&15)*4;
        float gv = d_g[b*LL + cc*CH + t];
        float4 v = *(const float4*)&d_v[((size_t)(b*LL + cc*CH + t))*DD + ds*64 + c4];
        v.x = f2tf_as_f(v.x*gv); v.y = f2tf_as_f(v.y*gv);
        v.z = f2tf_as_f(v.z*gv); v.w = f2tf_as_f(v.w*gv);
        *(float4*)&sV[t*72 + c4] = v;
    }
    size_t pbase = ((size_t)(b*NCH + cc))*64*DD;
    for (int i = tid; i < 64*16; i += 256){
        int p = i>>4, c4 = (i&15)*4;
        float4 v = *(const float4*)&d_pref[pbase + (size_t)p*DD + ds*64 + c4];
        v.x = f2tf_as_f(v.x); v.y = f2tf_as_f(v.y);
        v.z = f2tf_as_f(v.z); v.w = f2tf_as_f(v.w);
        *(float4*)&sP[p*72 + c4] = v;
    }
    __syncthreads();

    // scores
    {
        float acc2[2][8][4];
        #pragma unroll
        for (int mt=0;mt<2;mt++)
            #pragma unroll
            for (int nt=0;nt<8;nt++)
                #pragma unroll
                for (int i=0;i<4;i++) acc2[mt][nt][i]=0.f;
        #pragma unroll
        for (int ks = 0; ks < 64; ks += 8){
            uint32_t afr[2][4], bfr[8][2];
            #pragma unroll
            for (int mt=0; mt<2; mt++){
                int rb = wm*32 + mt*16 + grp;
                afr[mt][0] = fb(sQ[(rb  )*68 + ks + tig    ]);
                afr[mt][1] = fb(sQ[(rb+8)*68 + ks + tig    ]);
                afr[mt][2] = fb(sQ[(rb  )*68 + ks + tig + 4]);
                afr[mt][3] = fb(sQ[(rb+8)*68 + ks + tig + 4]);
            }
            #pragma unroll
            for (int nt=0; nt<8; nt++){
                int cb = wn*64 + nt*8 + grp;
                bfr[nt][0] = fb(sKT[(ks + tig    )*136 + cb]);
                bfr[nt][1] = fb(sKT[(ks + tig + 4)*136 + cb]);
            }
            #pragma unroll
            for (int mt=0; mt<2; mt++)
                #pragma unroll
                for (int nt=0; nt<8; nt++)
                    mma_tf32(acc2[mt][nt], afr[mt], bfr[nt]);
        }
        #pragma unroll
        for (int mt=0; mt<2; mt++)
            #pragma unroll
            for (int nt=0; nt<8; nt++)
                #pragma unroll
                for (int half=0; half<2; half++){
                    int row = wm*32 + mt*16 + grp + half*8;
                    int col = wn*64 + nt*8 + 2*tig;
                    sS[row*132 + col    ] = (col   <= row) ? acc2[mt][nt][half*2  ] : 0.f;
                    sS[row*132 + col + 1] = (col+1 <= row) ? acc2[mt][nt][half*2+1] : 0.f;
                }
    }
    __syncthreads();

    // out
    float acc[2][4][4];
    #pragma unroll
    for (int mt=0;mt<2;mt++)
        #pragma unroll
        for (int nt=0;nt<4;nt++)
            #pragma unroll
            for (int i=0;i<4;i++) acc[mt][nt][i]=0.f;

    #pragma unroll 4
    for (int ks = 0; ks < 128; ks += 8){
        uint32_t afr[2][4], bfr[4][2];
        #pragma unroll
        for (int mt=0; mt<2; mt++){
            int rb = wm*32 + mt*16 + grp;
            afr[mt][0] = fb(sS[(rb  )*132 + ks + tig    ]);
            afr[mt][1] = fb(sS[(rb+8)*132 + ks + tig    ]);
            afr[mt][2] = fb(sS[(rb  )*132 + ks + tig + 4]);
            afr[mt][3] = fb(sS[(rb+8)*132 + ks + tig + 4]);
        }
        #pragma unroll
        for (int nt=0; nt<4; nt++){
            int cb = wn*32 + nt*8 + grp;
            bfr[nt][0] = fb(sV[(ks + tig    )*72 + cb]);
            bfr[nt][1] = fb(sV[(ks + tig + 4)*72 + cb]);
        }
        #pragma unroll
        for (int mt=0; mt<2; mt++)
            #pragma unroll
            for (int nt=0; nt<4; nt++)
                mma_tf32(acc[mt][nt], afr[mt], bfr[nt]);
    }
    #pragma unroll
    for (int ks = 0; ks < 64; ks += 8){
        uint32_t afr[2][4], bfr[4][2];
        #pragma unroll
        for (int mt=0; mt<2; mt++){
            int rb = wm*32 + mt*16 + grp;
            afr[mt][0] = fb(sQ[(rb  )*68 + ks + tig    ]);
            afr[mt][1] = fb(sQ[(rb+8)*68 + ks + tig    ]);
            afr[mt][2] = fb(sQ[(rb  )*68 + ks + tig + 4]);
            afr[mt][3] = fb(sQ[(rb+8)*68 + ks + tig + 4]);
        }
        #pragma unroll
        for (int nt=0; nt<4; nt++){
            int cb = wn*32 + nt*8 + grp;
            bfr[nt][0] = fb(sP[(ks + tig    )*72 + cb]);
            bfr[nt][1] = fb(sP[(ks + tig + 4)*72 + cb]);
        }
        #pragma unroll
        for (int mt=0; mt<2; mt++)
            #pragma unroll
            for (int nt=0; nt<4; nt++)
                mma_tf32(acc[mt][nt], afr[mt], bfr[nt]);
    }

    // epilogue: gc scale, write, LN1 stats
    #pragma unroll
    for (int mt=0; mt<2; mt++){
        #pragma unroll
        for (int half=0; half<2; half++){
            int rloc = wm*32 + mt*16 + grp + half*8;
            int gtok = b*LL + cc*CH + rloc;
            float sc = rsqrtf(fmaxf(d_gc[gtok], 1.f)) * 0.17677669529663687f;
            float s = 0.f, ss = 0.f;
            #pragma unroll
            for (int nt=0; nt<4; nt++){
                int col = wn*32 + nt*8 + 2*tig;
                float v0 = acc[mt][nt][half*2+0]*sc;
                float v1 = acc[mt][nt][half*2+1]*sc;
                *(float2*)&d_ret[(size_t)gtok*DD + ds*64 + col] = make_float2(v0, v1);
                s += v0 + v1; ss += v0*v0 + v1*v1;
            }
            s  += __shfl_xor_sync(0xffffffffu, s, 1);
            s  += __shfl_xor_sync(0xffffffffu, s, 2);
            ss += __shfl_xor_sync(0xffffffffu, ss, 1);
            ss += __shfl_xor_sync(0xffffffffu, ss, 2);
            if (tig == 0){
                atomicAdd(&d_s1[gtok], s);
                atomicAdd(&d_s2[gtok], ss);
            }
        }
    }
}

// ---------------- launch ----------------
extern "C" void kernel_launch(void* const* d_in, const int* in_sizes, int n_in,
                              void* d_out, int out_size)
{
    const float* x    = (const float*)d_in[0];
    const float* Wk   = (const float*)d_in[1];
    const float* bk   = (const float*)d_in[2];
    const float* Wv   = (const float*)d_in[3];
    const float* bv   = (const float*)d_in[4];
    const float* Wg1  = (const float*)d_in[5];
    const float* bg1  = (const float*)d_in[6];
    const float* Wg2  = (const float*)d_in[7];
    const float* bg2  = (const float*)d_in[8];
    const float* ln1g = (const float*)d_in[9];
    const float* ln1b = (const float*)d_in[10];
    const float* Wr1  = (const float*)d_in[11];
    const float* br1  = (const float*)d_in[12];
    const float* Wr2  = (const float*)d_in[13];
    const float* br2  = (const float*)d_in[14];
    const float* ln2g = (const float*)d_in[15];
    const float* ln2b = (const float*)d_in[16];
    const float* Wo   = (const float*)d_in[17];
    const float* bo   = (const float*)d_in[18];
    float* out = (float*)d_out;

    float *p_v, *p_ret, *p_t1, *p_t2, *p_gpart, *p_s1, *p_s2, *p_s1b, *p_s2b;
    cudaGetSymbolAddress((void**)&p_v,    d_v);
    cudaGetSymbolAddress((void**)&p_ret,  d_ret);
    cudaGetSymbolAddress((void**)&p_t1,   d_t1);
    cudaGetSymbolAddress((void**)&p_t2,   d_t2);
    cudaGetSymbolAddress((void**)&p_gpart,d_gpart);
    cudaGetSymbolAddress((void**)&p_s1,   d_s1);
    cudaGetSymbolAddress((void**)&p_s2,   d_s2);
    cudaGetSymbolAddress((void**)&p_s1b,  d_s1b);
    cudaGetSymbolAddress((void**)&p_s2b,  d_s2b);

    static cudaStream_t sA = 0, sB = 0;
    static cudaEvent_t eRoot = 0, ePh = 0, eV = 0;
    if (!sA){
        cudaStreamCreateWithFlags(&sA, cudaStreamNonBlocking);
        cudaStreamCreateWithFlags(&sB, cudaStreamNonBlocking);
        cudaEventCreateWithFlags(&eRoot, cudaEventDisableTiming);
        cudaEventCreateWithFlags(&ePh,   cudaEventDisableTiming);
        cudaEventCreateWithFlags(&eV,    cudaEventDisableTiming);

        cudaFuncSetAttribute(gemm_tf32_kernel<A_CONCAT,E_GATE>, cudaFuncAttributeMaxDynamicSharedMemorySize, GEMM_SMEM);
        cudaFuncSetAttribute(gemm_tf32_kernel<A_PLAIN,E_NONE>,  cudaFuncAttributeMaxDynamicSharedMemorySize, GEMM_SMEM);
        cudaFuncSetAttribute(gemm_tf32_kernel<A_LN,E_GELU>,     cudaFuncAttributeMaxDynamicSharedMemorySize, GEMM_SMEM);
        cudaFuncSetAttribute(gemm_tf32_kernel<A_PLAIN,E_STAT>,  cudaFuncAttributeMaxDynamicSharedMemorySize, GEMM_SMEM);
        cudaFuncSetAttribute(gemm_tf32_kernel<A_LN,E_OUT>,      cudaFuncAttributeMaxDynamicSharedMemorySize, GEMM_SMEM);
        cudaFuncSetAttribute(chunk_out_kernel, cudaFuncAttributeMaxDynamicSharedMemorySize, OUT_SMEM);
    }

    cudaEventRecord(eRoot, 0);
    cudaStreamWaitEvent(sA, eRoot, 0);
    cudaStreamWaitEvent(sB, eRoot, 0);

    // branch A: phases
    phases_kernel<<<NTOK/8, 256, 0, sA>>>(x, Wk, bk);
    cudaEventRecord(ePh, sA);

    // branch B: values GEMM
    gemm_tf32_kernel<A_PLAIN, E_NONE><<<dim3(DD/64, NTOK/128), 256, GEMM_SMEM, sB>>>(
        x, Wv, bv, p_v, nullptr, nullptr, nullptr, nullptr, nullptr,
        nullptr, nullptr, nullptr, nullptr, NTOK, DD, DD);
    cudaEventRecord(eV, sB);

    // main: gate GEMM (partial dots) -> cumsum (gate finalize + scan + stat zero)
    gemm_tf32_kernel<A_CONCAT, E_GATE><<<dim3(DD/64, NTOK/128), 256, GEMM_SMEM>>>(
        x, Wg1, bg1, nullptr, nullptr, nullptr, nullptr, nullptr, nullptr,
        nullptr, nullptr, Wg2, p_gpart, NTOK, DD, 2*DD);
    cumsum_kernel<<<BB, 256>>>(bg2);

    // attention chain
    cudaStreamWaitEvent(0, ePh, 0);
    cudaStreamWaitEvent(0, eV, 0);
    chunk_state_kernel<<<dim3(NCH, BB), 256>>>();
    chunk_prefix_kernel<<<dim3(BB, 16), 256>>>();
    chunk_out_kernel<<<dim3(NCH, 4, BB), 256, OUT_SMEM>>>();

    // refine MLP with fused LayerNorms
    gemm_tf32_kernel<A_LN, E_GELU><<<dim3(2*DD/64, NTOK/128), 256, GEMM_SMEM>>>(
        p_ret, Wr1, br1, p_t1, nullptr, p_s1, p_s2, ln1g, ln1b,
        nullptr, nullptr, nullptr, nullptr, NTOK, 2*DD, DD);
    gemm_tf32_kernel<A_PLAIN, E_STAT><<<dim3(DD/64, NTOK/128), 256, GEMM_SMEM>>>(
        p_t1, Wr2, br2, p_t2, nullptr, nullptr, nullptr, nullptr, nullptr,
        p_s1b, p_s2b, nullptr, nullptr, NTOK, DD, 2*DD);
    gemm_tf32_kernel<A_LN, E_OUT><<<dim3(DD/64, NTOK/128), 256, GEMM_SMEM>>>(
        p_t2, Wo, bo, out, x, p_s1b, p_s2b, ln2g, ln2b,
        nullptr, nullptr, nullptr, nullptr, NTOK, DD, DD);
    (void)in_sizes; (void)n_in; (void)out_size;
}

// round 8
// speedup vs baseline: 2.7256x; 1.0630x over previous
#include <cuda_runtime.h>
#include <math.h>
#include <stdint.h>

#define BB 2
#define LL 2048
#define DD 256
#define PP 32
#define NTOK (BB*LL)
#define NCH 16
#define CH 128
#define NBLK 128

// ---------------- scratch ----------------
__device__ float d_cq[NTOK*PP];
__device__ float d_sq[NTOK*PP];
__device__ float d_g [NTOK];
__device__ float d_gc[NTOK];
__device__ float d_v [NTOK*DD];
__device__ float d_ret[NTOK*DD];
__device__ float d_t1[NTOK*2*DD];
__device__ float d_t2[NTOK*DD];
__device__ float d_state[BB*NCH*64*DD];
__device__ float d_pref [BB*NCH*64*DD];
__device__ float d_gpart[NTOK*8];        // row-contiguous gate partials
__device__ float d_s1 [8*NTOK];          // LN1 slot sums
__device__ float d_s2 [8*NTOK];
__device__ float d_s1b[8*NTOK];          // LN2 slot sums
__device__ float d_s2b[8*NTOK];

__device__ unsigned bar_cnt = 0;
__device__ unsigned bar_gen = 0;

__device__ __forceinline__ void gbar(){
    __syncthreads();
    __threadfence();
    if (threadIdx.x == 0){
        volatile unsigned* vg = &bar_gen;
        unsigned gen = *vg;
        unsigned t = atomicAdd(&bar_cnt, 1);
        if (t == gridDim.x - 1){
            atomicExch(&bar_cnt, 0);
            __threadfence();
            atomicAdd(&bar_gen, 1);
        } else {
            while (*vg == gen) { __nanosleep(32); }
        }
    }
    __syncthreads();
}

__device__ __forceinline__ float gelu_f(float x){
    return 0.5f*x*(1.0f+erff(x*0.7071067811865476f));
}
__device__ __forceinline__ float phasor(int b, int tok, int c){
    int t = b*LL + tok;
    return (c < 32) ? d_cq[t*PP + c] : d_sq[t*PP + c - 32];
}
__device__ __forceinline__ uint32_t f2tf(float f){
    uint32_t r; asm("cvt.rna.tf32.f32 %0, %1;" : "=r"(r) : "f"(f)); return r;
}
__device__ __forceinline__ uint32_t fb(float f){ return __float_as_uint(f); }
__device__ __forceinline__ float f2tf_as_f(float f){
    uint32_t r = f2tf(f); return __uint_as_float(r);
}
__device__ __forceinline__ void mma_tf32(float* c, const uint32_t* a, const uint32_t* b){
    asm volatile(
      "mma.sync.aligned.m16n8k8.row.col.f32.tf32.tf32.f32 "
      "{%0,%1,%2,%3}, {%4,%5,%6,%7}, {%8,%9}, {%0,%1,%2,%3};\n"
      : "+f"(c[0]), "+f"(c[1]), "+f"(c[2]), "+f"(c[3])
      : "r"(a[0]), "r"(a[1]), "r"(a[2]), "r"(a[3]), "r"(b[0]), "r"(b[1]));
}
__device__ __forceinline__ void cp16(uint32_t dst, const void* src, int sz){
    asm volatile("cp.async.cg.shared.global [%0], [%1], 16, %2;\n"
                 :: "r"(dst), "l"(src), "r"(sz));
}
__device__ __forceinline__ void cp_commit(){ asm volatile("cp.async.commit_group;\n"); }
__device__ __forceinline__ void cp_wait1(){ asm volatile("cp.async.wait_group 1;\n"); }

// ---------------- GEMM tile (device) ----------------
#define A_PLAIN  0
#define A_CONCAT 1
#define A_LN     2
#define E_NONE 0
#define E_GELU 1
#define E_OUT  3
#define E_GATE 4
#define E_STAT 5

#define APITCH 36
#define WPITCH 72

template<int AMODE, int EPI>
__device__ void gemm_tile(float* smem,
                 const float* __restrict__ A,
                 const float* __restrict__ W,
                 const float* __restrict__ bias,
                 float* __restrict__ C,
                 const float* __restrict__ extra,
                 const float* __restrict__ lnS1, const float* __restrict__ lnS2,
                 const float* __restrict__ lnG,  const float* __restrict__ lnB,
                 float* __restrict__ oS1, float* __restrict__ oS2,
                 const float* __restrict__ gw, float* __restrict__ gpart,
                 int m0, int n0, int M, int N, int K)
{
    float* Asm = smem;
    float* Wsm = smem + 2*128*APITCH;

    const int tid = threadIdx.x;
    const int wid = tid >> 5;
    const int lane = tid & 31;
    const int grp = lane >> 2;
    const int tig = lane & 3;
    const int wm = wid >> 1;
    const int wn = wid & 1;

    float acc[2][4][4];
    #pragma unroll
    for (int mt=0;mt<2;mt++)
        #pragma unroll
        for (int nt=0;nt<4;nt++)
            #pragma unroll
            for (int i=0;i<4;i++) acc[mt][nt][i]=0.f;

    float4 areg[4]; float4 gv4, bv4;
    float mrow[4], rsrow[4];
    if (AMODE == A_LN){
        #pragma unroll
        for (int it=0; it<4; it++){
            int r = m0 + (tid>>3) + it*32;
            float sa = 0.f, sb = 0.f;
            #pragma unroll
            for (int s=0; s<8; s++){ sa += lnS1[s*NTOK + r]; sb += lnS2[s*NTOK + r]; }
            float mean = sa*(1.f/256.f);
            float var = fmaxf(sb*(1.f/256.f) - mean*mean, 0.f);
            mrow[it] = mean;
            rsrow[it] = rsqrtf(var + 1e-5f);
        }
    }

    auto ldA_regs = [&](int k0){
        int kq = (tid & 7)*4;
        gv4 = *(const float4*)&lnG[k0+kq];
        bv4 = *(const float4*)&lnB[k0+kq];
        #pragma unroll
        for (int it=0; it<4; it++){
            int r = m0 + (tid>>3) + it*32;
            areg[it] = *(const float4*)&A[(size_t)r*K + k0 + kq];
        }
    };
    auto stA = [&](int buf){
        float* As = Asm + buf*128*APITCH;
        int kq = (tid & 7)*4;
        #pragma unroll
        for (int it=0; it<4; it++){
            int row = (tid>>3) + it*32;
            float4 v = areg[it];
            v.x = (v.x - mrow[it])*rsrow[it]*gv4.x + bv4.x;
            v.y = (v.y - mrow[it])*rsrow[it]*gv4.y + bv4.y;
            v.z = (v.z - mrow[it])*rsrow[it]*gv4.z + bv4.z;
            v.w = (v.w - mrow[it])*rsrow[it]*gv4.w + bv4.w;
            *(float4*)&As[row*APITCH + kq] = v;
        }
    };

    auto load_tiles = [&](int buf, int k0){
        float* As = Asm + buf*128*APITCH;
        float* Ws = Wsm + buf*32*WPITCH;
        if (AMODE != A_LN){
            #pragma unroll
            for (int it = 0; it < 4; it++){
                int linear = tid + it*256;
                int row = linear >> 3;
                int kq  = (linear & 7)*4;
                int m = m0 + row;
                int kg = k0 + kq;
                const float* src; int sz = 16;
                if (AMODE == A_PLAIN){
                    src = A + (size_t)m*K + kg;
                } else {
                    if (kg < DD) src = A + (size_t)m*DD + kg;
                    else {
                        int l = m & (LL-1);
                        if (l == 0){ sz = 0; src = A; }
                        else src = A + (size_t)(m-1)*DD + (kg-DD);
                    }
                }
                cp16((uint32_t)__cvta_generic_to_shared(&As[row*APITCH + kq]), src, sz);
            }
        }
        #pragma unroll
        for (int it = 0; it < 2; it++){
            int linear = tid + it*256;
            int row = linear >> 4;
            int wnq = (linear & 15)*4;
            const float* src = W + (size_t)(k0+row)*N + n0 + wnq;
            cp16((uint32_t)__cvta_generic_to_shared(&Ws[row*WPITCH + wnq]), src, 16);
        }
    };

    const int ntiles = K >> 5;
    if (AMODE == A_LN) ldA_regs(0);
    load_tiles(0, 0);
    cp_commit();
    if (AMODE == A_LN) stA(0);

    for (int kt = 0; kt < ntiles; kt++){
        int buf = kt & 1;
        if (kt+1 < ntiles){
            if (AMODE == A_LN) ldA_regs((kt+1)*32);
            load_tiles(buf^1, (kt+1)*32);
        }
        cp_commit();
        cp_wait1();
        __syncthreads();

        const float* As = Asm + buf*128*APITCH;
        const float* Ws = Wsm + buf*32*WPITCH;
        #pragma unroll
        for (int ks = 0; ks < 32; ks += 8){
            uint32_t afr[2][4], bfr[4][2];
            #pragma unroll
            for (int mt=0; mt<2; mt++){
                int rb = wm*32 + mt*16 + grp;
                afr[mt][0] = fb(As[(rb  )*APITCH + ks + tig    ]);
                afr[mt][1] = fb(As[(rb+8)*APITCH + ks + tig    ]);
                afr[mt][2] = fb(As[(rb  )*APITCH + ks + tig + 4]);
                afr[mt][3] = fb(As[(rb+8)*APITCH + ks + tig + 4]);
            }
            #pragma unroll
            for (int nt=0; nt<4; nt++){
                int cb = wn*32 + nt*8 + grp;
                bfr[nt][0] = fb(Ws[(ks + tig    )*WPITCH + cb]);
                bfr[nt][1] = fb(Ws[(ks + tig + 4)*WPITCH + cb]);
            }
            #pragma unroll
            for (int mt=0; mt<2; mt++)
                #pragma unroll
                for (int nt=0; nt<4; nt++)
                    mma_tf32(acc[mt][nt], afr[mt], bfr[nt]);
        }
        if (AMODE == A_LN && kt+1 < ntiles) stA(buf^1);
        __syncthreads();
    }

    if (EPI == E_GATE){
        int slot = (n0 >> 6)*2 + wn;
        #pragma unroll
        for (int mt=0; mt<2; mt++){
            #pragma unroll
            for (int half=0; half<2; half++){
                int r = m0 + wm*32 + mt*16 + grp + half*8;
                float part = 0.f;
                #pragma unroll
                for (int nt=0; nt<4; nt++){
                    int cb = n0 + wn*32 + nt*8 + 2*tig;
                    float v0 = gelu_f(acc[mt][nt][half*2+0] + bias[cb]);
                    float v1 = gelu_f(acc[mt][nt][half*2+1] + bias[cb+1]);
                    part += v0*gw[cb] + v1*gw[cb+1];
                }
                part += __shfl_xor_sync(0xffffffffu, part, 1);
                part += __shfl_xor_sync(0xffffffffu, part, 2);
                if (tig == 0)
                    gpart[(size_t)r*8 + slot] = part;
            }
        }
        return;
    }

    #pragma unroll
    for (int mt=0; mt<2; mt++){
        #pragma unroll
        for (int half=0; half<2; half++){
            int r = m0 + wm*32 + mt*16 + grp + half*8;
            float s = 0.f, ss = 0.f;
            #pragma unroll
            for (int nt=0; nt<4; nt++){
                int cb = n0 + wn*32 + nt*8 + 2*tig;
                float v0 = acc[mt][nt][half*2+0] + bias[cb];
                float v1 = acc[mt][nt][half*2+1] + bias[cb+1];
                if (EPI == E_GELU){ v0 = gelu_f(v0); v1 = gelu_f(v1); }
                if (EPI == E_OUT) { v0 += extra[(size_t)r*DD + cb];
                                    v1 += extra[(size_t)r*DD + cb + 1]; }
                if (EPI == E_STAT){ s += v0 + v1; ss += v0*v0 + v1*v1; }
                *(float2*)&C[(size_t)r*N + cb] = make_float2(v0, v1);
            }
            if (EPI == E_STAT){
                s  += __shfl_xor_sync(0xffffffffu, s, 1);
                s  += __shfl_xor_sync(0xffffffffu, s, 2);
                ss += __shfl_xor_sync(0xffffffffu, ss, 1);
                ss += __shfl_xor_sync(0xffffffffu, ss, 2);
                if (tig == 0){
                    int slot = (n0 >> 6)*2 + wn;
                    oS1[slot*NTOK + r] = s;
                    oS2[slot*NTOK + r] = ss;
                }
            }
        }
    }
}

// ---------------- phases job: 32 tokens per block ----------------
__device__ void phases_job(int blk, const float* __restrict__ x,
                           const float* __restrict__ Wk,
                           const float* __restrict__ bk){
    int base = blk*32 + ((threadIdx.x >> 5) << 2);   // 4 tokens per warp
    int p = threadIdx.x & 31;
    const float* x0 = x + (size_t)(base+0)*DD;
    const float* x1 = x + (size_t)(base+1)*DD;
    const float* x2 = x + (size_t)(base+2)*DD;
    const float* x3 = x + (size_t)(base+3)*DD;
    float bkp = bk[p];
    float s0=bkp, s1=bkp, s2=bkp, s3=bkp;
    #pragma unroll 8
    for (int k = 0; k < DD; k++){
        float w = Wk[k*PP + p];
        s0 += x0[k]*w; s1 += x1[k]*w; s2 += x2[k]*w; s3 += x3[k]*w;
    }
    const float PI = 3.14159265358979323846f;
    float sn, cs;
    sincosf(tanhf(s0)*PI, &sn, &cs); d_cq[(base+0)*PP+p]=cs; d_sq[(base+0)*PP+p]=sn;
    sincosf(tanhf(s1)*PI, &sn, &cs); d_cq[(base+1)*PP+p]=cs; d_sq[(base+1)*PP+p]=sn;
    sincosf(tanhf(s2)*PI, &sn, &cs); d_cq[(base+2)*PP+p]=cs; d_sq[(base+2)*PP+p]=sn;
    sincosf(tanhf(s3)*PI, &sn, &cs); d_cq[(base+3)*PP+p]=cs; d_sq[(base+3)*PP+p]=sn;
}

// ---------------- gate finalize + scan (per batch) ----------------
__device__ void cumsum_job(int b, const float* __restrict__ bg2, float* smem){
    int tid = threadIdx.x;
    int lane = tid & 31, warp = tid >> 5;
    float* wtot = smem;   // 8 floats
    float bv = bg2[0];
    float v[8]; float run = 0.f;
    #pragma unroll
    for (int i=0;i<8;i++){
        int tok = b*LL + tid*8 + i;
        float4 a = *(const float4*)&d_gpart[(size_t)tok*8];
        float4 c = *(const float4*)&d_gpart[(size_t)tok*8 + 4];
        float s = bv + a.x+a.y+a.z+a.w + c.x+c.y+c.z+c.w;
        float g = 1.f/(1.f + expf(-s));
        d_g[tok] = g;
        run += g; v[i] = run;
    }
    float x = run;
    #pragma unroll
    for (int o=1;o<32;o<<=1){
        float y = __shfl_up_sync(0xffffffffu, x, o);
        if (lane >= o) x += y;
    }
    if (lane == 31) wtot[warp] = x;
    __syncthreads();
    if (warp == 0 && lane < 8){
        float t = wtot[lane];
        #pragma unroll
        for (int o=1;o<8;o<<=1){
            float z = __shfl_up_sync(0xffu, t, o);
            if (lane >= o) t += z;
        }
        wtot[lane] = t;
    }
    __syncthreads();
    float off = (x - run) + (warp ? wtot[warp-1] : 0.f);
    float* gc = d_gc + b*LL + tid*8;
    #pragma unroll
    for (int i=0;i<8;i++) gc[i] = v[i] + off;
}

// ---------------- chunk state ----------------
__device__ void chunk_state_job(int cc, int b, float* smem){
    float* sA = smem;            // 64*36
    float* sB = sA + 64*36;      // 32*264
    const int tid = threadIdx.x;
    const int wid = tid >> 5, lane = tid & 31;
    const int grp = lane >> 2, tig = lane & 3;
    const int wm = wid >> 2;
    const int wn = wid & 3;

    float acc[2][8][4];
    #pragma unroll
    for (int mt=0;mt<2;mt++)
        #pragma unroll
        for (int nt=0;nt<8;nt++)
            #pragma unroll
            for (int i=0;i<4;i++) acc[mt][nt][i]=0.f;

    for (int tile = 0; tile < 4; tile++){
        int t0 = cc*CH + tile*32;
        for (int i = tid; i < 64*32; i += 256){
            int p = i>>5, t = i&31;
            int gt = t0 + t;
            sA[p*36 + t] = (gt >= 1) ? f2tf_as_f(phasor(b, gt-1, p)) : 0.f;
        }
        for (int i = tid; i < 32*64; i += 256){
            int t = i>>6, c4 = (i&63)*4;
            float gv = d_g[b*LL + t0 + t];
            float4 v = *(const float4*)&d_v[((size_t)(b*LL + t0 + t))*DD + c4];
            v.x = f2tf_as_f(v.x*gv); v.y = f2tf_as_f(v.y*gv);
            v.z = f2tf_as_f(v.z*gv); v.w = f2tf_as_f(v.w*gv);
            *(float4*)&sB[t*264 + c4] = v;
        }
        __syncthreads();
        #pragma unroll
        for (int ks = 0; ks < 32; ks += 8){
            uint32_t afr[2][4], bfr[8][2];
            #pragma unroll
            for (int mt=0; mt<2; mt++){
                int rb = wm*32 + mt*16 + grp;
                afr[mt][0] = fb(sA[(rb  )*36 + ks + tig    ]);
                afr[mt][1] = fb(sA[(rb+8)*36 + ks + tig    ]);
                afr[mt][2] = fb(sA[(rb  )*36 + ks + tig + 4]);
                afr[mt][3] = fb(sA[(rb+8)*36 + ks + tig + 4]);
            }
            #pragma unroll
            for (int nt=0; nt<8; nt++){
                int cb = wn*64 + nt*8 + grp;
                bfr[nt][0] = fb(sB[(ks + tig    )*264 + cb]);
                bfr[nt][1] = fb(sB[(ks + tig + 4)*264 + cb]);
            }
            #pragma unroll
            for (int mt=0; mt<2; mt++)
                #pragma unroll
                for (int nt=0; nt<8; nt++)
                    mma_tf32(acc[mt][nt], afr[mt], bfr[nt]);
        }
        __syncthreads();
    }
    size_t base = ((size_t)(b*NCH + cc))*64*DD;
    #pragma unroll
    for (int mt=0; mt<2; mt++)
        #pragma unroll
        for (int nt=0; nt<8; nt++)
            #pragma unroll
            for (int half=0; half<2; half++){
                int row = wm*32 + mt*16 + grp + half*8;
                int col = wn*64 + nt*8 + 2*tig;
                *(float2*)&d_state[base + (size_t)row*DD + col] =
                    make_float2(acc[mt][nt][half*2], acc[mt][nt][half*2+1]);
            }
}

// ---------------- chunk prefix ----------------
__device__ void chunk_prefix_job(int b, int gs){
    int off = gs*1024 + threadIdx.x*4;
    float4 run = make_float4(0.f,0.f,0.f,0.f);
    #pragma unroll
    for (int c = 0; c < NCH; c++){
        size_t base = ((size_t)(b*NCH + c))*16384 + off;
        float4 v = *(const float4*)&d_state[base];
        *(float4*)&d_pref[base] = run;
        run.x += v.x; run.y += v.y; run.z += v.z; run.w += v.w;
    }
}

// ---------------- chunk out (fused scores + scale + LN1 slot stats) ----------------
__device__ void chunk_out_job(int cc, int ds, int b, float* sm){
    float* sQ  = sm;
    float* sKT = sQ + 128*68;
    float* sS  = sKT + 64*136;
    float* sV  = sS + 128*132;
    float* sP  = sV + 128*72;
    const int tid = threadIdx.x;
    const int wid = tid >> 5, lane = tid & 31;
    const int grp = lane >> 2, tig = lane & 3;
    const int wm = wid >> 1;
    const int wn = wid & 1;

    for (int i = tid; i < CH*64; i += 256){
        int r = i>>6, c = i&63;
        sQ[r*68 + c] = f2tf_as_f(phasor(b, cc*CH + r, c));
    }
    for (int i = tid; i < CH*64; i += 256){
        int t = i>>6, c = i&63;
        int gt = cc*CH + t;
        sKT[c*136 + t] = (gt >= 1) ? f2tf_as_f(phasor(b, gt-1, c)) : 0.f;
    }
    for (int i = tid; i < 128*16; i += 256){
        int t = i>>4, c4 = (i&15)*4;
        float gv = d_g[b*LL + cc*CH + t];
        float4 v = *(const float4*)&d_v[((size_t)(b*LL + cc*CH + t))*DD + ds*64 + c4];
        v.x = f2tf_as_f(v.x*gv); v.y = f2tf_as_f(v.y*gv);
        v.z = f2tf_as_f(v.z*gv); v.w = f2tf_as_f(v.w*gv);
        *(float4*)&sV[t*72 + c4] = v;
    }
    size_t pbase = ((size_t)(b*NCH + cc))*64*DD;
    for (int i = tid; i < 64*16; i += 256){
        int p = i>>4, c4 = (i&15)*4;
        float4 v = *(const float4*)&d_pref[pbase + (size_t)p*DD + ds*64 + c4];
        v.x = f2tf_as_f(v.x); v.y = f2tf_as_f(v.y);
        v.z = f2tf_as_f(v.z); v.w = f2tf_as_f(v.w);
        *(float4*)&sP[p*72 + c4] = v;
    }
    __syncthreads();

    // scores
    {
        float acc2[2][8][4];
        #pragma unroll
        for (int mt=0;mt<2;mt++)
            #pragma unroll
            for (int nt=0;nt<8;nt++)
                #pragma unroll
                for (int i=0;i<4;i++) acc2[mt][nt][i]=0.f;
        #pragma unroll
        for (int ks = 0; ks < 64; ks += 8){
            uint32_t afr[2][4], bfr[8][2];
            #pragma unroll
            for (int mt=0; mt<2; mt++){
                int rb = wm*32 + mt*16 + grp;
                afr[mt][0] = fb(sQ[(rb  )*68 + ks + tig    ]);
                afr[mt][1] = fb(sQ[(rb+8)*68 + ks + tig    ]);
                afr[mt][2] = fb(sQ[(rb  )*68 + ks + tig + 4]);
                afr[mt][3] = fb(sQ[(rb+8)*68 + ks + tig + 4]);
            }
            #pragma unroll
            for (int nt=0; nt<8; nt++){
                int cb = wn*64 + nt*8 + grp;
                bfr[nt][0] = fb(sKT[(ks + tig    )*136 + cb]);
                bfr[nt][1] = fb(sKT[(ks + tig + 4)*136 + cb]);
            }
            #pragma unroll
            for (int mt=0; mt<2; mt++)
                #pragma unroll
                for (int nt=0; nt<8; nt++)
                    mma_tf32(acc2[mt][nt], afr[mt], bfr[nt]);
        }
        #pragma unroll
        for (int mt=0; mt<2; mt++)
            #pragma unroll
            for (int nt=0; nt<8; nt++)
                #pragma unroll
                for (int half=0; half<2; half++){
                    int row = wm*32 + mt*16 + grp + half*8;
                    int col = wn*64 + nt*8 + 2*tig;
                    sS[row*132 + col    ] = (col   <= row) ? acc2[mt][nt][half*2  ] : 0.f;
                    sS[row*132 + col + 1] = (col+1 <= row) ? acc2[mt][nt][half*2+1] : 0.f;
                }
    }
    __syncthreads();

    float acc[2][4][4];
    #pragma unroll
    for (int mt=0;mt<2;mt++)
        #pragma unroll
        for (int nt=0;nt<4;nt++)
            #pragma unroll
            for (int i=0;i<4;i++) acc[mt][nt][i]=0.f;

    #pragma unroll 4
    for (int ks = 0; ks < 128; ks += 8){
        uint32_t afr[2][4], bfr[4][2];
        #pragma unroll
        for (int mt=0; mt<2; mt++){
            int rb = wm*32 + mt*16 + grp;
            afr[mt][0] = fb(sS[(rb  )*132 + ks + tig    ]);
            afr[mt][1] = fb(sS[(rb+8)*132 + ks + tig    ]);
            afr[mt][2] = fb(sS[(rb  )*132 + ks + tig + 4]);
            afr[mt][3] = fb(sS[(rb+8)*132 + ks + tig + 4]);
        }
        #pragma unroll
        for (int nt=0; nt<4; nt++){
            int cb = wn*32 + nt*8 + grp;
            bfr[nt][0] = fb(sV[(ks + tig    )*72 + cb]);
            bfr[nt][1] = fb(sV[(ks + tig + 4)*72 + cb]);
        }
        #pragma unroll
        for (int mt=0; mt<2; mt++)
            #pragma unroll
            for (int nt=0; nt<4; nt++)
                mma_tf32(acc[mt][nt], afr[mt], bfr[nt]);
    }
    #pragma unroll
    for (int ks = 0; ks < 64; ks += 8){
        uint32_t afr[2][4], bfr[4][2];
        #pragma unroll
        for (int mt=0; mt<2; mt++){
            int rb = wm*32 + mt*16 + grp;
            afr[mt][0] = fb(sQ[(rb  )*68 + ks + tig    ]);
            afr[mt][1] = fb(sQ[(rb+8)*68 + ks + tig    ]);
            afr[mt][2] = fb(sQ[(rb  )*68 + ks + tig + 4]);
            afr[mt][3] = fb(sQ[(rb+8)*68 + ks + tig + 4]);
        }
        #pragma unroll
        for (int nt=0; nt<4; nt++){
            int cb = wn*32 + nt*8 + grp;
            bfr[nt][0] = fb(sP[(ks + tig    )*72 + cb]);
            bfr[nt][1] = fb(sP[(ks + tig + 4)*72 + cb]);
        }
        #pragma unroll
        for (int mt=0; mt<2; mt++)
            #pragma unroll
            for (int nt=0; nt<4; nt++)
                mma_tf32(acc[mt][nt], afr[mt], bfr[nt]);
    }

    int slot = ds*2 + wn;
    #pragma unroll
    for (int mt=0; mt<2; mt++){
        #pragma unroll
        for (int half=0; half<2; half++){
            int rloc = wm*32 + mt*16 + grp + half*8;
            int gtok = b*LL + cc*CH + rloc;
            float sc = rsqrtf(fmaxf(d_gc[gtok], 1.f)) * 0.17677669529663687f;
            float s = 0.f, ss = 0.f;
            #pragma unroll
            for (int nt=0; nt<4; nt++){
                int col = wn*32 + nt*8 + 2*tig;
                float v0 = acc[mt][nt][half*2+0]*sc;
                float v1 = acc[mt][nt][half*2+1]*sc;
                *(float2*)&d_ret[(size_t)gtok*DD + ds*64 + col] = make_float2(v0, v1);
                s += v0 + v1; ss += v0*v0 + v1*v1;
            }
            s  += __shfl_xor_sync(0xffffffffu, s, 1);
            s  += __shfl_xor_sync(0xffffffffu, s, 2);
            ss += __shfl_xor_sync(0xffffffffu, ss, 1);
            ss += __shfl_xor_sync(0xffffffffu, ss, 2);
            if (tig == 0){
                d_s1[slot*NTOK + gtok] = s;
                d_s2[slot*NTOK + gtok] = ss;
            }
        }
    }
}

// ---------------- mega kernel ----------------
#define MEGA_SMEM ((128*68 + 64*136 + 128*132 + 128*72 + 64*72)*(int)sizeof(float))

__global__ void __launch_bounds__(256, 1)
mega_kernel(const float* __restrict__ x,
            const float* __restrict__ Wk,  const float* __restrict__ bk,
            const float* __restrict__ Wv,  const float* __restrict__ bv,
            const float* __restrict__ Wg1, const float* __restrict__ bg1,
            const float* __restrict__ Wg2, const float* __restrict__ bg2,
            const float* __restrict__ ln1g,const float* __restrict__ ln1b,
            const float* __restrict__ Wr1, const float* __restrict__ br1,
            const float* __restrict__ Wr2, const float* __restrict__ br2,
            const float* __restrict__ ln2g,const float* __restrict__ ln2b,
            const float* __restrict__ Wo,  const float* __restrict__ bo,
            float* __restrict__ out)
{
    extern __shared__ __align__(16) float smem[];
    const int blk = blockIdx.x;
    const int m0 = (blk & 31)*128;
    const int n0 = (blk >> 5)*64;

    // Phase A: gate GEMM, values GEMM, phases (independent given x)
    gemm_tile<A_CONCAT, E_GATE>(smem, x, Wg1, bg1, nullptr, nullptr,
        nullptr, nullptr, nullptr, nullptr, nullptr, nullptr,
        Wg2, d_gpart, m0, n0, NTOK, DD, 2*DD);
    gemm_tile<A_PLAIN, E_NONE>(smem, x, Wv, bv, d_v, nullptr,
        nullptr, nullptr, nullptr, nullptr, nullptr, nullptr,
        nullptr, nullptr, m0, n0, NTOK, DD, DD);
    phases_job(blk, x, Wk, bk);
    gbar();

    // Phase B: gate finalize + scan
    if (blk < BB) cumsum_job(blk, bg2, smem);
    gbar();

    // Phase C: chunk states
    if (blk < 32) chunk_state_job(blk >> 1, blk & 1, smem);
    gbar();

    // Phase D: chunk prefix
    if (blk < 32) chunk_prefix_job(blk >> 4, blk & 15);
    gbar();

    // Phase E: chunk out
    {
        int b  = blk >> 6;
        int cc = (blk >> 2) & 15;
        int ds = blk & 3;
        chunk_out_job(cc, ds, b, smem);
    }
    gbar();

    // Phase F: Wr1 (LN1-fused), 256 tiles -> 2 per block
    for (int t = blk; t < 256; t += NBLK){
        int fm0 = (t & 31)*128;
        int fn0 = (t >> 5)*64;
        gemm_tile<A_LN, E_GELU>(smem, d_ret, Wr1, br1, d_t1, nullptr,
            d_s1, d_s2, ln1g, ln1b, nullptr, nullptr,
            nullptr, nullptr, fm0, fn0, NTOK, 2*DD, DD);
    }
    gbar();

    // Phase G: Wr2 with LN2 slot stats
    gemm_tile<A_PLAIN, E_STAT>(smem, d_t1, Wr2, br2, d_t2, nullptr,
        nullptr, nullptr, nullptr, nullptr, d_s1b, d_s2b,
        nullptr, nullptr, m0, n0, NTOK, DD, 2*DD);
    gbar();

    // Phase H: Wo (LN2-fused) + residual
    gemm_tile<A_LN, E_OUT>(smem, d_t2, Wo, bo, out, x,
        d_s1b, d_s2b, ln2g, ln2b, nullptr, nullptr,
        nullptr, nullptr, m0, n0, NTOK, DD, DD);
}

// ---------------- launch ----------------
extern "C" void kernel_launch(void* const* d_in, const int* in_sizes, int n_in,
                              void* d_out, int out_size)
{
    const float* x    = (const float*)d_in[0];
    const float* Wk   = (const float*)d_in[1];
    const float* bk   = (const float*)d_in[2];
    const float* Wv   = (const float*)d_in[3];
    const float* bv   = (const float*)d_in[4];
    const float* Wg1  = (const float*)d_in[5];
    const float* bg1  = (const float*)d_in[6];
    const float* Wg2  = (const float*)d_in[7];
    const float* bg2  = (const float*)d_in[8];
    const float* ln1g = (const float*)d_in[9];
    const float* ln1b = (const float*)d_in[10];
    const float* Wr1  = (const float*)d_in[11];
    const float* br1  = (const float*)d_in[12];
    const float* Wr2  = (const float*)d_in[13];
    const float* br2  = (const float*)d_in[14];
    const float* ln2g = (const float*)d_in[15];
    const float* ln2b = (const float*)d_in[16];
    const float* Wo   = (const float*)d_in[17];
    const float* bo   = (const float*)d_in[18];
    float* out = (float*)d_out;

    static bool init = false;
    if (!init){
        cudaFuncSetAttribute(mega_kernel, cudaFuncAttributeMaxDynamicSharedMemorySize, MEGA_SMEM);
        init = true;
    }

    mega_kernel<<<NBLK, 256, MEGA_SMEM>>>(
        x, Wk, bk, Wv, bv, Wg1, bg1, Wg2, bg2,
        ln1g, ln1b, Wr1, br1, Wr2, br2, ln2g, ln2b, Wo, bo, out);
    (void)in_sizes; (void)n_in; (void)out_size;
}

// round 9
// speedup vs baseline: 2.8135x; 1.0323x over previous
#include <cuda_runtime.h>
#include <math.h>
#include <stdint.h>

#define BB 2
#define LL 2048
#define DD 256
#define PP 32
#define NTOK (BB*LL)
#define NCH 16
#define CH 128
#define NBLK 128
#define NTHR 512

// ---------------- scratch ----------------
__device__ float d_cq[NTOK*PP];
__device__ float d_sq[NTOK*PP];
__device__ float d_g [NTOK];
__device__ float d_gc[NTOK];
__device__ float d_v [NTOK*DD];
__device__ float d_ret[NTOK*DD];
__device__ float d_t1[NTOK*2*DD];
__device__ float d_t2[NTOK*DD];
__device__ float d_state[BB*64*64*DD];   // 64 partial slices per batch (4 per chunk)
__device__ float d_pref [BB*NCH*64*DD];
__device__ float d_gpart[NTOK*8];
__device__ float d_s1 [8*NTOK];
__device__ float d_s2 [8*NTOK];
__device__ float d_s1b[8*NTOK];
__device__ float d_s2b[8*NTOK];

__device__ unsigned bar_cnt = 0;
__device__ unsigned bar_gen = 0;

__device__ __forceinline__ void gbar(){
    __syncthreads();
    __threadfence();
    if (threadIdx.x == 0){
        volatile unsigned* vg = &bar_gen;
        unsigned gen = *vg;
        unsigned t = atomicAdd(&bar_cnt, 1);
        if (t == gridDim.x - 1){
            atomicExch(&bar_cnt, 0);
            __threadfence();
            atomicAdd(&bar_gen, 1);
        } else {
            while (*vg == gen) { __nanosleep(32); }
        }
    }
    __syncthreads();
}

__device__ __forceinline__ float gelu_f(float x){
    return 0.5f*x*(1.0f+erff(x*0.7071067811865476f));
}
__device__ __forceinline__ float phasor(int b, int tok, int c){
    int t = b*LL + tok;
    return (c < 32) ? d_cq[t*PP + c] : d_sq[t*PP + c - 32];
}
__device__ __forceinline__ uint32_t f2tf(float f){
    uint32_t r; asm("cvt.rna.tf32.f32 %0, %1;" : "=r"(r) : "f"(f)); return r;
}
__device__ __forceinline__ uint32_t fb(float f){ return __float_as_uint(f); }
__device__ __forceinline__ float f2tf_as_f(float f){
    uint32_t r = f2tf(f); return __uint_as_float(r);
}
__device__ __forceinline__ void mma_tf32(float* c, const uint32_t* a, const uint32_t* b){
    asm volatile(
      "mma.sync.aligned.m16n8k8.row.col.f32.tf32.tf32.f32 "
      "{%0,%1,%2,%3}, {%4,%5,%6,%7}, {%8,%9}, {%0,%1,%2,%3};\n"
      : "+f"(c[0]), "+f"(c[1]), "+f"(c[2]), "+f"(c[3])
      : "r"(a[0]), "r"(a[1]), "r"(a[2]), "r"(a[3]), "r"(b[0]), "r"(b[1]));
}
__device__ __forceinline__ void cp16(uint32_t dst, const void* src, int sz){
    asm volatile("cp.async.cg.shared.global [%0], [%1], 16, %2;\n"
                 :: "r"(dst), "l"(src), "r"(sz));
}
__device__ __forceinline__ void cp_commit(){ asm volatile("cp.async.commit_group;\n"); }
__device__ __forceinline__ void cp_wait1(){ asm volatile("cp.async.wait_group 1;\n"); }

// ---------------- GEMM tile (device, 512 threads, warps 8x2) ----------------
#define A_PLAIN  0
#define A_CONCAT 1
#define A_LN     2
#define E_NONE 0
#define E_GELU 1
#define E_OUT  3
#define E_GATE 4
#define E_STAT 5

#define APITCH 36
#define WPITCH 72

template<int AMODE, int EPI>
__device__ void gemm_tile(float* smem,
                 const float* __restrict__ A,
                 const float* __restrict__ W,
                 const float* __restrict__ bias,
                 float* __restrict__ C,
                 const float* __restrict__ extra,
                 const float* __restrict__ lnS1, const float* __restrict__ lnS2,
                 const float* __restrict__ lnG,  const float* __restrict__ lnB,
                 float* __restrict__ oS1, float* __restrict__ oS2,
                 const float* __restrict__ gw, float* __restrict__ gpart,
                 int m0, int n0, int M, int N, int K)
{
    float* Asm = smem;
    float* Wsm = smem + 2*128*APITCH;

    const int tid = threadIdx.x;
    const int wid = tid >> 5;
    const int lane = tid & 31;
    const int grp = lane >> 2;
    const int tig = lane & 3;
    const int wm = wid >> 1;      // 0..7: 16-row strips
    const int wn = wid & 1;       // 0..1: 32-col strips

    float acc[4][4];
    #pragma unroll
    for (int nt=0;nt<4;nt++)
        #pragma unroll
        for (int i=0;i<4;i++) acc[nt][i]=0.f;

    float4 areg[2]; float4 gv4, bv4;
    float mrow[2], rsrow[2];
    if (AMODE == A_LN){
        #pragma unroll
        for (int it=0; it<2; it++){
            int r = m0 + (tid>>3) + it*64;
            float sa = 0.f, sb = 0.f;
            #pragma unroll
            for (int s=0; s<8; s++){ sa += lnS1[s*NTOK + r]; sb += lnS2[s*NTOK + r]; }
            float mean = sa*(1.f/256.f);
            float var = fmaxf(sb*(1.f/256.f) - mean*mean, 0.f);
            mrow[it] = mean;
            rsrow[it] = rsqrtf(var + 1e-5f);
        }
    }

    auto ldA_regs = [&](int k0){
        int kq = (tid & 7)*4;
        gv4 = *(const float4*)&lnG[k0+kq];
        bv4 = *(const float4*)&lnB[k0+kq];
        #pragma unroll
        for (int it=0; it<2; it++){
            int r = m0 + (tid>>3) + it*64;
            areg[it] = *(const float4*)&A[(size_t)r*K + k0 + kq];
        }
    };
    auto stA = [&](int buf){
        float* As = Asm + buf*128*APITCH;
        int kq = (tid & 7)*4;
        #pragma unroll
        for (int it=0; it<2; it++){
            int row = (tid>>3) + it*64;
            float4 v = areg[it];
            v.x = (v.x - mrow[it])*rsrow[it]*gv4.x + bv4.x;
            v.y = (v.y - mrow[it])*rsrow[it]*gv4.y + bv4.y;
            v.z = (v.z - mrow[it])*rsrow[it]*gv4.z + bv4.z;
            v.w = (v.w - mrow[it])*rsrow[it]*gv4.w + bv4.w;
            *(float4*)&As[row*APITCH + kq] = v;
        }
    };

    auto load_tiles = [&](int buf, int k0){
        float* As = Asm + buf*128*APITCH;
        float* Ws = Wsm + buf*32*WPITCH;
        if (AMODE != A_LN){
            #pragma unroll
            for (int it = 0; it < 2; it++){
                int linear = tid + it*NTHR;
                int row = linear >> 3;
                int kq  = (linear & 7)*4;
                int m = m0 + row;
                int kg = k0 + kq;
                const float* src; int sz = 16;
                if (AMODE == A_PLAIN){
                    src = A + (size_t)m*K + kg;
                } else {
                    if (kg < DD) src = A + (size_t)m*DD + kg;
                    else {
                        int l = m & (LL-1);
                        if (l == 0){ sz = 0; src = A; }
                        else src = A + (size_t)(m-1)*DD + (kg-DD);
                    }
                }
                cp16((uint32_t)__cvta_generic_to_shared(&As[row*APITCH + kq]), src, sz);
            }
        }
        {
            int row = tid >> 4;
            int wnq = (tid & 15)*4;
            const float* src = W + (size_t)(k0+row)*N + n0 + wnq;
            cp16((uint32_t)__cvta_generic_to_shared(&Ws[row*WPITCH + wnq]), src, 16);
        }
    };

    const int ntiles = K >> 5;
    if (AMODE == A_LN) ldA_regs(0);
    load_tiles(0, 0);
    cp_commit();
    if (AMODE == A_LN) stA(0);

    for (int kt = 0; kt < ntiles; kt++){
        int buf = kt & 1;
        if (kt+1 < ntiles){
            if (AMODE == A_LN) ldA_regs((kt+1)*32);
            load_tiles(buf^1, (kt+1)*32);
        }
        cp_commit();
        cp_wait1();
        __syncthreads();

        const float* As = Asm + buf*128*APITCH;
        const float* Ws = Wsm + buf*32*WPITCH;
        #pragma unroll
        for (int ks = 0; ks < 32; ks += 8){
            uint32_t afr[4], bfr[4][2];
            int rb = wm*16 + grp;
            afr[0] = fb(As[(rb  )*APITCH + ks + tig    ]);
            afr[1] = fb(As[(rb+8)*APITCH + ks + tig    ]);
            afr[2] = fb(As[(rb  )*APITCH + ks + tig + 4]);
            afr[3] = fb(As[(rb+8)*APITCH + ks + tig + 4]);
            #pragma unroll
            for (int nt=0; nt<4; nt++){
                int cb = wn*32 + nt*8 + grp;
                bfr[nt][0] = fb(Ws[(ks + tig    )*WPITCH + cb]);
                bfr[nt][1] = fb(Ws[(ks + tig + 4)*WPITCH + cb]);
            }
            #pragma unroll
            for (int nt=0; nt<4; nt++)
                mma_tf32(acc[nt], afr, bfr[nt]);
        }
        if (AMODE == A_LN && kt+1 < ntiles) stA(buf^1);
        __syncthreads();
    }

    if (EPI == E_GATE){
        int slot = (n0 >> 6)*2 + wn;
        #pragma unroll
        for (int half=0; half<2; half++){
            int r = m0 + wm*16 + grp + half*8;
            float part = 0.f;
            #pragma unroll
            for (int nt=0; nt<4; nt++){
                int cb = n0 + wn*32 + nt*8 + 2*tig;
                float v0 = gelu_f(acc[nt][half*2+0] + bias[cb]);
                float v1 = gelu_f(acc[nt][half*2+1] + bias[cb+1]);
                part += v0*gw[cb] + v1*gw[cb+1];
            }
            part += __shfl_xor_sync(0xffffffffu, part, 1);
            part += __shfl_xor_sync(0xffffffffu, part, 2);
            if (tig == 0)
                gpart[(size_t)r*8 + slot] = part;
        }
        return;
    }

    #pragma unroll
    for (int half=0; half<2; half++){
        int r = m0 + wm*16 + grp + half*8;
        float s = 0.f, ss = 0.f;
        #pragma unroll
        for (int nt=0; nt<4; nt++){
            int cb = n0 + wn*32 + nt*8 + 2*tig;
            float v0 = acc[nt][half*2+0] + bias[cb];
            float v1 = acc[nt][half*2+1] + bias[cb+1];
            if (EPI == E_GELU){ v0 = gelu_f(v0); v1 = gelu_f(v1); }
            if (EPI == E_OUT) { v0 += extra[(size_t)r*DD + cb];
                                v1 += extra[(size_t)r*DD + cb + 1]; }
            if (EPI == E_STAT){ s += v0 + v1; ss += v0*v0 + v1*v1; }
            *(float2*)&C[(size_t)r*N + cb] = make_float2(v0, v1);
        }
        if (EPI == E_STAT){
            s  += __shfl_xor_sync(0xffffffffu, s, 1);
            s  += __shfl_xor_sync(0xffffffffu, s, 2);
            ss += __shfl_xor_sync(0xffffffffu, ss, 1);
            ss += __shfl_xor_sync(0xffffffffu, ss, 2);
            if (tig == 0){
                int slot = (n0 >> 6)*2 + wn;
                oS1[slot*NTOK + r] = s;
                oS2[slot*NTOK + r] = ss;
            }
        }
    }
}

// ---------------- phases job: 32 tokens per block (2 per warp) ----------------
__device__ void phases_job(int blk, const float* __restrict__ x,
                           const float* __restrict__ Wk,
                           const float* __restrict__ bk){
    int base = blk*32 + ((threadIdx.x >> 5) << 1);
    int p = threadIdx.x & 31;
    const float* x0 = x + (size_t)(base+0)*DD;
    const float* x1 = x + (size_t)(base+1)*DD;
    float bkp = bk[p];
    float s0=bkp, s1=bkp;
    #pragma unroll 8
    for (int k = 0; k < DD; k++){
        float w = Wk[k*PP + p];
        s0 += x0[k]*w; s1 += x1[k]*w;
    }
    const float PI = 3.14159265358979323846f;
    float sn, cs;
    sincosf(tanhf(s0)*PI, &sn, &cs); d_cq[(base+0)*PP+p]=cs; d_sq[(base+0)*PP+p]=sn;
    sincosf(tanhf(s1)*PI, &sn, &cs); d_cq[(base+1)*PP+p]=cs; d_sq[(base+1)*PP+p]=sn;
}

// ---------------- gate finalize + scan (per batch, 512 threads x 4 elems) ----------------
__device__ void cumsum_job(int b, const float* __restrict__ bg2, float* smem){
    int tid = threadIdx.x;
    int lane = tid & 31, warp = tid >> 5;   // 16 warps
    float* wtot = smem;
    float bv = bg2[0];
    float v[4]; float run = 0.f;
    #pragma unroll
    for (int i=0;i<4;i++){
        int tok = b*LL + tid*4 + i;
        float4 a = *(const float4*)&d_gpart[(size_t)tok*8];
        float4 c = *(const float4*)&d_gpart[(size_t)tok*8 + 4];
        float s = bv + a.x+a.y+a.z+a.w + c.x+c.y+c.z+c.w;
        float g = 1.f/(1.f + expf(-s));
        d_g[tok] = g;
        run += g; v[i] = run;
    }
    float x = run;
    #pragma unroll
    for (int o=1;o<32;o<<=1){
        float y = __shfl_up_sync(0xffffffffu, x, o);
        if (lane >= o) x += y;
    }
    if (lane == 31) wtot[warp] = x;
    __syncthreads();
    if (warp == 0 && lane < 16){
        float t = wtot[lane];
        #pragma unroll
        for (int o=1;o<16;o<<=1){
            float z = __shfl_up_sync(0xffffu, t, o);
            if (lane >= o) t += z;
        }
        wtot[lane] = t;
    }
    __syncthreads();
    float off = (x - run) + (warp ? wtot[warp-1] : 0.f);
    float* gc = d_gc + b*LL + tid*4;
    #pragma unroll
    for (int i=0;i<4;i++) gc[i] = v[i] + off;
}

// ---------------- chunk state slice: one 32-token tile -> partial state ----------------
__device__ void chunk_state_job(int cc, int b, int tile, float* smem){
    float* sA = smem;            // 64*36
    float* sB = sA + 64*36;      // 32*264
    const int tid = threadIdx.x;
    const int wid = tid >> 5, lane = tid & 31;
    const int grp = lane >> 2, tig = lane & 3;
    const int wm = wid >> 3;     // 0..1 : 32-row strips
    const int wn = wid & 7;      // 0..7 : 32-col strips

    float acc[2][4][4];
    #pragma unroll
    for (int mt=0;mt<2;mt++)
        #pragma unroll
        for (int nt=0;nt<4;nt++)
            #pragma unroll
            for (int i=0;i<4;i++) acc[mt][nt][i]=0.f;

    int t0 = cc*CH + tile*32;
    for (int i = tid; i < 64*32; i += NTHR){
        int p = i>>5, t = i&31;
        int gt = t0 + t;
        sA[p*36 + t] = (gt >= 1) ? f2tf_as_f(phasor(b, gt-1, p)) : 0.f;
    }
    for (int i = tid; i < 32*64; i += NTHR){
        int t = i>>6, c4 = (i&63)*4;
        float gv = d_g[b*LL + t0 + t];
        float4 v = *(const float4*)&d_v[((size_t)(b*LL + t0 + t))*DD + c4];
        v.x = f2tf_as_f(v.x*gv); v.y = f2tf_as_f(v.y*gv);
        v.z = f2tf_as_f(v.z*gv); v.w = f2tf_as_f(v.w*gv);
        *(float4*)&sB[t*264 + c4] = v;
    }
    __syncthreads();
    #pragma unroll
    for (int ks = 0; ks < 32; ks += 8){
        uint32_t afr[2][4], bfr[4][2];
        #pragma unroll
        for (int mt=0; mt<2; mt++){
            int rb = wm*32 + mt*16 + grp;
            afr[mt][0] = fb(sA[(rb  )*36 + ks + tig    ]);
            afr[mt][1] = fb(sA[(rb+8)*36 + ks + tig    ]);
            afr[mt][2] = fb(sA[(rb  )*36 + ks + tig + 4]);
            afr[mt][3] = fb(sA[(rb+8)*36 + ks + tig + 4]);
        }
        #pragma unroll
        for (int nt=0; nt<4; nt++){
            int cb = wn*32 + nt*8 + grp;
            bfr[nt][0] = fb(sB[(ks + tig    )*264 + cb]);
            bfr[nt][1] = fb(sB[(ks + tig + 4)*264 + cb]);
        }
        #pragma unroll
        for (int mt=0; mt<2; mt++)
            #pragma unroll
            for (int nt=0; nt<4; nt++)
                mma_tf32(acc[mt][nt], afr[mt], bfr[nt]);
    }
    __syncthreads();
    size_t base = ((size_t)(b*64 + cc*4 + tile))*64*DD;
    #pragma unroll
    for (int mt=0; mt<2; mt++)
        #pragma unroll
        for (int nt=0; nt<4; nt++)
            #pragma unroll
            for (int half=0; half<2; half++){
                int row = wm*32 + mt*16 + grp + half*8;
                int col = wn*32 + nt*8 + 2*tig;
                *(float2*)&d_state[base + (size_t)row*DD + col] =
                    make_float2(acc[mt][nt][half*2], acc[mt][nt][half*2+1]);
            }
}

// ---------------- chunk prefix over 64 slices ----------------
__device__ void chunk_prefix_job(int b, int gs){
    int off = gs*2048 + threadIdx.x*4;
    float4 run = make_float4(0.f,0.f,0.f,0.f);
    #pragma unroll 4
    for (int c = 0; c < 64; c++){
        size_t base = ((size_t)(b*64 + c))*16384 + off;
        float4 v = *(const float4*)&d_state[base];
        if ((c & 3) == 0){
            size_t pb = ((size_t)(b*NCH + (c>>2)))*16384 + off;
            *(float4*)&d_pref[pb] = run;
        }
        run.x += v.x; run.y += v.y; run.z += v.z; run.w += v.w;
    }
}

// ---------------- chunk out (512 threads) ----------------
__device__ void chunk_out_job(int cc, int ds, int b, float* sm){
    float* sQ  = sm;
    float* sKT = sQ + 128*68;
    float* sS  = sKT + 64*136;
    float* sV  = sS + 128*132;
    float* sP  = sV + 128*72;
    const int tid = threadIdx.x;
    const int wid = tid >> 5, lane = tid & 31;
    const int grp = lane >> 2, tig = lane & 3;

    for (int i = tid; i < CH*64; i += NTHR){
        int r = i>>6, c = i&63;
        sQ[r*68 + c] = f2tf_as_f(phasor(b, cc*CH + r, c));
    }
    for (int i = tid; i < CH*64; i += NTHR){
        int t = i>>6, c = i&63;
        int gt = cc*CH + t;
        sKT[c*136 + t] = (gt >= 1) ? f2tf_as_f(phasor(b, gt-1, c)) : 0.f;
    }
    for (int i = tid; i < 128*16; i += NTHR){
        int t = i>>4, c4 = (i&15)*4;
        float gv = d_g[b*LL + cc*CH + t];
        float4 v = *(const float4*)&d_v[((size_t)(b*LL + cc*CH + t))*DD + ds*64 + c4];
        v.x = f2tf_as_f(v.x*gv); v.y = f2tf_as_f(v.y*gv);
        v.z = f2tf_as_f(v.z*gv); v.w = f2tf_as_f(v.w*gv);
        *(float4*)&sV[t*72 + c4] = v;
    }
    size_t pbase = ((size_t)(b*NCH + cc))*64*DD;
    for (int i = tid; i < 64*16; i += NTHR){
        int p = i>>4, c4 = (i&15)*4;
        float4 v = *(const float4*)&d_pref[pbase + (size_t)p*DD + ds*64 + c4];
        v.x = f2tf_as_f(v.x); v.y = f2tf_as_f(v.y);
        v.z = f2tf_as_f(v.z); v.w = f2tf_as_f(v.w);
        *(float4*)&sP[p*72 + c4] = v;
    }
    __syncthreads();

    // scores: 16 warps, 4x4 layout (32x32 warp tiles)
    {
        const int wm = wid >> 2;   // 0..3
        const int wn = wid & 3;    // 0..3
        float acc2[2][4][4];
        #pragma unroll
        for (int mt=0;mt<2;mt++)
            #pragma unroll
            for (int nt=0;nt<4;nt++)
                #pragma unroll
                for (int i=0;i<4;i++) acc2[mt][nt][i]=0.f;
        #pragma unroll
        for (int ks = 0; ks < 64; ks += 8){
            uint32_t afr[2][4], bfr[4][2];
            #pragma unroll
            for (int mt=0; mt<2; mt++){
                int rb = wm*32 + mt*16 + grp;
                afr[mt][0] = fb(sQ[(rb  )*68 + ks + tig    ]);
                afr[mt][1] = fb(sQ[(rb+8)*68 + ks + tig    ]);
                afr[mt][2] = fb(sQ[(rb  )*68 + ks + tig + 4]);
                afr[mt][3] = fb(sQ[(rb+8)*68 + ks + tig + 4]);
            }
            #pragma unroll
            for (int nt=0; nt<4; nt++){
                int cb = wn*32 + nt*8 + grp;
                bfr[nt][0] = fb(sKT[(ks + tig    )*136 + cb]);
                bfr[nt][1] = fb(sKT[(ks + tig + 4)*136 + cb]);
            }
            #pragma unroll
            for (int mt=0; mt<2; mt++)
                #pragma unroll
                for (int nt=0; nt<4; nt++)
                    mma_tf32(acc2[mt][nt], afr[mt], bfr[nt]);
        }
        #pragma unroll
        for (int mt=0; mt<2; mt++)
            #pragma unroll
            for (int nt=0; nt<4; nt++)
                #pragma unroll
                for (int half=0; half<2; half++){
                    int row = wm*32 + mt*16 + grp + half*8;
                    int col = wn*32 + nt*8 + 2*tig;
                    sS[row*132 + col    ] = (col   <= row) ? acc2[mt][nt][half*2  ] : 0.f;
                    sS[row*132 + col + 1] = (col+1 <= row) ? acc2[mt][nt][half*2+1] : 0.f;
                }
    }
    __syncthreads();

    // out: 16 warps, 8x2 layout (16x32 warp tiles)
    const int wm = wid >> 1;   // 0..7
    const int wn = wid & 1;    // 0..1
    float acc[4][4];
    #pragma unroll
    for (int nt=0;nt<4;nt++)
        #pragma unroll
        for (int i=0;i<4;i++) acc[nt][i]=0.f;

    #pragma unroll 4
    for (int ks = 0; ks < 128; ks += 8){
        uint32_t afr[4], bfr[4][2];
        int rb = wm*16 + grp;
        afr[0] = fb(sS[(rb  )*132 + ks + tig    ]);
        afr[1] = fb(sS[(rb+8)*132 + ks + tig    ]);
        afr[2] = fb(sS[(rb  )*132 + ks + tig + 4]);
        afr[3] = fb(sS[(rb+8)*132 + ks + tig + 4]);
        #pragma unroll
        for (int nt=0; nt<4; nt++){
            int cb = wn*32 + nt*8 + grp;
            bfr[nt][0] = fb(sV[(ks + tig    )*72 + cb]);
            bfr[nt][1] = fb(sV[(ks + tig + 4)*72 + cb]);
        }
        #pragma unroll
        for (int nt=0; nt<4; nt++)
            mma_tf32(acc[nt], afr, bfr[nt]);
    }
    #pragma unroll
    for (int ks = 0; ks < 64; ks += 8){
        uint32_t afr[4], bfr[4][2];
        int rb = wm*16 + grp;
        afr[0] = fb(sQ[(rb  )*68 + ks + tig    ]);
        afr[1] = fb(sQ[(rb+8)*68 + ks + tig    ]);
        afr[2] = fb(sQ[(rb  )*68 + ks + tig + 4]);
        afr[3] = fb(sQ[(rb+8)*68 + ks + tig + 4]);
        #pragma unroll
        for (int nt=0; nt<4; nt++){
            int cb = wn*32 + nt*8 + grp;
            bfr[nt][0] = fb(sP[(ks + tig    )*72 + cb]);
            bfr[nt][1] = fb(sP[(ks + tig + 4)*72 + cb]);
        }
        #pragma unroll
        for (int nt=0; nt<4; nt++)
            mma_tf32(acc[nt], afr, bfr[nt]);
    }

    int slot = ds*2 + wn;
    #pragma unroll
    for (int half=0; half<2; half++){
        int rloc = wm*16 + grp + half*8;
        int gtok = b*LL + cc*CH + rloc;
        float sc = rsqrtf(fmaxf(d_gc[gtok], 1.f)) * 0.17677669529663687f;
        float s = 0.f, ss = 0.f;
        #pragma unroll
        for (int nt=0; nt<4; nt++){
            int col = wn*32 + nt*8 + 2*tig;
            float v0 = acc[nt][half*2+0]*sc;
            float v1 = acc[nt][half*2+1]*sc;
            *(float2*)&d_ret[(size_t)gtok*DD + ds*64 + col] = make_float2(v0, v1);
            s += v0 + v1; ss += v0*v0 + v1*v1;
        }
        s  += __shfl_xor_sync(0xffffffffu, s, 1);
        s  += __shfl_xor_sync(0xffffffffu, s, 2);
        ss += __shfl_xor_sync(0xffffffffu, ss, 1);
        ss += __shfl_xor_sync(0xffffffffu, ss, 2);
        if (tig == 0){
            d_s1[slot*NTOK + gtok] = s;
            d_s2[slot*NTOK + gtok] = ss;
        }
    }
}

// ---------------- mega kernel ----------------
#define MEGA_SMEM ((128*68 + 64*136 + 128*132 + 128*72 + 64*72)*(int)sizeof(float))

__global__ void __launch_bounds__(NTHR, 1)
mega_kernel(const float* __restrict__ x,
            const float* __restrict__ Wk,  const float* __restrict__ bk,
            const float* __restrict__ Wv,  const float* __restrict__ bv,
            const float* __restrict__ Wg1, const float* __restrict__ bg1,
            const float* __restrict__ Wg2, const float* __restrict__ bg2,
            const float* __restrict__ ln1g,const float* __restrict__ ln1b,
            const float* __restrict__ Wr1, const float* __restrict__ br1,
            const float* __restrict__ Wr2, const float* __restrict__ br2,
            const float* __restrict__ ln2g,const float* __restrict__ ln2b,
            const float* __restrict__ Wo,  const float* __restrict__ bo,
            float* __restrict__ out)
{
    extern __shared__ __align__(16) float smem[];
    const int blk = blockIdx.x;
    const int m0 = (blk & 31)*128;
    const int n0 = (blk >> 5)*64;

    // Phase A
    gemm_tile<A_CONCAT, E_GATE>(smem, x, Wg1, bg1, nullptr, nullptr,
        nullptr, nullptr, nullptr, nullptr, nullptr, nullptr,
        Wg2, d_gpart, m0, n0, NTOK, DD, 2*DD);
    gemm_tile<A_PLAIN, E_NONE>(smem, x, Wv, bv, d_v, nullptr,
        nullptr, nullptr, nullptr, nullptr, nullptr, nullptr,
        nullptr, nullptr, m0, n0, NTOK, DD, DD);
    phases_job(blk, x, Wk, bk);
    gbar();

    // Phase B
    if (blk < BB) cumsum_job(blk, bg2, smem);
    gbar();

    // Phase C: chunk state slices, all 128 blocks
    chunk_state_job((blk >> 2) & 15, blk >> 6, blk & 3, smem);
    gbar();

    // Phase D: prefix (16 blocks)
    if (blk < 16) chunk_prefix_job(blk >> 3, blk & 7);
    gbar();

    // Phase E: chunk out
    chunk_out_job((blk >> 2) & 15, blk & 3, blk >> 6, smem);
    gbar();

    // Phase F: Wr1 (LN1-fused), 256 tiles
    for (int t = blk; t < 256; t += NBLK){
        int fm0 = (t & 31)*128;
        int fn0 = (t >> 5)*64;
        gemm_tile<A_LN, E_GELU>(smem, d_ret, Wr1, br1, d_t1, nullptr,
            d_s1, d_s2, ln1g, ln1b, nullptr, nullptr,
            nullptr, nullptr, fm0, fn0, NTOK, 2*DD, DD);
    }
    gbar();

    // Phase G
    gemm_tile<A_PLAIN, E_STAT>(smem, d_t1, Wr2, br2, d_t2, nullptr,
        nullptr, nullptr, nullptr, nullptr, d_s1b, d_s2b,
        nullptr, nullptr, m0, n0, NTOK, DD, 2*DD);
    gbar();

    // Phase H
    gemm_tile<A_LN, E_OUT>(smem, d_t2, Wo, bo, out, x,
        d_s1b, d_s2b, ln2g, ln2b, nullptr, nullptr,
        nullptr, nullptr, m0, n0, NTOK, DD, DD);
}

// ---------------- launch ----------------
extern "C" void kernel_launch(void* const* d_in, const int* in_sizes, int n_in,
                              void* d_out, int out_size)
{
    const float* x    = (const float*)d_in[0];
    const float* Wk   = (const float*)d_in[1];
    const float* bk   = (const float*)d_in[2];
    const float* Wv   = (const float*)d_in[3];
    const float* bv   = (const float*)d_in[4];
    const float* Wg1  = (const float*)d_in[5];
    const float* bg1  = (const float*)d_in[6];
    const float* Wg2  = (const float*)d_in[7];
    const float* bg2  = (const float*)d_in[8];
    const float* ln1g = (const float*)d_in[9];
    const float* ln1b = (const float*)d_in[10];
    const float* Wr1  = (const float*)d_in[11];
    const float* br1  = (const float*)d_in[12];
    const float* Wr2  = (const float*)d_in[13];
    const float* br2  = (const float*)d_in[14];
    const float* ln2g = (const float*)d_in[15];
    const float* ln2b = (const float*)d_in[16];
    const float* Wo   = (const float*)d_in[17];
    const float* bo   = (const float*)d_in[18];
    float* out = (float*)d_out;

    static bool init = false;
    if (!init){
        cudaFuncSetAttribute(mega_kernel, cudaFuncAttributeMaxDynamicSharedMemorySize, MEGA_SMEM);
        init = true;
    }

    mega_kernel<<<NBLK, NTHR, MEGA_SMEM>>>(
        x, Wk, bk, Wv, bv, Wg1, bg1, Wg2, bg2,
        ln1g, ln1b, Wr1, br1, Wr2, br2, ln2g, ln2b, Wo, bo, out);
    (void)in_sizes; (void)n_in; (void)out_size;
}

// round 11
// speedup vs baseline: 2.9135x; 1.0356x over previous
#include <cuda_runtime.h>
#include <math.h>
#include <stdint.h>

#define BB 2
#define LL 2048
#define DD 256
#define PP 32
#define NTOK (BB*LL)
#define NCH 16
#define CH 128
#define NBLK 128
#define NTHR 512

// ---------------- scratch ----------------
__device__ float d_cq[NTOK*PP];
__device__ float d_sq[NTOK*PP];
__device__ float d_g [NTOK];
__device__ float d_gc[NTOK];
__device__ float d_v [NTOK*DD];
__device__ float d_ret[NTOK*DD];
__device__ float d_t1[NTOK*2*DD];
__device__ float d_t2[NTOK*DD];
__device__ float d_state[BB*64*64*DD];   // 64 partial slices per batch
__device__ float d_pref [BB*NCH*64*DD];
__device__ float d_gpart[NTOK*8];
__device__ float d_s1 [8*NTOK];
__device__ float d_s2 [8*NTOK];
__device__ float d_s1b[8*NTOK];
__device__ float d_s2b[8*NTOK];

__device__ unsigned bar_cnt = 0;
__device__ unsigned bar_gen = 0;

__device__ __forceinline__ void gbar(){
    __syncthreads();
    __threadfence();
    if (threadIdx.x == 0){
        volatile unsigned* vg = &bar_gen;
        unsigned gen = *vg;
        unsigned t = atomicAdd(&bar_cnt, 1);
        if (t == gridDim.x - 1){
            atomicExch(&bar_cnt, 0);
            __threadfence();
            atomicAdd(&bar_gen, 1);
        } else {
            while (*vg == gen) { __nanosleep(32); }
        }
    }
    __syncthreads();
}

__device__ __forceinline__ float gelu_f(float x){
    return 0.5f*x*(1.0f+erff(x*0.7071067811865476f));
}
__device__ __forceinline__ float phasor(int b, int tok, int c){
    int t = b*LL + tok;
    return (c < 32) ? d_cq[t*PP + c] : d_sq[t*PP + c - 32];
}
__device__ __forceinline__ uint32_t f2tf(float f){
    uint32_t r; asm("cvt.rna.tf32.f32 %0, %1;" : "=r"(r) : "f"(f)); return r;
}
__device__ __forceinline__ uint32_t fb(float f){ return __float_as_uint(f); }
__device__ __forceinline__ float f2tf_as_f(float f){
    uint32_t r = f2tf(f); return __uint_as_float(r);
}
__device__ __forceinline__ void mma_tf32(float* c, const uint32_t* a, const uint32_t* b){
    asm volatile(
      "mma.sync.aligned.m16n8k8.row.col.f32.tf32.tf32.f32 "
      "{%0,%1,%2,%3}, {%4,%5,%6,%7}, {%8,%9}, {%0,%1,%2,%3};\n"
      : "+f"(c[0]), "+f"(c[1]), "+f"(c[2]), "+f"(c[3])
      : "r"(a[0]), "r"(a[1]), "r"(a[2]), "r"(a[3]), "r"(b[0]), "r"(b[1]));
}
__device__ __forceinline__ void cp16(uint32_t dst, const void* src, int sz){
    asm volatile("cp.async.cg.shared.global [%0], [%1], 16, %2;\n"
                 :: "r"(dst), "l"(src), "r"(sz));
}
__device__ __forceinline__ void cp_commit(){ asm volatile("cp.async.commit_group;\n"); }
__device__ __forceinline__ void cp_wait2(){ asm volatile("cp.async.wait_group 2;\n"); }

// ---------------- GEMM tile (device, 512 threads, warps 8x2, 3-stage) ----------------
#define A_PLAIN  0
#define A_CONCAT 1
#define A_LN     2
#define E_NONE 0
#define E_GELU 1
#define E_OUT  3
#define E_GATE 4
#define E_STAT 5

#define APITCH 36
#define WPITCH 72

template<int AMODE, int EPI>
__device__ void gemm_tile(float* smem,
                 const float* __restrict__ A,
                 const float* __restrict__ W,
                 const float* __restrict__ bias,
                 float* __restrict__ C,
                 const float* __restrict__ extra,
                 const float* __restrict__ lnS1, const float* __restrict__ lnS2,
                 const float* __restrict__ lnG,  const float* __restrict__ lnB,
                 float* __restrict__ oS1, float* __restrict__ oS2,
                 const float* __restrict__ gw, float* __restrict__ gpart,
                 int m0, int n0, int M, int N, int K)
{
    float* Asm = smem;                       // 3 x 128*APITCH
    float* Wsm = smem + 3*128*APITCH;        // 3 x 32*WPITCH

    const int tid = threadIdx.x;
    const int wid = tid >> 5;
    const int lane = tid & 31;
    const int grp = lane >> 2;
    const int tig = lane & 3;
    const int wm = wid >> 1;
    const int wn = wid & 1;

    float acc[4][4];
    #pragma unroll
    for (int nt=0;nt<4;nt++)
        #pragma unroll
        for (int i=0;i<4;i++) acc[nt][i]=0.f;

    float4 areg[2]; float4 gv4, bv4;
    float mrow[2], rsrow[2];
    if (AMODE == A_LN){
        #pragma unroll
        for (int it=0; it<2; it++){
            int r = m0 + (tid>>3) + it*64;
            float sa = 0.f, sb = 0.f;
            #pragma unroll
            for (int s=0; s<8; s++){ sa += lnS1[s*NTOK + r]; sb += lnS2[s*NTOK + r]; }
            float mean = sa*(1.f/256.f);
            float var = fmaxf(sb*(1.f/256.f) - mean*mean, 0.f);
            mrow[it] = mean;
            rsrow[it] = rsqrtf(var + 1e-5f);
        }
    }

    auto ldA_regs = [&](int k0){
        int kq = (tid & 7)*4;
        gv4 = *(const float4*)&lnG[k0+kq];
        bv4 = *(const float4*)&lnB[k0+kq];
        #pragma unroll
        for (int it=0; it<2; it++){
            int r = m0 + (tid>>3) + it*64;
            areg[it] = *(const float4*)&A[(size_t)r*K + k0 + kq];
        }
    };
    auto stA = [&](int buf){
        float* As = Asm + buf*128*APITCH;
        int kq = (tid & 7)*4;
        #pragma unroll
        for (int it=0; it<2; it++){
            int row = (tid>>3) + it*64;
            float4 v = areg[it];
            v.x = (v.x - mrow[it])*rsrow[it]*gv4.x + bv4.x;
            v.y = (v.y - mrow[it])*rsrow[it]*gv4.y + bv4.y;
            v.z = (v.z - mrow[it])*rsrow[it]*gv4.z + bv4.z;
            v.w = (v.w - mrow[it])*rsrow[it]*gv4.w + bv4.w;
            *(float4*)&As[row*APITCH + kq] = v;
        }
    };

    auto load_tiles = [&](int buf, int k0){
        float* As = Asm + buf*128*APITCH;
        float* Ws = Wsm + buf*32*WPITCH;
        if (AMODE != A_LN){
            #pragma unroll
            for (int it = 0; it < 2; it++){
                int linear = tid + it*NTHR;
                int row = linear >> 3;
                int kq  = (linear & 7)*4;
                int m = m0 + row;
                int kg = k0 + kq;
                const float* src; int sz = 16;
                if (AMODE == A_PLAIN){
                    src = A + (size_t)m*K + kg;
                } else {
                    if (kg < DD) src = A + (size_t)m*DD + kg;
                    else {
                        int l = m & (LL-1);
                        if (l == 0){ sz = 0; src = A; }
                        else src = A + (size_t)(m-1)*DD + (kg-DD);
                    }
                }
                cp16((uint32_t)__cvta_generic_to_shared(&As[row*APITCH + kq]), src, sz);
            }
        }
        {
            int row = tid >> 4;
            int wnq = (tid & 15)*4;
            const float* src = W + (size_t)(k0+row)*N + n0 + wnq;
            cp16((uint32_t)__cvta_generic_to_shared(&Ws[row*WPITCH + wnq]), src, 16);
        }
    };

    const int ntiles = K >> 5;   // >= 8 always
    if (AMODE == A_LN) ldA_regs(0);
    load_tiles(0, 0);
    cp_commit();
    if (AMODE == A_LN) stA(0);
    if (AMODE == A_LN) ldA_regs(32);
    load_tiles(1, 32);
    cp_commit();
    if (AMODE == A_LN) stA(1);

    for (int kt = 0; kt < ntiles; kt++){
        int buf = kt % 3;
        if (kt+2 < ntiles){
            if (AMODE == A_LN) ldA_regs((kt+2)*32);
            load_tiles((kt+2)%3, (kt+2)*32);
        }
        cp_commit();
        cp_wait2();
        __syncthreads();

        const float* As = Asm + buf*128*APITCH;
        const float* Ws = Wsm + buf*32*WPITCH;
        #pragma unroll
        for (int ks = 0; ks < 32; ks += 8){
            uint32_t afr[4], bfr[4][2];
            int rb = wm*16 + grp;
            afr[0] = fb(As[(rb  )*APITCH + ks + tig    ]);
            afr[1] = fb(As[(rb+8)*APITCH + ks + tig    ]);
            afr[2] = fb(As[(rb  )*APITCH + ks + tig + 4]);
            afr[3] = fb(As[(rb+8)*APITCH + ks + tig + 4]);
            #pragma unroll
            for (int nt=0; nt<4; nt++){
                int cb = wn*32 + nt*8 + grp;
                bfr[nt][0] = fb(Ws[(ks + tig    )*WPITCH + cb]);
                bfr[nt][1] = fb(Ws[(ks + tig + 4)*WPITCH + cb]);
            }
            #pragma unroll
            for (int nt=0; nt<4; nt++)
                mma_tf32(acc[nt], afr, bfr[nt]);
        }
        if (AMODE == A_LN && kt+2 < ntiles) stA((kt+2)%3);
        __syncthreads();
    }

    if (EPI == E_GATE){
        int slot = (n0 >> 6)*2 + wn;
        #pragma unroll
        for (int half=0; half<2; half++){
            int r = m0 + wm*16 + grp + half*8;
            float part = 0.f;
            #pragma unroll
            for (int nt=0; nt<4; nt++){
                int cb = n0 + wn*32 + nt*8 + 2*tig;
                float v0 = gelu_f(acc[nt][half*2+0] + bias[cb]);
                float v1 = gelu_f(acc[nt][half*2+1] + bias[cb+1]);
                part += v0*gw[cb] + v1*gw[cb+1];
            }
            part += __shfl_xor_sync(0xffffffffu, part, 1);
            part += __shfl_xor_sync(0xffffffffu, part, 2);
            if (tig == 0)
                gpart[(size_t)r*8 + slot] = part;
        }
        return;
    }

    #pragma unroll
    for (int half=0; half<2; half++){
        int r = m0 + wm*16 + grp + half*8;
        float s = 0.f, ss = 0.f;
        #pragma unroll
        for (int nt=0; nt<4; nt++){
            int cb = n0 + wn*32 + nt*8 + 2*tig;
            float v0 = acc[nt][half*2+0] + bias[cb];
            float v1 = acc[nt][half*2+1] + bias[cb+1];
            if (EPI == E_GELU){ v0 = gelu_f(v0); v1 = gelu_f(v1); }
            if (EPI == E_OUT) { v0 += extra[(size_t)r*DD + cb];
                                v1 += extra[(size_t)r*DD + cb + 1]; }
            if (EPI == E_STAT){ s += v0 + v1; ss += v0*v0 + v1*v1; }
            *(float2*)&C[(size_t)r*N + cb] = make_float2(v0, v1);
        }
        if (EPI == E_STAT){
            s  += __shfl_xor_sync(0xffffffffu, s, 1);
            s  += __shfl_xor_sync(0xffffffffu, s, 2);
            ss += __shfl_xor_sync(0xffffffffu, ss, 1);
            ss += __shfl_xor_sync(0xffffffffu, ss, 2);
            if (tig == 0){
                int slot = (n0 >> 6)*2 + wn;
                oS1[slot*NTOK + r] = s;
                oS2[slot*NTOK + r] = ss;
            }
        }
    }
}

// ---------------- phases job: smem-staged, 32 tokens per block ----------------
__device__ void phases_job(int blk, const float* __restrict__ x,
                           const float* __restrict__ Wk,
                           const float* __restrict__ bk,
                           float* smem){
    __syncthreads();               // smem handoff from previous GEMM
    float* xs = smem;              // 32 x 256
    float* wk = smem + 32*256;     // 256 x 32
    const int tid = threadIdx.x;
    const int rowbase = blk*32;
    for (int i = tid; i < 32*64; i += NTHR){
        int r = i >> 6, c4 = (i & 63)*4;
        *(float4*)&xs[r*256 + c4] = *(const float4*)&x[(size_t)(rowbase+r)*DD + c4];
    }
    for (int i = tid; i < 2048; i += NTHR){
        *(float4*)&wk[i*4] = *(const float4*)&Wk[i*4];
    }
    __syncthreads();
    int w = tid >> 5, p = tid & 31;
    int t0 = 2*w;
    float bkp = bk[p];
    float s0 = bkp, s1 = bkp;
    #pragma unroll 16
    for (int k = 0; k < 256; k++){
        float wv = wk[k*32 + p];
        s0 += xs[t0*256 + k]*wv;
        s1 += xs[(t0+1)*256 + k]*wv;
    }
    const float PI = 3.14159265358979323846f;
    float sn, cs;
    sincosf(tanhf(s0)*PI, &sn, &cs); d_cq[(rowbase+t0  )*PP+p]=cs; d_sq[(rowbase+t0  )*PP+p]=sn;
    sincosf(tanhf(s1)*PI, &sn, &cs); d_cq[(rowbase+t0+1)*PP+p]=cs; d_sq[(rowbase+t0+1)*PP+p]=sn;
}

// ---------------- gate finalize + scan ----------------
__device__ void cumsum_job(int b, const float* __restrict__ bg2, float* smem){
    int tid = threadIdx.x;
    int lane = tid & 31, warp = tid >> 5;
    float* wtot = smem;
    float bv = bg2[0];
    float v[4]; float run = 0.f;
    #pragma unroll
    for (int i=0;i<4;i++){
        int tok = b*LL + tid*4 + i;
        float4 a = *(const float4*)&d_gpart[(size_t)tok*8];
        float4 c = *(const float4*)&d_gpart[(size_t)tok*8 + 4];
        float s = bv + a.x+a.y+a.z+a.w + c.x+c.y+c.z+c.w;
        float g = 1.f/(1.f + expf(-s));
        d_g[tok] = g;
        run += g; v[i] = run;
    }
    float x = run;
    #pragma unroll
    for (int o=1;o<32;o<<=1){
        float y = __shfl_up_sync(0xffffffffu, x, o);
        if (lane >= o) x += y;
    }
    if (lane == 31) wtot[warp] = x;
    __syncthreads();
    if (warp == 0 && lane < 16){
        float t = wtot[lane];
        #pragma unroll
        for (int o=1;o<16;o<<=1){
            float z = __shfl_up_sync(0xffffu, t, o);
            if (lane >= o) t += z;
        }
        wtot[lane] = t;
    }
    __syncthreads();
    float off = (x - run) + (warp ? wtot[warp-1] : 0.f);
    float* gc = d_gc + b*LL + tid*4;
    #pragma unroll
    for (int i=0;i<4;i++) gc[i] = v[i] + off;
}

// ---------------- chunk state slice ----------------
__device__ void chunk_state_job(int cc, int b, int tile, float* smem){
    float* sA = smem;            // 64*36
    float* sB = sA + 64*36;      // 32*264
    const int tid = threadIdx.x;
    const int wid = tid >> 5, lane = tid & 31;
    const int grp = lane >> 2, tig = lane & 3;
    const int wm = wid >> 3;
    const int wn = wid & 7;

    float acc[2][4][4];
    #pragma unroll
    for (int mt=0;mt<2;mt++)
        #pragma unroll
        for (int nt=0;nt<4;nt++)
            #pragma unroll
            for (int i=0;i<4;i++) acc[mt][nt][i]=0.f;

    int t0 = cc*CH + tile*32;
    for (int i = tid; i < 64*32; i += NTHR){
        int p = i>>5, t = i&31;
        int gt = t0 + t;
        sA[p*36 + t] = (gt >= 1) ? f2tf_as_f(phasor(b, gt-1, p)) : 0.f;
    }
    for (int i = tid; i < 32*64; i += NTHR){
        int t = i>>6, c4 = (i&63)*4;
        float gv = d_g[b*LL + t0 + t];
        float4 v = *(const float4*)&d_v[((size_t)(b*LL + t0 + t))*DD + c4];
        v.x = f2tf_as_f(v.x*gv); v.y = f2tf_as_f(v.y*gv);
        v.z = f2tf_as_f(v.z*gv); v.w = f2tf_as_f(v.w*gv);
        *(float4*)&sB[t*264 + c4] = v;
    }
    __syncthreads();
    #pragma unroll
    for (int ks = 0; ks < 32; ks += 8){
        uint32_t afr[2][4], bfr[4][2];
        #pragma unroll
        for (int mt=0; mt<2; mt++){
            int rb = wm*32 + mt*16 + grp;
            afr[mt][0] = fb(sA[(rb  )*36 + ks + tig    ]);
            afr[mt][1] = fb(sA[(rb+8)*36 + ks + tig    ]);
            afr[mt][2] = fb(sA[(rb  )*36 + ks + tig + 4]);
            afr[mt][3] = fb(sA[(rb+8)*36 + ks + tig + 4]);
        }
        #pragma unroll
        for (int nt=0; nt<4; nt++){
            int cb = wn*32 + nt*8 + grp;
            bfr[nt][0] = fb(sB[(ks + tig    )*264 + cb]);
            bfr[nt][1] = fb(sB[(ks + tig + 4)*264 + cb]);
        }
        #pragma unroll
        for (int mt=0; mt<2; mt++)
            #pragma unroll
            for (int nt=0; nt<4; nt++)
                mma_tf32(acc[mt][nt], afr[mt], bfr[nt]);
    }
    __syncthreads();
    size_t base = ((size_t)(b*64 + cc*4 + tile))*64*DD;
    #pragma unroll
    for (int mt=0; mt<2; mt++)
        #pragma unroll
        for (int nt=0; nt<4; nt++)
            #pragma unroll
            for (int half=0; half<2; half++){
                int row = wm*32 + mt*16 + grp + half*8;
                int col = wn*32 + nt*8 + 2*tig;
                *(float2*)&d_state[base + (size_t)row*DD + col] =
                    make_float2(acc[mt][nt][half*2], acc[mt][nt][half*2+1]);
            }
}

// ---------------- chunk prefix over 64 slices ----------------
__device__ void chunk_prefix_job(int b, int gs){
    int off = gs*2048 + threadIdx.x*4;
    float4 run = make_float4(0.f,0.f,0.f,0.f);
    #pragma unroll 8
    for (int c = 0; c < 64; c++){
        size_t base = ((size_t)(b*64 + c))*16384 + off;
        float4 v = *(const float4*)&d_state[base];
        if ((c & 3) == 0){
            size_t pb = ((size_t)(b*NCH + (c>>2)))*16384 + off;
            *(float4*)&d_pref[pb] = run;
        }
        run.x += v.x; run.y += v.y; run.z += v.z; run.w += v.w;
    }
}

// ---------------- chunk out ----------------
__device__ void chunk_out_job(int cc, int ds, int b, float* sm){
    float* sQ  = sm;
    float* sKT = sQ + 128*68;
    float* sS  = sKT + 64*136;
    float* sV  = sS + 128*132;
    float* sP  = sV + 128*72;
    const int tid = threadIdx.x;
    const int wid = tid >> 5, lane = tid & 31;
    const int grp = lane >> 2, tig = lane & 3;

    for (int i = tid; i < CH*64; i += NTHR){
        int r = i>>6, c = i&63;
        sQ[r*68 + c] = f2tf_as_f(phasor(b, cc*CH + r, c));
    }
    for (int i = tid; i < CH*64; i += NTHR){
        int t = i>>6, c = i&63;
        int gt = cc*CH + t;
        sKT[c*136 + t] = (gt >= 1) ? f2tf_as_f(phasor(b, gt-1, c)) : 0.f;
    }
    for (int i = tid; i < 128*16; i += NTHR){
        int t = i>>4, c4 = (i&15)*4;
        float gv = d_g[b*LL + cc*CH + t];
        float4 v = *(const float4*)&d_v[((size_t)(b*LL + cc*CH + t))*DD + ds*64 + c4];
        v.x = f2tf_as_f(v.x*gv); v.y = f2tf_as_f(v.y*gv);
        v.z = f2tf_as_f(v.z*gv); v.w = f2tf_as_f(v.w*gv);
        *(float4*)&sV[t*72 + c4] = v;
    }
    size_t pbase = ((size_t)(b*NCH + cc))*64*DD;
    for (int i = tid; i < 64*16; i += NTHR){
        int p = i>>4, c4 = (i&15)*4;
        float4 v = *(const float4*)&d_pref[pbase + (size_t)p*DD + ds*64 + c4];
        v.x = f2tf_as_f(v.x); v.y = f2tf_as_f(v.y);
        v.z = f2tf_as_f(v.z); v.w = f2tf_as_f(v.w);
        *(float4*)&sP[p*72 + c4] = v;
    }
    __syncthreads();

    // scores: 16 warps, 4x4 layout
    {
        const int wm = wid >> 2;
        const int wn = wid & 3;
        float acc2[2][4][4];
        #pragma unroll
        for (int mt=0;mt<2;mt++)
            #pragma unroll
            for (int nt=0;nt<4;nt++)
                #pragma unroll
                for (int i=0;i<4;i++) acc2[mt][nt][i]=0.f;
        #pragma unroll
        for (int ks = 0; ks < 64; ks += 8){
            uint32_t afr[2][4], bfr[4][2];
            #pragma unroll
            for (int mt=0; mt<2; mt++){
                int rb = wm*32 + mt*16 + grp;
                afr[mt][0] = fb(sQ[(rb  )*68 + ks + tig    ]);
                afr[mt][1] = fb(sQ[(rb+8)*68 + ks + tig    ]);
                afr[mt][2] = fb(sQ[(rb  )*68 + ks + tig + 4]);
                afr[mt][3] = fb(sQ[(rb+8)*68 + ks + tig + 4]);
            }
            #pragma unroll
            for (int nt=0; nt<4; nt++){
                int cb = wn*32 + nt*8 + grp;
                bfr[nt][0] = fb(sKT[(ks + tig    )*136 + cb]);
                bfr[nt][1] = fb(sKT[(ks + tig + 4)*136 + cb]);
            }
            #pragma unroll
            for (int mt=0; mt<2; mt++)
                #pragma unroll
                for (int nt=0; nt<4; nt++)
                    mma_tf32(acc2[mt][nt], afr[mt], bfr[nt]);
        }
        #pragma unroll
        for (int mt=0; mt<2; mt++)
            #pragma unroll
            for (int nt=0; nt<4; nt++)
                #pragma unroll
                for (int half=0; half<2; half++){
                    int row = wm*32 + mt*16 + grp + half*8;
                    int col = wn*32 + nt*8 + 2*tig;
                    sS[row*132 + col    ] = (col   <= row) ? acc2[mt][nt][half*2  ] : 0.f;
                    sS[row*132 + col + 1] = (col+1 <= row) ? acc2[mt][nt][half*2+1] : 0.f;
                }
    }
    __syncthreads();

    // out: 16 warps, 8x2 layout
    const int wm = wid >> 1;
    const int wn = wid & 1;
    float acc[4][4];
    #pragma unroll
    for (int nt=0;nt<4;nt++)
        #pragma unroll
        for (int i=0;i<4;i++) acc[nt][i]=0.f;

    #pragma unroll 4
    for (int ks = 0; ks < 128; ks += 8){
        uint32_t afr[4], bfr[4][2];
        int rb = wm*16 + grp;
        afr[0] = fb(sS[(rb  )*132 + ks + tig    ]);
        afr[1] = fb(sS[(rb+8)*132 + ks + tig    ]);
        afr[2] = fb(sS[(rb  )*132 + ks + tig + 4]);
        afr[3] = fb(sS[(rb+8)*132 + ks + tig + 4]);
        #pragma unroll
        for (int nt=0; nt<4; nt++){
            int cb = wn*32 + nt*8 + grp;
            bfr[nt][0] = fb(sV[(ks + tig    )*72 + cb]);
            bfr[nt][1] = fb(sV[(ks + tig + 4)*72 + cb]);
        }
        #pragma unroll
        for (int nt=0; nt<4; nt++)
            mma_tf32(acc[nt], afr, bfr[nt]);
    }
    #pragma unroll
    for (int ks = 0; ks < 64; ks += 8){
        uint32_t afr[4], bfr[4][2];
        int rb = wm*16 + grp;
        afr[0] = fb(sQ[(rb  )*68 + ks + tig    ]);
        afr[1] = fb(sQ[(rb+8)*68 + ks + tig    ]);
        afr[2] = fb(sQ[(rb  )*68 + ks + tig + 4]);
        afr[3] = fb(sQ[(rb+8)*68 + ks + tig + 4]);
        #pragma unroll
        for (int nt=0; nt<4; nt++){
            int cb = wn*32 + nt*8 + grp;
            bfr[nt][0] = fb(sP[(ks + tig    )*72 + cb]);
            bfr[nt][1] = fb(sP[(ks + tig + 4)*72 + cb]);
        }
        #pragma unroll
        for (int nt=0; nt<4; nt++)
            mma_tf32(acc[nt], afr, bfr[nt]);
    }

    int slot = ds*2 + wn;
    #pragma unroll
    for (int half=0; half<2; half++){
        int rloc = wm*16 + grp + half*8;
        int gtok = b*LL + cc*CH + rloc;
        float sc = rsqrtf(fmaxf(d_gc[gtok], 1.f)) * 0.17677669529663687f;
        float s = 0.f, ss = 0.f;
        #pragma unroll
        for (int nt=0; nt<4; nt++){
            int col = wn*32 + nt*8 + 2*tig;
            float v0 = acc[nt][half*2+0]*sc;
            float v1 = acc[nt][half*2+1]*sc;
            *(float2*)&d_ret[(size_t)gtok*DD + ds*64 + col] = make_float2(v0, v1);
            s += v0 + v1; ss += v0*v0 + v1*v1;
        }
        s  += __shfl_xor_sync(0xffffffffu, s, 1);
        s  += __shfl_xor_sync(0xffffffffu, s, 2);
        ss += __shfl_xor_sync(0xffffffffu, ss, 1);
        ss += __shfl_xor_sync(0xffffffffu, ss, 2);
        if (tig == 0){
            d_s1[slot*NTOK + gtok] = s;
            d_s2[slot*NTOK + gtok] = ss;
        }
    }
}

// ---------------- mega kernel ----------------
#define MEGA_SMEM ((128*68 + 64*136 + 128*132 + 128*72 + 64*72)*(int)sizeof(float))

__global__ void __launch_bounds__(NTHR, 1)
mega_kernel(const float* __restrict__ x,
            const float* __restrict__ Wk,  const float* __restrict__ bk,
            const float* __restrict__ Wv,  const float* __restrict__ bv,
            const float* __restrict__ Wg1, const float* __restrict__ bg1,
            const float* __restrict__ Wg2, const float* __restrict__ bg2,
            const float* __restrict__ ln1g,const float* __restrict__ ln1b,
            const float* __restrict__ Wr1, const float* __restrict__ br1,
            const float* __restrict__ Wr2, const float* __restrict__ br2,
            const float* __restrict__ ln2g,const float* __restrict__ ln2b,
            const float* __restrict__ Wo,  const float* __restrict__ bo,
            float* __restrict__ out)
{
    extern __shared__ __align__(16) float smem[];
    const int blk = blockIdx.x;
    const int m0 = (blk & 31)*128;
    const int n0 = (blk >> 5)*64;

    // Phase A
    gemm_tile<A_CONCAT, E_GATE>(smem, x, Wg1, bg1, nullptr, nullptr,
        nullptr, nullptr, nullptr, nullptr, nullptr, nullptr,
        Wg2, d_gpart, m0, n0, NTOK, DD, 2*DD);
    gemm_tile<A_PLAIN, E_NONE>(smem, x, Wv, bv, d_v, nullptr,
        nullptr, nullptr, nullptr, nullptr, nullptr, nullptr,
        nullptr, nullptr, m0, n0, NTOK, DD, DD);
    phases_job(blk, x, Wk, bk, smem);
    gbar();

    // Phase B
    if (blk < BB) cumsum_job(blk, bg2, smem);
    gbar();

    // Phase C
    chunk_state_job((blk >> 2) & 15, blk >> 6, blk & 3, smem);
    gbar();

    // Phase D
    if (blk < 16) chunk_prefix_job(blk >> 3, blk & 7);
    gbar();

    // Phase E
    chunk_out_job((blk >> 2) & 15, blk & 3, blk >> 6, smem);
    gbar();

    // Phase F
    for (int t = blk; t < 256; t += NBLK){
        int fm0 = (t & 31)*128;
        int fn0 = (t >> 5)*64;
        gemm_tile<A_LN, E_GELU>(smem, d_ret, Wr1, br1, d_t1, nullptr,
            d_s1, d_s2, ln1g, ln1b, nullptr, nullptr,
            nullptr, nullptr, fm0, fn0, NTOK, 2*DD, DD);
    }
    gbar();

    // Phase G
    gemm_tile<A_PLAIN, E_STAT>(smem, d_t1, Wr2, br2, d_t2, nullptr,
        nullptr, nullptr, nullptr, nullptr, d_s1b, d_s2b,
        nullptr, nullptr, m0, n0, NTOK, DD, 2*DD);
    gbar();

    // Phase H
    gemm_tile<A_LN, E_OUT>(smem, d_t2, Wo, bo, out, x,
        d_s1b, d_s2b, ln2g, ln2b, nullptr, nullptr,
        nullptr, nullptr, m0, n0, NTOK, DD, DD);
}

// ---------------- launch ----------------
extern "C" void kernel_launch(void* const* d_in, const int* in_sizes, int n_in,
                              void* d_out, int out_size)
{
    const float* x    = (const float*)d_in[0];
    const float* Wk   = (const float*)d_in[1];
    const float* bk   = (const float*)d_in[2];
    const float* Wv   = (const float*)d_in[3];
    const float* bv   = (const float*)d_in[4];
    const float* Wg1  = (const float*)d_in[5];
    const float* bg1  = (const float*)d_in[6];
    const float* Wg2  = (const float*)d_in[7];
    const float* bg2  = (const float*)d_in[8];
    const float* ln1g = (const float*)d_in[9];
    const float* ln1b = (const float*)d_in[10];
    const float* Wr1  = (const float*)d_in[11];
    const float* br1  = (const float*)d_in[12];
    const float* Wr2  = (const float*)d_in[13];
    const float* br2  = (const float*)d_in[14];
    const float* ln2g = (const float*)d_in[15];
    const float* ln2b = (const float*)d_in[16];
    const float* Wo   = (const float*)d_in[17];
    const float* bo   = (const float*)d_in[18];
    float* out = (float*)d_out;

    static bool init = false;
    if (!init){
        cudaFuncSetAttribute(mega_kernel, cudaFuncAttributeMaxDynamicSharedMemorySize, MEGA_SMEM);
        init = true;
    }

    mega_kernel<<<NBLK, NTHR, MEGA_SMEM>>>(
        x, Wk, bk, Wv, bv, Wg1, bg1, Wg2, bg2,
        ln1g, ln1b, Wr1, br1, Wr2, br2, ln2g, ln2b, Wo, bo, out);
    (void)in_sizes; (void)n_in; (void)out_size;
}

// round 12
// speedup vs baseline: 3.0716x; 1.0542x over previous
#include <cuda_runtime.h>
#include <math.h>
#include <stdint.h>

#define BB 2
#define LL 2048
#define DD 256
#define PP 32
#define NTOK (BB*LL)
#define NCH 16
#define CH 128
#define NBLK 128
#define NTHR 512

// ---------------- scratch ----------------
__device__ float d_cq[NTOK*PP];
__device__ float d_sq[NTOK*PP];
__device__ float d_g [NTOK];
__device__ float d_gc[NTOK];
__device__ float d_v [NTOK*DD];
__device__ float d_ret[NTOK*DD];
__device__ float d_t1[NTOK*2*DD];
__device__ float d_t2[NTOK*DD];
__device__ float d_state[BB*64*64*DD];
__device__ float d_pref [BB*NCH*64*DD];
__device__ float d_gpart[NTOK*8];
__device__ float d_s1 [8*NTOK];
__device__ float d_s2 [8*NTOK];
__device__ float d_s1b[8*NTOK];
__device__ float d_s2b[8*NTOK];

__device__ unsigned bar_cnt = 0;
__device__ unsigned bar_gen = 0;

__device__ __forceinline__ void gbar(){
    __syncthreads();
    __threadfence();
    if (threadIdx.x == 0){
        volatile unsigned* vg = &bar_gen;
        unsigned gen = *vg;
        unsigned t = atomicAdd(&bar_cnt, 1);
        if (t == gridDim.x - 1){
            atomicExch(&bar_cnt, 0);
            __threadfence();
            atomicAdd(&bar_gen, 1);
        } else {
            while (*vg == gen) { __nanosleep(32); }
        }
    }
    __syncthreads();
}

__device__ __forceinline__ float gelu_f(float x){
    return 0.5f*x*(1.0f+erff(x*0.7071067811865476f));
}
__device__ __forceinline__ float phasor(int b, int tok, int c){
    int t = b*LL + tok;
    return (c < 32) ? d_cq[t*PP + c] : d_sq[t*PP + c - 32];
}
__device__ __forceinline__ uint32_t f2tf(float f){
    uint32_t r; asm("cvt.rna.tf32.f32 %0, %1;" : "=r"(r) : "f"(f)); return r;
}
__device__ __forceinline__ uint32_t fb(float f){ return __float_as_uint(f); }
__device__ __forceinline__ float f2tf_as_f(float f){
    uint32_t r = f2tf(f); return __uint_as_float(r);
}
__device__ __forceinline__ void mma_tf32(float* c, const uint32_t* a, const uint32_t* b){
    asm volatile(
      "mma.sync.aligned.m16n8k8.row.col.f32.tf32.tf32.f32 "
      "{%0,%1,%2,%3}, {%4,%5,%6,%7}, {%8,%9}, {%0,%1,%2,%3};\n"
      : "+f"(c[0]), "+f"(c[1]), "+f"(c[2]), "+f"(c[3])
      : "r"(a[0]), "r"(a[1]), "r"(a[2]), "r"(a[3]), "r"(b[0]), "r"(b[1]));
}
// A-side fragment via ldmatrix: 4x 8x8-b16 tiles == 16x8-b32 tf32 A fragment.
__device__ __forceinline__ void ldsm4(uint32_t* r, uint32_t addr){
    asm volatile("ldmatrix.sync.aligned.m8n8.x4.shared.b16 {%0,%1,%2,%3}, [%4];\n"
        : "=r"(r[0]), "=r"(r[1]), "=r"(r[2]), "=r"(r[3]) : "r"(addr));
}
__device__ __forceinline__ uint32_t shaddr(const void* p){
    return (uint32_t)__cvta_generic_to_shared(p);
}
// per-lane byte offset (in floats *4) for ldmatrix A fragment rooted at (row0, col0), pitch P floats
__device__ __forceinline__ uint32_t ldsm_off(int lane, int row0, int P){
    int t8 = lane >> 3, r8 = lane & 7;
    return (uint32_t)(((row0 + r8 + (t8 & 1)*8)*P + (t8 >> 1)*4) * 4);
}

__device__ __forceinline__ void cp16(uint32_t dst, const void* src, int sz){
    asm volatile("cp.async.cg.shared.global [%0], [%1], 16, %2;\n"
                 :: "r"(dst), "l"(src), "r"(sz));
}
__device__ __forceinline__ void cp_commit(){ asm volatile("cp.async.commit_group;\n"); }
__device__ __forceinline__ void cp_wait1(){ asm volatile("cp.async.wait_group 1;\n"); }

// ---------------- GEMM tile (512 threads, warps 8x2, 3-stage, ldmatrix A) ----------------
#define A_PLAIN  0
#define A_CONCAT 1
#define A_LN     2
#define E_NONE 0
#define E_GELU 1
#define E_OUT  3
#define E_GATE 4
#define E_STAT 5

#define APITCH 36
#define WPITCH 72

template<int AMODE, int EPI>
__device__ void gemm_tile(float* smem,
                 const float* __restrict__ A,
                 const float* __restrict__ W,
                 const float* __restrict__ bias,
                 float* __restrict__ C,
                 const float* __restrict__ extra,
                 const float* __restrict__ lnS1, const float* __restrict__ lnS2,
                 const float* __restrict__ lnG,  const float* __restrict__ lnB,
                 float* __restrict__ oS1, float* __restrict__ oS2,
                 const float* __restrict__ gw, float* __restrict__ gpart,
                 int m0, int n0, int M, int N, int K)
{
    float* Asm = smem;                       // 3 x 128*APITCH
    float* Wsm = smem + 3*128*APITCH;        // 3 x 32*WPITCH

    const int tid = threadIdx.x;
    const int wid = tid >> 5;
    const int lane = tid & 31;
    const int grp = lane >> 2;
    const int tig = lane & 3;
    const int wm = wid >> 1;
    const int wn = wid & 1;

    float acc[4][4];
    #pragma unroll
    for (int nt=0;nt<4;nt++)
        #pragma unroll
        for (int i=0;i<4;i++) acc[nt][i]=0.f;

    float4 areg[2]; float4 gv4, bv4;
    float mrow[2], rsrow[2];
    if (AMODE == A_LN){
        #pragma unroll
        for (int it=0; it<2; it++){
            int r = m0 + (tid>>3) + it*64;
            float sa = 0.f, sb = 0.f;
            #pragma unroll
            for (int s=0; s<8; s++){ sa += lnS1[s*NTOK + r]; sb += lnS2[s*NTOK + r]; }
            float mean = sa*(1.f/256.f);
            float var = fmaxf(sb*(1.f/256.f) - mean*mean, 0.f);
            mrow[it] = mean;
            rsrow[it] = rsqrtf(var + 1e-5f);
        }
    }

    auto ldA_regs = [&](int k0){
        int kq = (tid & 7)*4;
        gv4 = *(const float4*)&lnG[k0+kq];
        bv4 = *(const float4*)&lnB[k0+kq];
        #pragma unroll
        for (int it=0; it<2; it++){
            int r = m0 + (tid>>3) + it*64;
            areg[it] = *(const float4*)&A[(size_t)r*K + k0 + kq];
        }
    };
    auto stA = [&](int buf){
        float* As = Asm + buf*128*APITCH;
        int kq = (tid & 7)*4;
        #pragma unroll
        for (int it=0; it<2; it++){
            int row = (tid>>3) + it*64;
            float4 v = areg[it];
            v.x = (v.x - mrow[it])*rsrow[it]*gv4.x + bv4.x;
            v.y = (v.y - mrow[it])*rsrow[it]*gv4.y + bv4.y;
            v.z = (v.z - mrow[it])*rsrow[it]*gv4.z + bv4.z;
            v.w = (v.w - mrow[it])*rsrow[it]*gv4.w + bv4.w;
            *(float4*)&As[row*APITCH + kq] = v;
        }
    };

    auto load_tiles = [&](int buf, int k0){
        float* As = Asm + buf*128*APITCH;
        float* Ws = Wsm + buf*32*WPITCH;
        if (AMODE != A_LN){
            #pragma unroll
            for (int it = 0; it < 2; it++){
                int linear = tid + it*NTHR;
                int row = linear >> 3;
                int kq  = (linear & 7)*4;
                int m = m0 + row;
                int kg = k0 + kq;
                const float* src; int sz = 16;
                if (AMODE == A_PLAIN){
                    src = A + (size_t)m*K + kg;
                } else {
                    if (kg < DD) src = A + (size_t)m*DD + kg;
                    else {
                        int l = m & (LL-1);
                        if (l == 0){ sz = 0; src = A; }
                        else src = A + (size_t)(m-1)*DD + (kg-DD);
                    }
                }
                cp16((uint32_t)__cvta_generic_to_shared(&As[row*APITCH + kq]), src, sz);
            }
        }
        {
            int row = tid >> 4;
            int wnq = (tid & 15)*4;
            const float* src = W + (size_t)(k0+row)*N + n0 + wnq;
            cp16((uint32_t)__cvta_generic_to_shared(&Ws[row*WPITCH + wnq]), src, 16);
        }
    };

    const uint32_t aoff = ldsm_off(lane, wm*16, APITCH);

    const int ntiles = K >> 5;   // >= 8 always
    if (AMODE == A_LN) ldA_regs(0);
    load_tiles(0, 0);
    cp_commit();
    if (AMODE == A_LN) stA(0);
    if (AMODE == A_LN) ldA_regs(32);
    load_tiles(1, 32);
    cp_commit();
    if (AMODE == A_LN) stA(1);

    for (int kt = 0; kt < ntiles; kt++){
        int buf = kt % 3;
        cp_wait1();
        __syncthreads();

        if (kt+2 < ntiles){
            if (AMODE == A_LN) ldA_regs((kt+2)*32);
            load_tiles((kt+2)%3, (kt+2)*32);
        }
        cp_commit();

        const float* As = Asm + buf*128*APITCH;
        const float* Ws = Wsm + buf*32*WPITCH;
        const uint32_t abase = shaddr(As) + aoff;
        #pragma unroll
        for (int ks = 0; ks < 32; ks += 8){
            uint32_t afr[4], bfr[4][2];
            ldsm4(afr, abase + ks*4);
            #pragma unroll
            for (int nt=0; nt<4; nt++){
                int cb = wn*32 + nt*8 + grp;
                bfr[nt][0] = fb(Ws[(ks + tig    )*WPITCH + cb]);
                bfr[nt][1] = fb(Ws[(ks + tig + 4)*WPITCH + cb]);
            }
            #pragma unroll
            for (int nt=0; nt<4; nt++)
                mma_tf32(acc[nt], afr, bfr[nt]);
        }
        if (AMODE == A_LN && kt+2 < ntiles) stA((kt+2)%3);
    }

    if (EPI == E_GATE){
        int slot = (n0 >> 6)*2 + wn;
        #pragma unroll
        for (int half=0; half<2; half++){
            int r = m0 + wm*16 + grp + half*8;
            float part = 0.f;
            #pragma unroll
            for (int nt=0; nt<4; nt++){
                int cb = n0 + wn*32 + nt*8 + 2*tig;
                float v0 = gelu_f(acc[nt][half*2+0] + bias[cb]);
                float v1 = gelu_f(acc[nt][half*2+1] + bias[cb+1]);
                part += v0*gw[cb] + v1*gw[cb+1];
            }
            part += __shfl_xor_sync(0xffffffffu, part, 1);
            part += __shfl_xor_sync(0xffffffffu, part, 2);
            if (tig == 0)
                gpart[(size_t)r*8 + slot] = part;
        }
        return;
    }

    #pragma unroll
    for (int half=0; half<2; half++){
        int r = m0 + wm*16 + grp + half*8;
        float s = 0.f, ss = 0.f;
        #pragma unroll
        for (int nt=0; nt<4; nt++){
            int cb = n0 + wn*32 + nt*8 + 2*tig;
            float v0 = acc[nt][half*2+0] + bias[cb];
            float v1 = acc[nt][half*2+1] + bias[cb+1];
            if (EPI == E_GELU){ v0 = gelu_f(v0); v1 = gelu_f(v1); }
            if (EPI == E_OUT) { v0 += extra[(size_t)r*DD + cb];
                                v1 += extra[(size_t)r*DD + cb + 1]; }
            if (EPI == E_STAT){ s += v0 + v1; ss += v0*v0 + v1*v1; }
            *(float2*)&C[(size_t)r*N + cb] = make_float2(v0, v1);
        }
        if (EPI == E_STAT){
            s  += __shfl_xor_sync(0xffffffffu, s, 1);
            s  += __shfl_xor_sync(0xffffffffu, s, 2);
            ss += __shfl_xor_sync(0xffffffffu, ss, 1);
            ss += __shfl_xor_sync(0xffffffffu, ss, 2);
            if (tig == 0){
                int slot = (n0 >> 6)*2 + wn;
                oS1[slot*NTOK + r] = s;
                oS2[slot*NTOK + r] = ss;
            }
        }
    }
}

// ---------------- phases job: smem-staged ----------------
__device__ void phases_job(int blk, const float* __restrict__ x,
                           const float* __restrict__ Wk,
                           const float* __restrict__ bk,
                           float* smem){
    __syncthreads();
    float* xs = smem;              // 32 x 256
    float* wk = smem + 32*256;     // 256 x 32
    const int tid = threadIdx.x;
    const int rowbase = blk*32;
    for (int i = tid; i < 32*64; i += NTHR){
        int r = i >> 6, c4 = (i & 63)*4;
        *(float4*)&xs[r*256 + c4] = *(const float4*)&x[(size_t)(rowbase+r)*DD + c4];
    }
    for (int i = tid; i < 2048; i += NTHR){
        *(float4*)&wk[i*4] = *(const float4*)&Wk[i*4];
    }
    __syncthreads();
    int w = tid >> 5, p = tid & 31;
    int t0 = 2*w;
    float bkp = bk[p];
    float s0 = bkp, s1 = bkp;
    #pragma unroll 16
    for (int k = 0; k < 256; k++){
        float wv = wk[k*32 + p];
        s0 += xs[t0*256 + k]*wv;
        s1 += xs[(t0+1)*256 + k]*wv;
    }
    const float PI = 3.14159265358979323846f;
    float sn, cs;
    sincosf(tanhf(s0)*PI, &sn, &cs); d_cq[(rowbase+t0  )*PP+p]=cs; d_sq[(rowbase+t0  )*PP+p]=sn;
    sincosf(tanhf(s1)*PI, &sn, &cs); d_cq[(rowbase+t0+1)*PP+p]=cs; d_sq[(rowbase+t0+1)*PP+p]=sn;
}

// ---------------- gate finalize + scan ----------------
__device__ void cumsum_job(int b, const float* __restrict__ bg2, float* smem){
    int tid = threadIdx.x;
    int lane = tid & 31, warp = tid >> 5;
    float* wtot = smem;
    float bv = bg2[0];
    float v[4]; float run = 0.f;
    #pragma unroll
    for (int i=0;i<4;i++){
        int tok = b*LL + tid*4 + i;
        float4 a = *(const float4*)&d_gpart[(size_t)tok*8];
        float4 c = *(const float4*)&d_gpart[(size_t)tok*8 + 4];
        float s = bv + a.x+a.y+a.z+a.w + c.x+c.y+c.z+c.w;
        float g = 1.f/(1.f + expf(-s));
        d_g[tok] = g;
        run += g; v[i] = run;
    }
    float x = run;
    #pragma unroll
    for (int o=1;o<32;o<<=1){
        float y = __shfl_up_sync(0xffffffffu, x, o);
        if (lane >= o) x += y;
    }
    if (lane == 31) wtot[warp] = x;
    __syncthreads();
    if (warp == 0 && lane < 16){
        float t = wtot[lane];
        #pragma unroll
        for (int o=1;o<16;o<<=1){
            float z = __shfl_up_sync(0xffffu, t, o);
            if (lane >= o) t += z;
        }
        wtot[lane] = t;
    }
    __syncthreads();
    float off = (x - run) + (warp ? wtot[warp-1] : 0.f);
    float* gc = d_gc + b*LL + tid*4;
    #pragma unroll
    for (int i=0;i<4;i++) gc[i] = v[i] + off;
}

// ---------------- chunk state slice ----------------
__device__ void chunk_state_job(int cc, int b, int tile, float* smem){
    float* sA = smem;            // 64*36
    float* sB = sA + 64*36;      // 32*264
    const int tid = threadIdx.x;
    const int wid = tid >> 5, lane = tid & 31;
    const int grp = lane >> 2, tig = lane & 3;
    const int wm = wid >> 3;
    const int wn = wid & 7;

    float acc[2][4][4];
    #pragma unroll
    for (int mt=0;mt<2;mt++)
        #pragma unroll
        for (int nt=0;nt<4;nt++)
            #pragma unroll
            for (int i=0;i<4;i++) acc[mt][nt][i]=0.f;

    int t0 = cc*CH + tile*32;
    for (int i = tid; i < 64*32; i += NTHR){
        int p = i>>5, t = i&31;
        int gt = t0 + t;
        sA[p*36 + t] = (gt >= 1) ? f2tf_as_f(phasor(b, gt-1, p)) : 0.f;
    }
    for (int i = tid; i < 32*64; i += NTHR){
        int t = i>>6, c4 = (i&63)*4;
        float gv = d_g[b*LL + t0 + t];
        float4 v = *(const float4*)&d_v[((size_t)(b*LL + t0 + t))*DD + c4];
        v.x = f2tf_as_f(v.x*gv); v.y = f2tf_as_f(v.y*gv);
        v.z = f2tf_as_f(v.z*gv); v.w = f2tf_as_f(v.w*gv);
        *(float4*)&sB[t*264 + c4] = v;
    }
    __syncthreads();
    const uint32_t abase = shaddr(sA) + ldsm_off(lane, wm*32, 36);
    #pragma unroll
    for (int ks = 0; ks < 32; ks += 8){
        uint32_t afr[2][4], bfr[4][2];
        #pragma unroll
        for (int mt=0; mt<2; mt++)
            ldsm4(afr[mt], abase + (mt*16*36 + ks)*4);
        #pragma unroll
        for (int nt=0; nt<4; nt++){
            int cb = wn*32 + nt*8 + grp;
            bfr[nt][0] = fb(sB[(ks + tig    )*264 + cb]);
            bfr[nt][1] = fb(sB[(ks + tig + 4)*264 + cb]);
        }
        #pragma unroll
        for (int mt=0; mt<2; mt++)
            #pragma unroll
            for (int nt=0; nt<4; nt++)
                mma_tf32(acc[mt][nt], afr[mt], bfr[nt]);
    }
    __syncthreads();
    size_t base = ((size_t)(b*64 + cc*4 + tile))*64*DD;
    #pragma unroll
    for (int mt=0; mt<2; mt++)
        #pragma unroll
        for (int nt=0; nt<4; nt++)
            #pragma unroll
            for (int half=0; half<2; half++){
                int row = wm*32 + mt*16 + grp + half*8;
                int col = wn*32 + nt*8 + 2*tig;
                *(float2*)&d_state[base + (size_t)row*DD + col] =
                    make_float2(acc[mt][nt][half*2], acc[mt][nt][half*2+1]);
            }
}

// ---------------- chunk prefix over 64 slices ----------------
__device__ void chunk_prefix_job(int b, int gs){
    int off = gs*2048 + threadIdx.x*4;
    float4 run = make_float4(0.f,0.f,0.f,0.f);
    #pragma unroll 8
    for (int c = 0; c < 64; c++){
        size_t base = ((size_t)(b*64 + c))*16384 + off;
        float4 v = *(const float4*)&d_state[base];
        if ((c & 3) == 0){
            size_t pb = ((size_t)(b*NCH + (c>>2)))*16384 + off;
            *(float4*)&d_pref[pb] = run;
        }
        run.x += v.x; run.y += v.y; run.z += v.z; run.w += v.w;
    }
}

// ---------------- chunk out ----------------
__device__ void chunk_out_job(int cc, int ds, int b, float* sm){
    float* sQ  = sm;
    float* sKT = sQ + 128*68;
    float* sS  = sKT + 64*136;
    float* sV  = sS + 128*132;
    float* sP  = sV + 128*72;
    const int tid = threadIdx.x;
    const int wid = tid >> 5, lane = tid & 31;
    const int grp = lane >> 2, tig = lane & 3;

    for (int i = tid; i < CH*64; i += NTHR){
        int r = i>>6, c = i&63;
        sQ[r*68 + c] = f2tf_as_f(phasor(b, cc*CH + r, c));
    }
    for (int i = tid; i < CH*64; i += NTHR){
        int t = i>>6, c = i&63;
        int gt = cc*CH + t;
        sKT[c*136 + t] = (gt >= 1) ? f2tf_as_f(phasor(b, gt-1, c)) : 0.f;
    }
    for (int i = tid; i < 128*16; i += NTHR){
        int t = i>>4, c4 = (i&15)*4;
        float gv = d_g[b*LL + cc*CH + t];
        float4 v = *(const float4*)&d_v[((size_t)(b*LL + cc*CH + t))*DD + ds*64 + c4];
        v.x = f2tf_as_f(v.x*gv); v.y = f2tf_as_f(v.y*gv);
        v.z = f2tf_as_f(v.z*gv); v.w = f2tf_as_f(v.w*gv);
        *(float4*)&sV[t*72 + c4] = v;
    }
    size_t pbase = ((size_t)(b*NCH + cc))*64*DD;
    for (int i = tid; i < 64*16; i += NTHR){
        int p = i>>4, c4 = (i&15)*4;
        float4 v = *(const float4*)&d_pref[pbase + (size_t)p*DD + ds*64 + c4];
        v.x = f2tf_as_f(v.x); v.y = f2tf_as_f(v.y);
        v.z = f2tf_as_f(v.z); v.w = f2tf_as_f(v.w);
        *(float4*)&sP[p*72 + c4] = v;
    }
    __syncthreads();

    // scores: 16 warps, 4x4 layout
    {
        const int wm = wid >> 2;
        const int wn = wid & 3;
        float acc2[2][4][4];
        #pragma unroll
        for (int mt=0;mt<2;mt++)
            #pragma unroll
            for (int nt=0;nt<4;nt++)
                #pragma unroll
                for (int i=0;i<4;i++) acc2[mt][nt][i]=0.f;
        const uint32_t qbase = shaddr(sQ) + ldsm_off(lane, wm*32, 68);
        #pragma unroll
        for (int ks = 0; ks < 64; ks += 8){
            uint32_t afr[2][4], bfr[4][2];
            #pragma unroll
            for (int mt=0; mt<2; mt++)
                ldsm4(afr[mt], qbase + (mt*16*68 + ks)*4);
            #pragma unroll
            for (int nt=0; nt<4; nt++){
                int cb = wn*32 + nt*8 + grp;
                bfr[nt][0] = fb(sKT[(ks + tig    )*136 + cb]);
                bfr[nt][1] = fb(sKT[(ks + tig + 4)*136 + cb]);
            }
            #pragma unroll
            for (int mt=0; mt<2; mt++)
                #pragma unroll
                for (int nt=0; nt<4; nt++)
                    mma_tf32(acc2[mt][nt], afr[mt], bfr[nt]);
        }
        #pragma unroll
        for (int mt=0; mt<2; mt++)
            #pragma unroll
            for (int nt=0; nt<4; nt++)
                #pragma unroll
                for (int half=0; half<2; half++){
                    int row = wm*32 + mt*16 + grp + half*8;
                    int col = wn*32 + nt*8 + 2*tig;
                    sS[row*132 + col    ] = (col   <= row) ? acc2[mt][nt][half*2  ] : 0.f;
                    sS[row*132 + col + 1] = (col+1 <= row) ? acc2[mt][nt][half*2+1] : 0.f;
                }
    }
    __syncthreads();

    // out: 16 warps, 8x2 layout
    const int wm = wid >> 1;
    const int wn = wid & 1;
    float acc[4][4];
    #pragma unroll
    for (int nt=0;nt<4;nt++)
        #pragma unroll
        for (int i=0;i<4;i++) acc[nt][i]=0.f;

    const uint32_t sbase = shaddr(sS) + ldsm_off(lane, wm*16, 132);
    #pragma unroll 4
    for (int ks = 0; ks < 128; ks += 8){
        uint32_t afr[4], bfr[4][2];
        ldsm4(afr, sbase + ks*4);
        #pragma unroll
        for (int nt=0; nt<4; nt++){
            int cb = wn*32 + nt*8 + grp;
            bfr[nt][0] = fb(sV[(ks + tig    )*72 + cb]);
            bfr[nt][1] = fb(sV[(ks + tig + 4)*72 + cb]);
        }
        #pragma unroll
        for (int nt=0; nt<4; nt++)
            mma_tf32(acc[nt], afr, bfr[nt]);
    }
    const uint32_t qb2 = shaddr(sQ) + ldsm_off(lane, wm*16, 68);
    #pragma unroll
    for (int ks = 0; ks < 64; ks += 8){
        uint32_t afr[4], bfr[4][2];
        ldsm4(afr, qb2 + ks*4);
        #pragma unroll
        for (int nt=0; nt<4; nt++){
            int cb = wn*32 + nt*8 + grp;
            bfr[nt][0] = fb(sP[(ks + tig    )*72 + cb]);
            bfr[nt][1] = fb(sP[(ks + tig + 4)*72 + cb]);
        }
        #pragma unroll
        for (int nt=0; nt<4; nt++)
            mma_tf32(acc[nt], afr, bfr[nt]);
    }

    int slot = ds*2 + wn;
    #pragma unroll
    for (int half=0; half<2; half++){
        int rloc = wm*16 + grp + half*8;
        int gtok = b*LL + cc*CH + rloc;
        float sc = rsqrtf(fmaxf(d_gc[gtok], 1.f)) * 0.17677669529663687f;
        float s = 0.f, ss = 0.f;
        #pragma unroll
        for (int nt=0; nt<4; nt++){
            int col = wn*32 + nt*8 + 2*tig;
            float v0 = acc[nt][half*2+0]*sc;
            float v1 = acc[nt][half*2+1]*sc;
            *(float2*)&d_ret[(size_t)gtok*DD + ds*64 + col] = make_float2(v0, v1);
            s += v0 + v1; ss += v0*v0 + v1*v1;
        }
        s  += __shfl_xor_sync(0xffffffffu, s, 1);
        s  += __shfl_xor_sync(0xffffffffu, s, 2);
        ss += __shfl_xor_sync(0xffffffffu, ss, 1);
        ss += __shfl_xor_sync(0xffffffffu, ss, 2);
        if (tig == 0){
            d_s1[slot*NTOK + gtok] = s;
            d_s2[slot*NTOK + gtok] = ss;
        }
    }
}

// ---------------- mega kernel ----------------
#define MEGA_SMEM ((128*68 + 64*136 + 128*132 + 128*72 + 64*72)*(int)sizeof(float))

__global__ void __launch_bounds__(NTHR, 1)
mega_kernel(const float* __restrict__ x,
            const float* __restrict__ Wk,  const float* __restrict__ bk,
            const float* __restrict__ Wv,  const float* __restrict__ bv,
            const float* __restrict__ Wg1, const float* __restrict__ bg1,
            const float* __restrict__ Wg2, const float* __restrict__ bg2,
            const float* __restrict__ ln1g,const float* __restrict__ ln1b,
            const float* __restrict__ Wr1, const float* __restrict__ br1,
            const float* __restrict__ Wr2, const float* __restrict__ br2,
            const float* __restrict__ ln2g,const float* __restrict__ ln2b,
            const float* __restrict__ Wo,  const float* __restrict__ bo,
            float* __restrict__ out)
{
    extern __shared__ __align__(16) float smem[];
    const int blk = blockIdx.x;
    const int m0 = (blk & 31)*128;
    const int n0 = (blk >> 5)*64;

    // Phase A
    gemm_tile<A_CONCAT, E_GATE>(smem, x, Wg1, bg1, nullptr, nullptr,
        nullptr, nullptr, nullptr, nullptr, nullptr, nullptr,
        Wg2, d_gpart, m0, n0, NTOK, DD, 2*DD);
    gemm_tile<A_PLAIN, E_NONE>(smem, x, Wv, bv, d_v, nullptr,
        nullptr, nullptr, nullptr, nullptr, nullptr, nullptr,
        nullptr, nullptr, m0, n0, NTOK, DD, DD);
    phases_job(blk, x, Wk, bk, smem);
    gbar();

    // Phase B
    if (blk < BB) cumsum_job(blk, bg2, smem);
    gbar();

    // Phase C
    chunk_state_job((blk >> 2) & 15, blk >> 6, blk & 3, smem);
    gbar();

    // Phase D
    if (blk < 16) chunk_prefix_job(blk >> 3, blk & 7);
    gbar();

    // Phase E
    chunk_out_job((blk >> 2) & 15, blk & 3, blk >> 6, smem);
    gbar();

    // Phase F
    for (int t = blk; t < 256; t += NBLK){
        int fm0 = (t & 31)*128;
        int fn0 = (t >> 5)*64;
        gemm_tile<A_LN, E_GELU>(smem, d_ret, Wr1, br1, d_t1, nullptr,
            d_s1, d_s2, ln1g, ln1b, nullptr, nullptr,
            nullptr, nullptr, fm0, fn0, NTOK, 2*DD, DD);
    }
    gbar();

    // Phase G
    gemm_tile<A_PLAIN, E_STAT>(smem, d_t1, Wr2, br2, d_t2, nullptr,
        nullptr, nullptr, nullptr, nullptr, d_s1b, d_s2b,
        nullptr, nullptr, m0, n0, NTOK, DD, 2*DD);
    gbar();

    // Phase H
    gemm_tile<A_LN, E_OUT>(smem, d_t2, Wo, bo, out, x,
        d_s1b, d_s2b, ln2g, ln2b, nullptr, nullptr,
        nullptr, nullptr, m0, n0, NTOK, DD, DD);
}

// ---------------- launch ----------------
extern "C" void kernel_launch(void* const* d_in, const int* in_sizes, int n_in,
                              void* d_out, int out_size)
{
    const float* x    = (const float*)d_in[0];
    const float* Wk   = (const float*)d_in[1];
    const float* bk   = (const float*)d_in[2];
    const float* Wv   = (const float*)d_in[3];
    const float* bv   = (const float*)d_in[4];
    const float* Wg1  = (const float*)d_in[5];
    const float* bg1  = (const float*)d_in[6];
    const float* Wg2  = (const float*)d_in[7];
    const float* bg2  = (const float*)d_in[8];
    const float* ln1g = (const float*)d_in[9];
    const float* ln1b = (const float*)d_in[10];
    const float* Wr1  = (const float*)d_in[11];
    const float* br1  = (const float*)d_in[12];
    const float* Wr2  = (const float*)d_in[13];
    const float* br2  = (const float*)d_in[14];
    const float* ln2g = (const float*)d_in[15];
    const float* ln2b = (const float*)d_in[16];
    const float* Wo   = (const float*)d_in[17];
    const float* bo   = (const float*)d_in[18];
    float* out = (float*)d_out;

    static bool init = false;
    if (!init){
        cudaFuncSetAttribute(mega_kernel, cudaFuncAttributeMaxDynamicSharedMemorySize, MEGA_SMEM);
        init = true;
    }

    mega_kernel<<<NBLK, NTHR, MEGA_SMEM>>>(
        x, Wk, bk, Wv, bv, Wg1, bg1, Wg2, bg2,
        ln1g, ln1b, Wr1, br1, Wr2, br2, ln2g, ln2b, Wo, bo, out);
    (void)in_sizes; (void)n_in; (void)out_size;
}

// round 13
// speedup vs baseline: 3.1884x; 1.0380x over previous
#include <cuda_runtime.h>
#include <math.h>
#include <stdint.h>

#define BB 2
#define LL 2048
#define DD 256
#define PP 32
#define NTOK (BB*LL)
#define NCH 16
#define CH 128
#define NBLK 128
#define NTHR 512

// ---------------- scratch ----------------
__device__ float d_cq[NTOK*PP];
__device__ float d_sq[NTOK*PP];
__device__ float d_g [NTOK];
__device__ float d_gc[NTOK];
__device__ float d_v [NTOK*DD];
__device__ float d_ret[NTOK*DD];
__device__ float d_t1[NTOK*2*DD];
__device__ float d_t2[NTOK*DD];
__device__ float d_state[BB*64*64*DD];
__device__ float d_pref [BB*NCH*64*DD];
__device__ float d_gpart[NTOK*8];
__device__ float d_s1 [8*NTOK];
__device__ float d_s2 [8*NTOK];
__device__ float d_s1b[8*NTOK];
__device__ float d_s2b[8*NTOK];

__device__ unsigned bar_cnt = 0;
__device__ unsigned bar_gen = 0;

__device__ __forceinline__ void gbar(){
    __syncthreads();
    __threadfence();
    if (threadIdx.x == 0){
        volatile unsigned* vg = &bar_gen;
        unsigned gen = *vg;
        unsigned t = atomicAdd(&bar_cnt, 1);
        if (t == gridDim.x - 1){
            atomicExch(&bar_cnt, 0);
            __threadfence();
            atomicAdd(&bar_gen, 1);
        } else {
            while (*vg == gen) { __nanosleep(32); }
        }
    }
    __syncthreads();
}

__device__ __forceinline__ float gelu_f(float x){
    return 0.5f*x*(1.0f+erff(x*0.7071067811865476f));
}
__device__ __forceinline__ float phasor(int b, int tok, int c){
    int t = b*LL + tok;
    return (c < 32) ? d_cq[t*PP + c] : d_sq[t*PP + c - 32];
}
__device__ __forceinline__ uint32_t f2tf(float f){
    uint32_t r; asm("cvt.rna.tf32.f32 %0, %1;" : "=r"(r) : "f"(f)); return r;
}
__device__ __forceinline__ uint32_t fb(float f){ return __float_as_uint(f); }
__device__ __forceinline__ float f2tf_as_f(float f){
    uint32_t r = f2tf(f); return __uint_as_float(r);
}
__device__ __forceinline__ void mma_tf32(float* c, const uint32_t* a, const uint32_t* b){
    asm volatile(
      "mma.sync.aligned.m16n8k8.row.col.f32.tf32.tf32.f32 "
      "{%0,%1,%2,%3}, {%4,%5,%6,%7}, {%8,%9}, {%0,%1,%2,%3};\n"
      : "+f"(c[0]), "+f"(c[1]), "+f"(c[2]), "+f"(c[3])
      : "r"(a[0]), "r"(a[1]), "r"(a[2]), "r"(a[3]), "r"(b[0]), "r"(b[1]));
}
__device__ __forceinline__ void ldsm4(uint32_t* r, uint32_t addr){
    asm volatile("ldmatrix.sync.aligned.m8n8.x4.shared.b16 {%0,%1,%2,%3}, [%4];\n"
        : "=r"(r[0]), "=r"(r[1]), "=r"(r[2]), "=r"(r[3]) : "r"(addr));
}
__device__ __forceinline__ uint32_t shaddr(const void* p){
    return (uint32_t)__cvta_generic_to_shared(p);
}
__device__ __forceinline__ uint32_t ldsm_off(int lane, int row0, int P){
    int t8 = lane >> 3, r8 = lane & 7;
    return (uint32_t)(((row0 + r8 + (t8 & 1)*8)*P + (t8 >> 1)*4) * 4);
}

__device__ __forceinline__ void cp16(uint32_t dst, const void* src, int sz){
    asm volatile("cp.async.cg.shared.global [%0], [%1], 16, %2;\n"
                 :: "r"(dst), "l"(src), "r"(sz));
}
__device__ __forceinline__ void cp_commit(){ asm volatile("cp.async.commit_group;\n"); }
__device__ __forceinline__ void cp_wait1(){ asm volatile("cp.async.wait_group 1;\n"); }

// ---------------- GEMM tile (512 threads, warps 8x2, 3-stage, ldmatrix A) ----------------
#define A_PLAIN  0
#define A_CONCAT 1
#define A_LN     2
#define E_NONE 0
#define E_GELU 1
#define E_OUT  3
#define E_GATE 4
#define E_STAT 5

#define APITCH 36
#define WPITCH 72

template<int AMODE, int EPI>
__device__ void gemm_tile(float* smem,
                 const float* __restrict__ A,
                 const float* __restrict__ W,
                 const float* __restrict__ bias,
                 float* __restrict__ C,
                 const float* __restrict__ extra,
                 const float* __restrict__ lnS1, const float* __restrict__ lnS2,
                 const float* __restrict__ lnG,  const float* __restrict__ lnB,
                 float* __restrict__ oS1, float* __restrict__ oS2,
                 const float* __restrict__ gw, float* __restrict__ gpart,
                 int m0, int n0, int M, int N, int K)
{
    float* Asm = smem;                       // 3 x 128*APITCH
    float* Wsm = smem + 3*128*APITCH;        // 3 x 32*WPITCH

    const int tid = threadIdx.x;
    const int wid = tid >> 5;
    const int lane = tid & 31;
    const int grp = lane >> 2;
    const int tig = lane & 3;
    const int wm = wid >> 1;
    const int wn = wid & 1;

    float acc[4][4];
    #pragma unroll
    for (int nt=0;nt<4;nt++)
        #pragma unroll
        for (int i=0;i<4;i++) acc[nt][i]=0.f;

    float4 areg[2]; float4 gv4, bv4;
    float mrow[2], rsrow[2];
    if (AMODE == A_LN){
        #pragma unroll
        for (int it=0; it<2; it++){
            int r = m0 + (tid>>3) + it*64;
            float sa = 0.f, sb = 0.f;
            #pragma unroll
            for (int s=0; s<8; s++){ sa += lnS1[s*NTOK + r]; sb += lnS2[s*NTOK + r]; }
            float mean = sa*(1.f/256.f);
            float var = fmaxf(sb*(1.f/256.f) - mean*mean, 0.f);
            mrow[it] = mean;
            rsrow[it] = rsqrtf(var + 1e-5f);
        }
    }

    auto ldA_regs = [&](int k0){
        int kq = (tid & 7)*4;
        gv4 = *(const float4*)&lnG[k0+kq];
        bv4 = *(const float4*)&lnB[k0+kq];
        #pragma unroll
        for (int it=0; it<2; it++){
            int r = m0 + (tid>>3) + it*64;
            areg[it] = *(const float4*)&A[(size_t)r*K + k0 + kq];
        }
    };
    auto stA = [&](int buf){
        float* As = Asm + buf*128*APITCH;
        int kq = (tid & 7)*4;
        #pragma unroll
        for (int it=0; it<2; it++){
            int row = (tid>>3) + it*64;
            float4 v = areg[it];
            v.x = (v.x - mrow[it])*rsrow[it]*gv4.x + bv4.x;
            v.y = (v.y - mrow[it])*rsrow[it]*gv4.y + bv4.y;
            v.z = (v.z - mrow[it])*rsrow[it]*gv4.z + bv4.z;
            v.w = (v.w - mrow[it])*rsrow[it]*gv4.w + bv4.w;
            *(float4*)&As[row*APITCH + kq] = v;
        }
    };

    auto load_tiles = [&](int buf, int k0){
        float* As = Asm + buf*128*APITCH;
        float* Ws = Wsm + buf*32*WPITCH;
        if (AMODE != A_LN){
            #pragma unroll
            for (int it = 0; it < 2; it++){
                int linear = tid + it*NTHR;
                int row = linear >> 3;
                int kq  = (linear & 7)*4;
                int m = m0 + row;
                int kg = k0 + kq;
                const float* src; int sz = 16;
                if (AMODE == A_PLAIN){
                    src = A + (size_t)m*K + kg;
                } else {
                    if (kg < DD) src = A + (size_t)m*DD + kg;
                    else {
                        int l = m & (LL-1);
                        if (l == 0){ sz = 0; src = A; }
                        else src = A + (size_t)(m-1)*DD + (kg-DD);
                    }
                }
                cp16((uint32_t)__cvta_generic_to_shared(&As[row*APITCH + kq]), src, sz);
            }
        }
        {
            int row = tid >> 4;
            int wnq = (tid & 15)*4;
            const float* src = W + (size_t)(k0+row)*N + n0 + wnq;
            cp16((uint32_t)__cvta_generic_to_shared(&Ws[row*WPITCH + wnq]), src, 16);
        }
    };

    const uint32_t aoff = ldsm_off(lane, wm*16, APITCH);

    const int ntiles = K >> 5;
    if (AMODE == A_LN) ldA_regs(0);
    load_tiles(0, 0);
    cp_commit();
    if (AMODE == A_LN) stA(0);
    if (AMODE == A_LN) ldA_regs(32);
    load_tiles(1, 32);
    cp_commit();
    if (AMODE == A_LN) stA(1);

    for (int kt = 0; kt < ntiles; kt++){
        int buf = kt % 3;
        cp_wait1();
        __syncthreads();

        if (kt+2 < ntiles){
            if (AMODE == A_LN) ldA_regs((kt+2)*32);
            load_tiles((kt+2)%3, (kt+2)*32);
        }
        cp_commit();

        const float* Ws = Wsm + buf*32*WPITCH;
        const uint32_t abase = shaddr(Asm + buf*128*APITCH) + aoff;
        #pragma unroll
        for (int ks = 0; ks < 32; ks += 8){
            uint32_t afr[4], bfr[4][2];
            ldsm4(afr, abase + ks*4);
            #pragma unroll
            for (int nt=0; nt<4; nt++){
                int cb = wn*32 + nt*8 + grp;
                bfr[nt][0] = fb(Ws[(ks + tig    )*WPITCH + cb]);
                bfr[nt][1] = fb(Ws[(ks + tig + 4)*WPITCH + cb]);
            }
            #pragma unroll
            for (int nt=0; nt<4; nt++)
                mma_tf32(acc[nt], afr, bfr[nt]);
        }
        if (AMODE == A_LN && kt+2 < ntiles) stA((kt+2)%3);
    }

    if (EPI == E_GATE){
        int slot = (n0 >> 6)*2 + wn;
        #pragma unroll
        for (int half=0; half<2; half++){
            int r = m0 + wm*16 + grp + half*8;
            float part = 0.f;
            #pragma unroll
            for (int nt=0; nt<4; nt++){
                int cb = n0 + wn*32 + nt*8 + 2*tig;
                float v0 = gelu_f(acc[nt][half*2+0] + bias[cb]);
                float v1 = gelu_f(acc[nt][half*2+1] + bias[cb+1]);
                part += v0*gw[cb] + v1*gw[cb+1];
            }
            part += __shfl_xor_sync(0xffffffffu, part, 1);
            part += __shfl_xor_sync(0xffffffffu, part, 2);
            if (tig == 0)
                gpart[(size_t)r*8 + slot] = part;
        }
        return;
    }

    #pragma unroll
    for (int half=0; half<2; half++){
        int r = m0 + wm*16 + grp + half*8;
        float s = 0.f, ss = 0.f;
        #pragma unroll
        for (int nt=0; nt<4; nt++){
            int cb = n0 + wn*32 + nt*8 + 2*tig;
            float v0 = acc[nt][half*2+0] + bias[cb];
            float v1 = acc[nt][half*2+1] + bias[cb+1];
            if (EPI == E_GELU){ v0 = gelu_f(v0); v1 = gelu_f(v1); }
            if (EPI == E_OUT) { v0 += extra[(size_t)r*DD + cb];
                                v1 += extra[(size_t)r*DD + cb + 1]; }
            if (EPI == E_STAT){ s += v0 + v1; ss += v0*v0 + v1*v1; }
            *(float2*)&C[(size_t)r*N + cb] = make_float2(v0, v1);
        }
        if (EPI == E_STAT){
            s  += __shfl_xor_sync(0xffffffffu, s, 1);
            s  += __shfl_xor_sync(0xffffffffu, s, 2);
            ss += __shfl_xor_sync(0xffffffffu, ss, 1);
            ss += __shfl_xor_sync(0xffffffffu, ss, 2);
            if (tig == 0){
                int slot = (n0 >> 6)*2 + wn;
                oS1[slot*NTOK + r] = s;
                oS2[slot*NTOK + r] = ss;
            }
        }
    }
}

// ---------------- dual-N GEMM for phase F: A_LN + E_GELU, N=512, strips n0 and n0+256 ----------------
__device__ void gemm_tile_f(float* smem,
                 const float* __restrict__ A,
                 const float* __restrict__ W,
                 const float* __restrict__ bias,
                 float* __restrict__ C,
                 const float* __restrict__ lnS1, const float* __restrict__ lnS2,
                 const float* __restrict__ lnG,  const float* __restrict__ lnB,
                 int m0, int n0)
{
    const int N = 2*DD, K = DD;
    float* Asm = smem;                         // 3 x 128*APITCH
    float* Wsm = smem + 3*128*APITCH;          // 3 x 2 x 32*WPITCH

    const int tid = threadIdx.x;
    const int wid = tid >> 5;
    const int lane = tid & 31;
    const int grp = lane >> 2;
    const int tig = lane & 3;
    const int wm = wid >> 1;
    const int wn = wid & 1;

    float acc[2][4][4];
    #pragma unroll
    for (int h=0;h<2;h++)
        #pragma unroll
        for (int nt=0;nt<4;nt++)
            #pragma unroll
            for (int i=0;i<4;i++) acc[h][nt][i]=0.f;

    float4 areg[2]; float4 gv4, bv4;
    float mrow[2], rsrow[2];
    #pragma unroll
    for (int it=0; it<2; it++){
        int r = m0 + (tid>>3) + it*64;
        float sa = 0.f, sb = 0.f;
        #pragma unroll
        for (int s=0; s<8; s++){ sa += lnS1[s*NTOK + r]; sb += lnS2[s*NTOK + r]; }
        float mean = sa*(1.f/256.f);
        float var = fmaxf(sb*(1.f/256.f) - mean*mean, 0.f);
        mrow[it] = mean;
        rsrow[it] = rsqrtf(var + 1e-5f);
    }

    auto ldA_regs = [&](int k0){
        int kq = (tid & 7)*4;
        gv4 = *(const float4*)&lnG[k0+kq];
        bv4 = *(const float4*)&lnB[k0+kq];
        #pragma unroll
        for (int it=0; it<2; it++){
            int r = m0 + (tid>>3) + it*64;
            areg[it] = *(const float4*)&A[(size_t)r*K + k0 + kq];
        }
    };
    auto stA = [&](int buf){
        float* As = Asm + buf*128*APITCH;
        int kq = (tid & 7)*4;
        #pragma unroll
        for (int it=0; it<2; it++){
            int row = (tid>>3) + it*64;
            float4 v = areg[it];
            v.x = (v.x - mrow[it])*rsrow[it]*gv4.x + bv4.x;
            v.y = (v.y - mrow[it])*rsrow[it]*gv4.y + bv4.y;
            v.z = (v.z - mrow[it])*rsrow[it]*gv4.z + bv4.z;
            v.w = (v.w - mrow[it])*rsrow[it]*gv4.w + bv4.w;
            *(float4*)&As[row*APITCH + kq] = v;
        }
    };
    auto load_W = [&](int buf, int k0){
        float* Ws = Wsm + buf*2*32*WPITCH;
        int row = tid >> 4;
        int wnq = (tid & 15)*4;
        #pragma unroll
        for (int h = 0; h < 2; h++){
            const float* src = W + (size_t)(k0+row)*N + n0 + h*256 + wnq;
            cp16((uint32_t)__cvta_generic_to_shared(&Ws[h*32*WPITCH + row*WPITCH + wnq]), src, 16);
        }
    };

    const uint32_t aoff = ldsm_off(lane, wm*16, APITCH);
    const int ntiles = K >> 5;   // 8
    ldA_regs(0); load_W(0, 0); cp_commit(); stA(0);
    ldA_regs(32); load_W(1, 32); cp_commit(); stA(1);

    for (int kt = 0; kt < ntiles; kt++){
        int buf = kt % 3;
        cp_wait1();
        __syncthreads();
        if (kt+2 < ntiles){ ldA_regs((kt+2)*32); load_W((kt+2)%3, (kt+2)*32); }
        cp_commit();

        const float* Ws = Wsm + buf*2*32*WPITCH;
        const uint32_t abase = shaddr(Asm + buf*128*APITCH) + aoff;
        #pragma unroll
        for (int ks = 0; ks < 32; ks += 8){
            uint32_t afr[4];
            ldsm4(afr, abase + ks*4);
            #pragma unroll
            for (int h=0; h<2; h++){
                const float* Wh = Ws + h*32*WPITCH;
                #pragma unroll
                for (int nt=0; nt<4; nt++){
                    uint32_t bfr[2];
                    int cb = wn*32 + nt*8 + grp;
                    bfr[0] = fb(Wh[(ks + tig    )*WPITCH + cb]);
                    bfr[1] = fb(Wh[(ks + tig + 4)*WPITCH + cb]);
                    mma_tf32(acc[h][nt], afr, bfr);
                }
            }
        }
        if (kt+2 < ntiles) stA((kt+2)%3);
    }

    #pragma unroll
    for (int h=0; h<2; h++){
        #pragma unroll
        for (int half=0; half<2; half++){
            int r = m0 + wm*16 + grp + half*8;
            #pragma unroll
            for (int nt=0; nt<4; nt++){
                int cb = n0 + h*256 + wn*32 + nt*8 + 2*tig;
                float v0 = gelu_f(acc[h][nt][half*2+0] + bias[cb]);
                float v1 = gelu_f(acc[h][nt][half*2+1] + bias[cb+1]);
                *(float2*)&C[(size_t)r*N + cb] = make_float2(v0, v1);
            }
        }
    }
}

// ---------------- phases job: smem-staged ----------------
__device__ void phases_job(int blk, const float* __restrict__ x,
                           const float* __restrict__ Wk,
                           const float* __restrict__ bk,
                           float* smem){
    __syncthreads();
    float* xs = smem;              // 32 x 256
    float* wk = smem + 32*256;     // 256 x 32
    const int tid = threadIdx.x;
    const int rowbase = blk*32;
    for (int i = tid; i < 32*64; i += NTHR){
        int r = i >> 6, c4 = (i & 63)*4;
        *(float4*)&xs[r*256 + c4] = *(const float4*)&x[(size_t)(rowbase+r)*DD + c4];
    }
    for (int i = tid; i < 2048; i += NTHR){
        *(float4*)&wk[i*4] = *(const float4*)&Wk[i*4];
    }
    __syncthreads();
    int w = tid >> 5, p = tid & 31;
    int t0 = 2*w;
    float bkp = bk[p];
    float s0 = bkp, s1 = bkp;
    #pragma unroll 16
    for (int k = 0; k < 256; k++){
        float wv = wk[k*32 + p];
        s0 += xs[t0*256 + k]*wv;
        s1 += xs[(t0+1)*256 + k]*wv;
    }
    const float PI = 3.14159265358979323846f;
    float sn, cs;
    sincosf(tanhf(s0)*PI, &sn, &cs); d_cq[(rowbase+t0  )*PP+p]=cs; d_sq[(rowbase+t0  )*PP+p]=sn;
    sincosf(tanhf(s1)*PI, &sn, &cs); d_cq[(rowbase+t0+1)*PP+p]=cs; d_sq[(rowbase+t0+1)*PP+p]=sn;
}

// ---------------- gate finalize + scan ----------------
__device__ void cumsum_job(int b, const float* __restrict__ bg2, float* smem){
    int tid = threadIdx.x;
    int lane = tid & 31, warp = tid >> 5;
    float* wtot = smem;
    float bv = bg2[0];
    float v[4]; float run = 0.f;
    #pragma unroll
    for (int i=0;i<4;i++){
        int tok = b*LL + tid*4 + i;
        float4 a = *(const float4*)&d_gpart[(size_t)tok*8];
        float4 c = *(const float4*)&d_gpart[(size_t)tok*8 + 4];
        float s = bv + a.x+a.y+a.z+a.w + c.x+c.y+c.z+c.w;
        float g = 1.f/(1.f + expf(-s));
        d_g[tok] = g;
        run += g; v[i] = run;
    }
    float x = run;
    #pragma unroll
    for (int o=1;o<32;o<<=1){
        float y = __shfl_up_sync(0xffffffffu, x, o);
        if (lane >= o) x += y;
    }
    if (lane == 31) wtot[warp] = x;
    __syncthreads();
    if (warp == 0 && lane < 16){
        float t = wtot[lane];
        #pragma unroll
        for (int o=1;o<16;o<<=1){
            float z = __shfl_up_sync(0xffffu, t, o);
            if (lane >= o) t += z;
        }
        wtot[lane] = t;
    }
    __syncthreads();
    float off = (x - run) + (warp ? wtot[warp-1] : 0.f);
    float* gc = d_gc + b*LL + tid*4;
    #pragma unroll
    for (int i=0;i<4;i++) gc[i] = v[i] + off;
}

// ---------------- chunk state slice (computes g locally from gpart) ----------------
__device__ void chunk_state_job(int cc, int b, int tile, const float* __restrict__ bg2,
                                float* smem){
    float* sA = smem;            // 64*36
    float* sB = sA + 64*36;      // 32*264
    float* sg = sB + 32*264;     // 32
    const int tid = threadIdx.x;
    const int wid = tid >> 5, lane = tid & 31;
    const int grp = lane >> 2, tig = lane & 3;
    const int wm = wid >> 3;
    const int wn = wid & 7;

    int t0 = cc*CH + tile*32;
    if (tid < 32){
        int tok = b*LL + t0 + tid;
        float4 a = *(const float4*)&d_gpart[(size_t)tok*8];
        float4 c = *(const float4*)&d_gpart[(size_t)tok*8 + 4];
        float s = bg2[0] + a.x+a.y+a.z+a.w + c.x+c.y+c.z+c.w;
        sg[tid] = 1.f/(1.f + expf(-s));
    }

    float acc[2][4][4];
    #pragma unroll
    for (int mt=0;mt<2;mt++)
        #pragma unroll
        for (int nt=0;nt<4;nt++)
            #pragma unroll
            for (int i=0;i<4;i++) acc[mt][nt][i]=0.f;

    for (int i = tid; i < 64*32; i += NTHR){
        int p = i>>5, t = i&31;
        int gt = t0 + t;
        sA[p*36 + t] = (gt >= 1) ? f2tf_as_f(phasor(b, gt-1, p)) : 0.f;
    }
    __syncthreads();   // sg visible; sA done
    for (int i = tid; i < 32*64; i += NTHR){
        int t = i>>6, c4 = (i&63)*4;
        float gv = sg[t];
        float4 v = *(const float4*)&d_v[((size_t)(b*LL + t0 + t))*DD + c4];
        v.x = f2tf_as_f(v.x*gv); v.y = f2tf_as_f(v.y*gv);
        v.z = f2tf_as_f(v.z*gv); v.w = f2tf_as_f(v.w*gv);
        *(float4*)&sB[t*264 + c4] = v;
    }
    __syncthreads();
    const uint32_t abase = shaddr(sA) + ldsm_off(lane, wm*32, 36);
    #pragma unroll
    for (int ks = 0; ks < 32; ks += 8){
        uint32_t afr[2][4], bfr[4][2];
        #pragma unroll
        for (int mt=0; mt<2; mt++)
            ldsm4(afr[mt], abase + (mt*16*36 + ks)*4);
        #pragma unroll
        for (int nt=0; nt<4; nt++){
            int cb = wn*32 + nt*8 + grp;
            bfr[nt][0] = fb(sB[(ks + tig    )*264 + cb]);
            bfr[nt][1] = fb(sB[(ks + tig + 4)*264 + cb]);
        }
        #pragma unroll
        for (int mt=0; mt<2; mt++)
            #pragma unroll
            for (int nt=0; nt<4; nt++)
                mma_tf32(acc[mt][nt], afr[mt], bfr[nt]);
    }
    __syncthreads();
    size_t base = ((size_t)(b*64 + cc*4 + tile))*64*DD;
    #pragma unroll
    for (int mt=0; mt<2; mt++)
        #pragma unroll
        for (int nt=0; nt<4; nt++)
            #pragma unroll
            for (int half=0; half<2; half++){
                int row = wm*32 + mt*16 + grp + half*8;
                int col = wn*32 + nt*8 + 2*tig;
                *(float2*)&d_state[base + (size_t)row*DD + col] =
                    make_float2(acc[mt][nt][half*2], acc[mt][nt][half*2+1]);
            }
}

// ---------------- chunk prefix over 64 slices ----------------
__device__ void chunk_prefix_job(int b, int gs){
    int off = gs*2048 + threadIdx.x*4;
    float4 run = make_float4(0.f,0.f,0.f,0.f);
    #pragma unroll 8
    for (int c = 0; c < 64; c++){
        size_t base = ((size_t)(b*64 + c))*16384 + off;
        float4 v = *(const float4*)&d_state[base];
        if ((c & 3) == 0){
            size_t pb = ((size_t)(b*NCH + (c>>2)))*16384 + off;
            *(float4*)&d_pref[pb] = run;
        }
        run.x += v.x; run.y += v.y; run.z += v.z; run.w += v.w;
    }
}

// ---------------- chunk out ----------------
__device__ void chunk_out_job(int cc, int ds, int b, float* sm){
    float* sQ  = sm;
    float* sKT = sQ + 128*68;
    float* sS  = sKT + 64*136;
    float* sV  = sS + 128*132;
    float* sP  = sV + 128*72;
    const int tid = threadIdx.x;
    const int wid = tid >> 5, lane = tid & 31;
    const int grp = lane >> 2, tig = lane & 3;

    for (int i = tid; i < CH*64; i += NTHR){
        int r = i>>6, c = i&63;
        sQ[r*68 + c] = f2tf_as_f(phasor(b, cc*CH + r, c));
    }
    for (int i = tid; i < CH*64; i += NTHR){
        int t = i>>6, c = i&63;
        int gt = cc*CH + t;
        sKT[c*136 + t] = (gt >= 1) ? f2tf_as_f(phasor(b, gt-1, c)) : 0.f;
    }
    for (int i = tid; i < 128*16; i += NTHR){
        int t = i>>4, c4 = (i&15)*4;
        float gv = d_g[b*LL + cc*CH + t];
        float4 v = *(const float4*)&d_v[((size_t)(b*LL + cc*CH + t))*DD + ds*64 + c4];
        v.x = f2tf_as_f(v.x*gv); v.y = f2tf_as_f(v.y*gv);
        v.z = f2tf_as_f(v.z*gv); v.w = f2tf_as_f(v.w*gv);
        *(float4*)&sV[t*72 + c4] = v;
    }
    size_t pbase = ((size_t)(b*NCH + cc))*64*DD;
    for (int i = tid; i < 64*16; i += NTHR){
        int p = i>>4, c4 = (i&15)*4;
        float4 v = *(const float4*)&d_pref[pbase + (size_t)p*DD + ds*64 + c4];
        v.x = f2tf_as_f(v.x); v.y = f2tf_as_f(v.y);
        v.z = f2tf_as_f(v.z); v.w = f2tf_as_f(v.w);
        *(float4*)&sP[p*72 + c4] = v;
    }
    __syncthreads();

    // scores: 16 warps, 4x4 layout
    {
        const int wm = wid >> 2;
        const int wn = wid & 3;
        float acc2[2][4][4];
        #pragma unroll
        for (int mt=0;mt<2;mt++)
            #pragma unroll
            for (int nt=0;nt<4;nt++)
                #pragma unroll
                for (int i=0;i<4;i++) acc2[mt][nt][i]=0.f;
        const uint32_t qbase = shaddr(sQ) + ldsm_off(lane, wm*32, 68);
        #pragma unroll
        for (int ks = 0; ks < 64; ks += 8){
            uint32_t afr[2][4], bfr[4][2];
            #pragma unroll
            for (int mt=0; mt<2; mt++)
                ldsm4(afr[mt], qbase + (mt*16*68 + ks)*4);
            #pragma unroll
            for (int nt=0; nt<4; nt++){
                int cb = wn*32 + nt*8 + grp;
                bfr[nt][0] = fb(sKT[(ks + tig    )*136 + cb]);
                bfr[nt][1] = fb(sKT[(ks + tig + 4)*136 + cb]);
            }
            #pragma unroll
            for (int mt=0; mt<2; mt++)
                #pragma unroll
                for (int nt=0; nt<4; nt++)
                    mma_tf32(acc2[mt][nt], afr[mt], bfr[nt]);
        }
        #pragma unroll
        for (int mt=0; mt<2; mt++)
            #pragma unroll
            for (int nt=0; nt<4; nt++)
                #pragma unroll
                for (int half=0; half<2; half++){
                    int row = wm*32 + mt*16 + grp + half*8;
                    int col = wn*32 + nt*8 + 2*tig;
                    sS[row*132 + col    ] = (col   <= row) ? acc2[mt][nt][half*2  ] : 0.f;
                    sS[row*132 + col + 1] = (col+1 <= row) ? acc2[mt][nt][half*2+1] : 0.f;
                }
    }
    __syncthreads();

    // out: 16 warps, 8x2 layout
    const int wm = wid >> 1;
    const int wn = wid & 1;
    float acc[4][4];
    #pragma unroll
    for (int nt=0;nt<4;nt++)
        #pragma unroll
        for (int i=0;i<4;i++) acc[nt][i]=0.f;

    const uint32_t sbase = shaddr(sS) + ldsm_off(lane, wm*16, 132);
    #pragma unroll 4
    for (int ks = 0; ks < 128; ks += 8){
        uint32_t afr[4], bfr[4][2];
        ldsm4(afr, sbase + ks*4);
        #pragma unroll
        for (int nt=0; nt<4; nt++){
            int cb = wn*32 + nt*8 + grp;
            bfr[nt][0] = fb(sV[(ks + tig    )*72 + cb]);
            bfr[nt][1] = fb(sV[(ks + tig + 4)*72 + cb]);
        }
        #pragma unroll
        for (int nt=0; nt<4; nt++)
            mma_tf32(acc[nt], afr, bfr[nt]);
    }
    const uint32_t qb2 = shaddr(sQ) + ldsm_off(lane, wm*16, 68);
    #pragma unroll
    for (int ks = 0; ks < 64; ks += 8){
        uint32_t afr[4], bfr[4][2];
        ldsm4(afr, qb2 + ks*4);
        #pragma unroll
        for (int nt=0; nt<4; nt++){
            int cb = wn*32 + nt*8 + grp;
            bfr[nt][0] = fb(sP[(ks + tig    )*72 + cb]);
            bfr[nt][1] = fb(sP[(ks + tig + 4)*72 + cb]);
        }
        #pragma unroll
        for (int nt=0; nt<4; nt++)
            mma_tf32(acc[nt], afr, bfr[nt]);
    }

    int slot = ds*2 + wn;
    #pragma unroll
    for (int half=0; half<2; half++){
        int rloc = wm*16 + grp + half*8;
        int gtok = b*LL + cc*CH + rloc;
        float sc = rsqrtf(fmaxf(d_gc[gtok], 1.f)) * 0.17677669529663687f;
        float s = 0.f, ss = 0.f;
        #pragma unroll
        for (int nt=0; nt<4; nt++){
            int col = wn*32 + nt*8 + 2*tig;
            float v0 = acc[nt][half*2+0]*sc;
            float v1 = acc[nt][half*2+1]*sc;
            *(float2*)&d_ret[(size_t)gtok*DD + ds*64 + col] = make_float2(v0, v1);
            s += v0 + v1; ss += v0*v0 + v1*v1;
        }
        s  += __shfl_xor_sync(0xffffffffu, s, 1);
        s  += __shfl_xor_sync(0xffffffffu, s, 2);
        ss += __shfl_xor_sync(0xffffffffu, ss, 1);
        ss += __shfl_xor_sync(0xffffffffu, ss, 2);
        if (tig == 0){
            d_s1[slot*NTOK + gtok] = s;
            d_s2[slot*NTOK + gtok] = ss;
        }
    }
}

// ---------------- mega kernel ----------------
#define MEGA_SMEM ((128*68 + 64*136 + 128*132 + 128*72 + 64*72)*(int)sizeof(float))

__global__ void __launch_bounds__(NTHR, 1)
mega_kernel(const float* __restrict__ x,
            const float* __restrict__ Wk,  const float* __restrict__ bk,
            const float* __restrict__ Wv,  const float* __restrict__ bv,
            const float* __restrict__ Wg1, const float* __restrict__ bg1,
            const float* __restrict__ Wg2, const float* __restrict__ bg2,
            const float* __restrict__ ln1g,const float* __restrict__ ln1b,
            const float* __restrict__ Wr1, const float* __restrict__ br1,
            const float* __restrict__ Wr2, const float* __restrict__ br2,
            const float* __restrict__ ln2g,const float* __restrict__ ln2b,
            const float* __restrict__ Wo,  const float* __restrict__ bo,
            float* __restrict__ out)
{
    extern __shared__ __align__(16) float smem[];
    const int blk = blockIdx.x;
    const int m0 = (blk & 31)*128;
    const int n0 = (blk >> 5)*64;

    // Phase A
    gemm_tile<A_CONCAT, E_GATE>(smem, x, Wg1, bg1, nullptr, nullptr,
        nullptr, nullptr, nullptr, nullptr, nullptr, nullptr,
        Wg2, d_gpart, m0, n0, NTOK, DD, 2*DD);
    gemm_tile<A_PLAIN, E_NONE>(smem, x, Wv, bv, d_v, nullptr,
        nullptr, nullptr, nullptr, nullptr, nullptr, nullptr,
        nullptr, nullptr, m0, n0, NTOK, DD, DD);
    phases_job(blk, x, Wk, bk, smem);
    gbar();

    // Phase B||C: blocks 0-1 run the scan; all blocks compute states with local g
    if (blk < BB) cumsum_job(blk, bg2, smem);
    __syncthreads();
    chunk_state_job((blk >> 2) & 15, blk >> 6, blk & 3, bg2, smem);
    gbar();

    // Phase D
    if (blk < 16) chunk_prefix_job(blk >> 3, blk & 7);
    gbar();

    // Phase E
    chunk_out_job((blk >> 2) & 15, blk & 3, blk >> 6, smem);
    gbar();

    // Phase F: dual-N fused (one K pass, A LN'd once)
    gemm_tile_f(smem, d_ret, Wr1, br1, d_t1,
        d_s1, d_s2, ln1g, ln1b, m0, n0);
    gbar();

    // Phase G
    gemm_tile<A_PLAIN, E_STAT>(smem, d_t1, Wr2, br2, d_t2, nullptr,
        nullptr, nullptr, nullptr, nullptr, d_s1b, d_s2b,
        nullptr, nullptr, m0, n0, NTOK, DD, 2*DD);
    gbar();

    // Phase H
    gemm_tile<A_LN, E_OUT>(smem, d_t2, Wo, bo, out, x,
        d_s1b, d_s2b, ln2g, ln2b, nullptr, nullptr,
        nullptr, nullptr, m0, n0, NTOK, DD, DD);
}

// ---------------- launch ----------------
extern "C" void kernel_launch(void* const* d_in, const int* in_sizes, int n_in,
                              void* d_out, int out_size)
{
    const float* x    = (const float*)d_in[0];
    const float* Wk   = (const float*)d_in[1];
    const float* bk   = (const float*)d_in[2];
    const float* Wv   = (const float*)d_in[3];
    const float* bv   = (const float*)d_in[4];
    const float* Wg1  = (const float*)d_in[5];
    const float* bg1  = (const float*)d_in[6];
    const float* Wg2  = (const float*)d_in[7];
    const float* bg2  = (const float*)d_in[8];
    const float* ln1g = (const float*)d_in[9];
    const float* ln1b = (const float*)d_in[10];
    const float* Wr1  = (const float*)d_in[11];
    const float* br1  = (const float*)d_in[12];
    const float* Wr2  = (const float*)d_in[13];
    const float* br2  = (const float*)d_in[14];
    const float* ln2g = (const float*)d_in[15];
    const float* ln2b = (const float*)d_in[16];
    const float* Wo   = (const float*)d_in[17];
    const float* bo   = (const float*)d_in[18];
    float* out = (float*)d_out;

    static bool init = false;
    if (!init){
        cudaFuncSetAttribute(mega_kernel, cudaFuncAttributeMaxDynamicSharedMemorySize, MEGA_SMEM);
        init = true;
    }

    mega_kernel<<<NBLK, NTHR, MEGA_SMEM>>>(
        x, Wk, bk, Wv, bv, Wg1, bg1, Wg2, bg2,
        ln1g, ln1b, Wr1, br1, Wr2, br2, ln2g, ln2b, Wo, bo, out);
    (void)in_sizes; (void)n_in; (void)out_size;
}

// round 15
// speedup vs baseline: 3.2342x; 1.0144x over previous
#include <cuda_runtime.h>
#include <math.h>
#include <stdint.h>

#define BB 2
#define LL 2048
#define DD 256
#define PP 32
#define NTOK (BB*LL)
#define NCH 16
#define CH 128
#define NBLK 128
#define NTHR 512

// ---------------- scratch ----------------
__device__ float d_cq[NTOK*PP];
__device__ float d_sq[NTOK*PP];
__device__ float d_g [NTOK];
__device__ float d_gc[NTOK];
__device__ float d_v [NTOK*DD];
__device__ float d_ret[NTOK*DD];
__device__ float d_t1[NTOK*2*DD];
__device__ float d_t2[NTOK*DD];
__device__ float d_state[BB*64*64*DD];
__device__ float d_pref [BB*NCH*64*DD];
__device__ float d_gpart[NTOK*8];
__device__ float d_s1 [8*NTOK];
__device__ float d_s2 [8*NTOK];
__device__ float d_s1b[8*NTOK];
__device__ float d_s2b[8*NTOK];

__device__ unsigned bar_cnt = 0;
__device__ unsigned bar_gen = 0;

__device__ __forceinline__ void gbar(){
    __syncthreads();
    __threadfence();
    if (threadIdx.x == 0){
        volatile unsigned* vg = &bar_gen;
        unsigned gen = *vg;
        unsigned t = atomicAdd(&bar_cnt, 1);
        if (t == gridDim.x - 1){
            atomicExch(&bar_cnt, 0);
            __threadfence();
            atomicAdd(&bar_gen, 1);
        } else {
            while (*vg == gen) { __nanosleep(32); }
        }
    }
    __syncthreads();
}

__device__ __forceinline__ float gelu_f(float x){
    return 0.5f*x*(1.0f+erff(x*0.7071067811865476f));
}
__device__ __forceinline__ float phasor(int b, int tok, int c){
    int t = b*LL + tok;
    return (c < 32) ? d_cq[t*PP + c] : d_sq[t*PP + c - 32];
}
__device__ __forceinline__ uint32_t f2tf(float f){
    uint32_t r; asm("cvt.rna.tf32.f32 %0, %1;" : "=r"(r) : "f"(f)); return r;
}
__device__ __forceinline__ uint32_t fb(float f){ return __float_as_uint(f); }
__device__ __forceinline__ float f2tf_as_f(float f){
    uint32_t r = f2tf(f); return __uint_as_float(r);
}
__device__ __forceinline__ void mma_tf32(float* c, const uint32_t* a, const uint32_t* b){
    asm volatile(
      "mma.sync.aligned.m16n8k8.row.col.f32.tf32.tf32.f32 "
      "{%0,%1,%2,%3}, {%4,%5,%6,%7}, {%8,%9}, {%0,%1,%2,%3};\n"
      : "+f"(c[0]), "+f"(c[1]), "+f"(c[2]), "+f"(c[3])
      : "r"(a[0]), "r"(a[1]), "r"(a[2]), "r"(a[3]), "r"(b[0]), "r"(b[1]));
}
__device__ __forceinline__ void ldsm4(uint32_t* r, uint32_t addr){
    asm volatile("ldmatrix.sync.aligned.m8n8.x4.shared.b16 {%0,%1,%2,%3}, [%4];\n"
        : "=r"(r[0]), "=r"(r[1]), "=r"(r[2]), "=r"(r[3]) : "r"(addr));
}
__device__ __forceinline__ uint32_t shaddr(const void* p){
    return (uint32_t)__cvta_generic_to_shared(p);
}
__device__ __forceinline__ uint32_t ldsm_off(int lane, int row0, int P){
    int t8 = lane >> 3, r8 = lane & 7;
    return (uint32_t)(((row0 + r8 + (t8 & 1)*8)*P + (t8 >> 1)*4) * 4);
}

__device__ __forceinline__ void cp16(uint32_t dst, const void* src, int sz){
    asm volatile("cp.async.cg.shared.global [%0], [%1], 16, %2;\n"
                 :: "r"(dst), "l"(src), "r"(sz));
}
__device__ __forceinline__ void cp_commit(){ asm volatile("cp.async.commit_group;\n"); }
__device__ __forceinline__ void cp_wait1(){ asm volatile("cp.async.wait_group 1;\n"); }

#define A_PLAIN  0
#define A_CONCAT 1
#define A_LN     2
#define E_NONE 0
#define E_GELU 1
#define E_OUT  3
#define E_GATE 4
#define E_STAT 5

#define APITCH 36
#define WPITCH 72

// ---------------- generic GEMM tile (used for phases G, H) ----------------
template<int AMODE, int EPI>
__device__ void gemm_tile(float* smem,
                 const float* __restrict__ A,
                 const float* __restrict__ W,
                 const float* __restrict__ bias,
                 float* __restrict__ C,
                 const float* __restrict__ extra,
                 const float* __restrict__ lnS1, const float* __restrict__ lnS2,
                 const float* __restrict__ lnG,  const float* __restrict__ lnB,
                 float* __restrict__ oS1, float* __restrict__ oS2,
                 int m0, int n0, int M, int N, int K)
{
    float* Asm = smem;                       // 3 x 128*APITCH
    float* Wsm = smem + 3*128*APITCH;        // 3 x 32*WPITCH

    const int tid = threadIdx.x;
    const int wid = tid >> 5;
    const int lane = tid & 31;
    const int grp = lane >> 2;
    const int tig = lane & 3;
    const int wm = wid >> 1;
    const int wn = wid & 1;

    float acc[4][4];
    #pragma unroll
    for (int nt=0;nt<4;nt++)
        #pragma unroll
        for (int i=0;i<4;i++) acc[nt][i]=0.f;

    float4 areg[2]; float4 gv4, bv4;
    float mrow[2], rsrow[2];
    if (AMODE == A_LN){
        #pragma unroll
        for (int it=0; it<2; it++){
            int r = m0 + (tid>>3) + it*64;
            float sa = 0.f, sb = 0.f;
            #pragma unroll
            for (int s=0; s<8; s++){ sa += lnS1[s*NTOK + r]; sb += lnS2[s*NTOK + r]; }
            float mean = sa*(1.f/256.f);
            float var = fmaxf(sb*(1.f/256.f) - mean*mean, 0.f);
            mrow[it] = mean;
            rsrow[it] = rsqrtf(var + 1e-5f);
        }
    }

    auto ldA_regs = [&](int k0){
        int kq = (tid & 7)*4;
        gv4 = *(const float4*)&lnG[k0+kq];
        bv4 = *(const float4*)&lnB[k0+kq];
        #pragma unroll
        for (int it=0; it<2; it++){
            int r = m0 + (tid>>3) + it*64;
            areg[it] = *(const float4*)&A[(size_t)r*K + k0 + kq];
        }
    };
    auto stA = [&](int buf){
        float* As = Asm + buf*128*APITCH;
        int kq = (tid & 7)*4;
        #pragma unroll
        for (int it=0; it<2; it++){
            int row = (tid>>3) + it*64;
            float4 v = areg[it];
            v.x = (v.x - mrow[it])*rsrow[it]*gv4.x + bv4.x;
            v.y = (v.y - mrow[it])*rsrow[it]*gv4.y + bv4.y;
            v.z = (v.z - mrow[it])*rsrow[it]*gv4.z + bv4.z;
            v.w = (v.w - mrow[it])*rsrow[it]*gv4.w + bv4.w;
            *(float4*)&As[row*APITCH + kq] = v;
        }
    };

    auto load_tiles = [&](int buf, int k0){
        float* As = Asm + buf*128*APITCH;
        float* Ws = Wsm + buf*32*WPITCH;
        if (AMODE != A_LN){
            #pragma unroll
            for (int it = 0; it < 2; it++){
                int linear = tid + it*NTHR;
                int row = linear >> 3;
                int kq  = (linear & 7)*4;
                int m = m0 + row;
                int kg = k0 + kq;
                const float* src = A + (size_t)m*K + kg;
                cp16((uint32_t)__cvta_generic_to_shared(&As[row*APITCH + kq]), src, 16);
            }
        }
        {
            int row = tid >> 4;
            int wnq = (tid & 15)*4;
            const float* src = W + (size_t)(k0+row)*N + n0 + wnq;
            cp16((uint32_t)__cvta_generic_to_shared(&Ws[row*WPITCH + wnq]), src, 16);
        }
    };

    const uint32_t aoff = ldsm_off(lane, wm*16, APITCH);

    const int ntiles = K >> 5;
    if (AMODE == A_LN) ldA_regs(0);
    load_tiles(0, 0);
    cp_commit();
    if (AMODE == A_LN) stA(0);
    if (AMODE == A_LN) ldA_regs(32);
    load_tiles(1, 32);
    cp_commit();
    if (AMODE == A_LN) stA(1);

    for (int kt = 0; kt < ntiles; kt++){
        int buf = kt % 3;
        cp_wait1();
        __syncthreads();

        if (kt+2 < ntiles){
            if (AMODE == A_LN) ldA_regs((kt+2)*32);
            load_tiles((kt+2)%3, (kt+2)*32);
        }
        cp_commit();

        const float* Ws = Wsm + buf*32*WPITCH;
        const uint32_t abase = shaddr(Asm + buf*128*APITCH) + aoff;
        #pragma unroll
        for (int ks = 0; ks < 32; ks += 8){
            uint32_t afr[4], bfr[4][2];
            ldsm4(afr, abase + ks*4);
            #pragma unroll
            for (int nt=0; nt<4; nt++){
                int cb = wn*32 + nt*8 + grp;
                bfr[nt][0] = fb(Ws[(ks + tig    )*WPITCH + cb]);
                bfr[nt][1] = fb(Ws[(ks + tig + 4)*WPITCH + cb]);
            }
            #pragma unroll
            for (int nt=0; nt<4; nt++)
                mma_tf32(acc[nt], afr, bfr[nt]);
        }
        if (AMODE == A_LN && kt+2 < ntiles) stA((kt+2)%3);
    }

    #pragma unroll
    for (int half=0; half<2; half++){
        int r = m0 + wm*16 + grp + half*8;
        float s = 0.f, ss = 0.f;
        #pragma unroll
        for (int nt=0; nt<4; nt++){
            int cb = n0 + wn*32 + nt*8 + 2*tig;
            float v0 = acc[nt][half*2+0] + bias[cb];
            float v1 = acc[nt][half*2+1] + bias[cb+1];
            if (EPI == E_GELU){ v0 = gelu_f(v0); v1 = gelu_f(v1); }
            if (EPI == E_OUT) { v0 += extra[(size_t)r*DD + cb];
                                v1 += extra[(size_t)r*DD + cb + 1]; }
            if (EPI == E_STAT){ s += v0 + v1; ss += v0*v0 + v1*v1; }
            *(float2*)&C[(size_t)r*N + cb] = make_float2(v0, v1);
        }
        if (EPI == E_STAT){
            s  += __shfl_xor_sync(0xffffffffu, s, 1);
            s  += __shfl_xor_sync(0xffffffffu, s, 2);
            ss += __shfl_xor_sync(0xffffffffu, ss, 1);
            ss += __shfl_xor_sync(0xffffffffu, ss, 2);
            if (tig == 0){
                int slot = (n0 >> 6)*2 + wn;
                oS1[slot*NTOK + r] = s;
                oS2[slot*NTOK + r] = ss;
            }
        }
    }
}

// ---------------- phase-A fused GEMM: gate (K=512, A=[x,shift]) + Wv (K=256, shares A) ----------------
__device__ void gemm_tile_a(float* smem,
                 const float* __restrict__ x,
                 const float* __restrict__ Wg1, const float* __restrict__ bg1,
                 const float* __restrict__ gw,  float* __restrict__ gpart,
                 const float* __restrict__ Wv,  const float* __restrict__ bv,
                 float* __restrict__ Cv,
                 int m0, int n0)
{
    const int KG = 2*DD;   // 512
    float* Asm = smem;                         // 3 x 128*APITCH
    float* Wsm = smem + 3*128*APITCH;          // 3 x 2 x 32*WPITCH (h=0 gate, h=1 v)

    const int tid = threadIdx.x;
    const int wid = tid >> 5;
    const int lane = tid & 31;
    const int grp = lane >> 2;
    const int tig = lane & 3;
    const int wm = wid >> 1;
    const int wn = wid & 1;

    float accg[4][4], accv[4][4];
    #pragma unroll
    for (int nt=0;nt<4;nt++)
        #pragma unroll
        for (int i=0;i<4;i++){ accg[nt][i]=0.f; accv[nt][i]=0.f; }

    auto load_tiles = [&](int buf, int k0){
        float* As = Asm + buf*128*APITCH;
        float* Ws = Wsm + buf*2*32*WPITCH;
        #pragma unroll
        for (int it = 0; it < 2; it++){
            int linear = tid + it*NTHR;
            int row = linear >> 3;
            int kq  = (linear & 7)*4;
            int m = m0 + row;
            int kg = k0 + kq;
            const float* src; int sz = 16;
            if (kg < DD) src = x + (size_t)m*DD + kg;
            else {
                int l = m & (LL-1);
                if (l == 0){ sz = 0; src = x; }
                else src = x + (size_t)(m-1)*DD + (kg-DD);
            }
            cp16((uint32_t)__cvta_generic_to_shared(&As[row*APITCH + kq]), src, sz);
        }
        {
            int row = tid >> 4;
            int wnq = (tid & 15)*4;
            const float* src = Wg1 + (size_t)(k0+row)*DD + n0 + wnq;
            cp16((uint32_t)__cvta_generic_to_shared(&Ws[row*WPITCH + wnq]), src, 16);
            if (k0 < DD){
                const float* srcv = Wv + (size_t)(k0+row)*DD + n0 + wnq;
                cp16((uint32_t)__cvta_generic_to_shared(&Ws[32*WPITCH + row*WPITCH + wnq]), srcv, 16);
            }
        }
    };

    const uint32_t aoff = ldsm_off(lane, wm*16, APITCH);
    const int ntiles = KG >> 5;   // 16
    load_tiles(0, 0);  cp_commit();
    load_tiles(1, 32); cp_commit();

    for (int kt = 0; kt < ntiles; kt++){
        int buf = kt % 3;
        cp_wait1();
        __syncthreads();
        if (kt+2 < ntiles) load_tiles((kt+2)%3, (kt+2)*32);
        cp_commit();

        const float* Ws = Wsm + buf*2*32*WPITCH;
        const uint32_t abase = shaddr(Asm + buf*128*APITCH) + aoff;
        const bool dov = (kt < 8);
        #pragma unroll
        for (int ks = 0; ks < 32; ks += 8){
            uint32_t afr[4];
            ldsm4(afr, abase + ks*4);
            #pragma unroll
            for (int nt=0; nt<4; nt++){
                uint32_t bfr[2];
                int cb = wn*32 + nt*8 + grp;
                bfr[0] = fb(Ws[(ks + tig    )*WPITCH + cb]);
                bfr[1] = fb(Ws[(ks + tig + 4)*WPITCH + cb]);
                mma_tf32(accg[nt], afr, bfr);
            }
            if (dov){
                const float* Wh = Ws + 32*WPITCH;
                #pragma unroll
                for (int nt=0; nt<4; nt++){
                    uint32_t bfr[2];
                    int cb = wn*32 + nt*8 + grp;
                    bfr[0] = fb(Wh[(ks + tig    )*WPITCH + cb]);
                    bfr[1] = fb(Wh[(ks + tig + 4)*WPITCH + cb]);
                    mma_tf32(accv[nt], afr, bfr);
                }
            }
        }
    }

    // gate epilogue -> gpart
    int slot = (n0 >> 6)*2 + wn;
    #pragma unroll
    for (int half=0; half<2; half++){
        int r = m0 + wm*16 + grp + half*8;
        float part = 0.f;
        #pragma unroll
        for (int nt=0; nt<4; nt++){
            int cb = n0 + wn*32 + nt*8 + 2*tig;
            float v0 = gelu_f(accg[nt][half*2+0] + bg1[cb]);
            float v1 = gelu_f(accg[nt][half*2+1] + bg1[cb+1]);
            part += v0*gw[cb] + v1*gw[cb+1];
        }
        part += __shfl_xor_sync(0xffffffffu, part, 1);
        part += __shfl_xor_sync(0xffffffffu, part, 2);
        if (tig == 0)
            gpart[(size_t)r*8 + slot] = part;
    }
    // value epilogue -> d_v
    #pragma unroll
    for (int half=0; half<2; half++){
        int r = m0 + wm*16 + grp + half*8;
        #pragma unroll
        for (int nt=0; nt<4; nt++){
            int cb = n0 + wn*32 + nt*8 + 2*tig;
            float v0 = accv[nt][half*2+0] + bv[cb];
            float v1 = accv[nt][half*2+1] + bv[cb+1];
            *(float2*)&Cv[(size_t)r*DD + cb] = make_float2(v0, v1);
        }
    }
}

// ---------------- dual-N GEMM for phase F ----------------
__device__ void gemm_tile_f(float* smem,
                 const float* __restrict__ A,
                 const float* __restrict__ W,
                 const float* __restrict__ bias,
                 float* __restrict__ C,
                 const float* __restrict__ lnS1, const float* __restrict__ lnS2,
                 const float* __restrict__ lnG,  const float* __restrict__ lnB,
                 int m0, int n0)
{
    const int N = 2*DD, K = DD;
    float* Asm = smem;
    float* Wsm = smem + 3*128*APITCH;

    const int tid = threadIdx.x;
    const int wid = tid >> 5;
    const int lane = tid & 31;
    const int grp = lane >> 2;
    const int tig = lane & 3;
    const int wm = wid >> 1;
    const int wn = wid & 1;

    float acc[2][4][4];
    #pragma unroll
    for (int h=0;h<2;h++)
        #pragma unroll
        for (int nt=0;nt<4;nt++)
            #pragma unroll
            for (int i=0;i<4;i++) acc[h][nt][i]=0.f;

    float4 areg[2]; float4 gv4, bv4;
    float mrow[2], rsrow[2];
    #pragma unroll
    for (int it=0; it<2; it++){
        int r = m0 + (tid>>3) + it*64;
        float sa = 0.f, sb = 0.f;
        #pragma unroll
        for (int s=0; s<8; s++){ sa += lnS1[s*NTOK + r]; sb += lnS2[s*NTOK + r]; }
        float mean = sa*(1.f/256.f);
        float var = fmaxf(sb*(1.f/256.f) - mean*mean, 0.f);
        mrow[it] = mean;
        rsrow[it] = rsqrtf(var + 1e-5f);
    }

    auto ldA_regs = [&](int k0){
        int kq = (tid & 7)*4;
        gv4 = *(const float4*)&lnG[k0+kq];
        bv4 = *(const float4*)&lnB[k0+kq];
        #pragma unroll
        for (int it=0; it<2; it++){
            int r = m0 + (tid>>3) + it*64;
            areg[it] = *(const float4*)&A[(size_t)r*K + k0 + kq];
        }
    };
    auto stA = [&](int buf){
        float* As = Asm + buf*128*APITCH;
        int kq = (tid & 7)*4;
        #pragma unroll
        for (int it=0; it<2; it++){
            int row = (tid>>3) + it*64;
            float4 v = areg[it];
            v.x = (v.x - mrow[it])*rsrow[it]*gv4.x + bv4.x;
            v.y = (v.y - mrow[it])*rsrow[it]*gv4.y + bv4.y;
            v.z = (v.z - mrow[it])*rsrow[it]*gv4.z + bv4.z;
            v.w = (v.w - mrow[it])*rsrow[it]*gv4.w + bv4.w;
            *(float4*)&As[row*APITCH + kq] = v;
        }
    };
    auto load_W = [&](int buf, int k0){
        float* Ws = Wsm + buf*2*32*WPITCH;
        int row = tid >> 4;
        int wnq = (tid & 15)*4;
        #pragma unroll
        for (int h = 0; h < 2; h++){
            const float* src = W + (size_t)(k0+row)*N + n0 + h*256 + wnq;
            cp16((uint32_t)__cvta_generic_to_shared(&Ws[h*32*WPITCH + row*WPITCH + wnq]), src, 16);
        }
    };

    const uint32_t aoff = ldsm_off(lane, wm*16, APITCH);
    const int ntiles = K >> 5;
    ldA_regs(0); load_W(0, 0); cp_commit(); stA(0);
    ldA_regs(32); load_W(1, 32); cp_commit(); stA(1);

    for (int kt = 0; kt < ntiles; kt++){
        int buf = kt % 3;
        cp_wait1();
        __syncthreads();
        if (kt+2 < ntiles){ ldA_regs((kt+2)*32); load_W((kt+2)%3, (kt+2)*32); }
        cp_commit();

        const float* Ws = Wsm + buf*2*32*WPITCH;
        const uint32_t abase = shaddr(Asm + buf*128*APITCH) + aoff;
        #pragma unroll
        for (int ks = 0; ks < 32; ks += 8){
            uint32_t afr[4];
            ldsm4(afr, abase + ks*4);
            #pragma unroll
            for (int h=0; h<2; h++){
                const float* Wh = Ws + h*32*WPITCH;
                #pragma unroll
                for (int nt=0; nt<4; nt++){
                    uint32_t bfr[2];
                    int cb = wn*32 + nt*8 + grp;
                    bfr[0] = fb(Wh[(ks + tig    )*WPITCH + cb]);
                    bfr[1] = fb(Wh[(ks + tig + 4)*WPITCH + cb]);
                    mma_tf32(acc[h][nt], afr, bfr);
                }
            }
        }
        if (kt+2 < ntiles) stA((kt+2)%3);
    }

    #pragma unroll
    for (int h=0; h<2; h++){
        #pragma unroll
        for (int half=0; half<2; half++){
            int r = m0 + wm*16 + grp + half*8;
            #pragma unroll
            for (int nt=0; nt<4; nt++){
                int cb = n0 + h*256 + wn*32 + nt*8 + 2*tig;
                float v0 = gelu_f(acc[h][nt][half*2+0] + bias[cb]);
                float v1 = gelu_f(acc[h][nt][half*2+1] + bias[cb+1]);
                *(float2*)&C[(size_t)r*N + cb] = make_float2(v0, v1);
            }
        }
    }
}

// ---------------- phases job: smem-staged ----------------
__device__ void phases_job(int blk, const float* __restrict__ x,
                           const float* __restrict__ Wk,
                           const float* __restrict__ bk,
                           float* smem){
    __syncthreads();
    float* xs = smem;              // 32 x 256
    float* wk = smem + 32*256;     // 256 x 32
    const int tid = threadIdx.x;
    const int rowbase = blk*32;
    for (int i = tid; i < 32*64; i += NTHR){
        int r = i >> 6, c4 = (i & 63)*4;
        *(float4*)&xs[r*256 + c4] = *(const float4*)&x[(size_t)(rowbase+r)*DD + c4];
    }
    for (int i = tid; i < 2048; i += NTHR){
        *(float4*)&wk[i*4] = *(const float4*)&Wk[i*4];
    }
    __syncthreads();
    int w = tid >> 5, p = tid & 31;
    int t0 = 2*w;
    float bkp = bk[p];
    float s0 = bkp, s1 = bkp;
    #pragma unroll 16
    for (int k = 0; k < 256; k++){
        float wv = wk[k*32 + p];
        s0 += xs[t0*256 + k]*wv;
        s1 += xs[(t0+1)*256 + k]*wv;
    }
    const float PI = 3.14159265358979323846f;
    float sn, cs;
    sincosf(tanhf(s0)*PI, &sn, &cs); d_cq[(rowbase+t0  )*PP+p]=cs; d_sq[(rowbase+t0  )*PP+p]=sn;
    sincosf(tanhf(s1)*PI, &sn, &cs); d_cq[(rowbase+t0+1)*PP+p]=cs; d_sq[(rowbase+t0+1)*PP+p]=sn;
}

// ---------------- gate finalize + scan ----------------
__device__ void cumsum_job(int b, const float* __restrict__ bg2, float* smem){
    int tid = threadIdx.x;
    int lane = tid & 31, warp = tid >> 5;
    float* wtot = smem;
    float bv = bg2[0];
    float v[4]; float run = 0.f;
    #pragma unroll
    for (int i=0;i<4;i++){
        int tok = b*LL + tid*4 + i;
        float4 a = *(const float4*)&d_gpart[(size_t)tok*8];
        float4 c = *(const float4*)&d_gpart[(size_t)tok*8 + 4];
        float s = bv + a.x+a.y+a.z+a.w + c.x+c.y+c.z+c.w;
        float g = 1.f/(1.f + expf(-s));
        d_g[tok] = g;
        run += g; v[i] = run;
    }
    float x = run;
    #pragma unroll
    for (int o=1;o<32;o<<=1){
        float y = __shfl_up_sync(0xffffffffu, x, o);
        if (lane >= o) x += y;
    }
    if (lane == 31) wtot[warp] = x;
    __syncthreads();
    if (warp == 0 && lane < 16){
        float t = wtot[lane];
        #pragma unroll
        for (int o=1;o<16;o<<=1){
            float z = __shfl_up_sync(0xffffu, t, o);
            if (lane >= o) t += z;
        }
        wtot[lane] = t;
    }
    __syncthreads();
    float off = (x - run) + (warp ? wtot[warp-1] : 0.f);
    float* gc = d_gc + b*LL + tid*4;
    #pragma unroll
    for (int i=0;i<4;i++) gc[i] = v[i] + off;
}

// ---------------- chunk state slice (computes g locally from gpart) ----------------
__device__ void chunk_state_job(int cc, int b, int tile, const float* __restrict__ bg2,
                                float* smem){
    float* sA = smem;            // 64*36
    float* sB = sA + 64*36;      // 32*264
    float* sg = sB + 32*264;     // 32
    const int tid = threadIdx.x;
    const int wid = tid >> 5, lane = tid & 31;
    const int grp = lane >> 2, tig = lane & 3;
    const int wm = wid >> 3;
    const int wn = wid & 7;

    int t0 = cc*CH + tile*32;
    if (tid < 32){
        int tok = b*LL + t0 + tid;
        float4 a = *(const float4*)&d_gpart[(size_t)tok*8];
        float4 c = *(const float4*)&d_gpart[(size_t)tok*8 + 4];
        float s = bg2[0] + a.x+a.y+a.z+a.w + c.x+c.y+c.z+c.w;
        sg[tid] = 1.f/(1.f + expf(-s));
    }

    float acc[2][4][4];
    #pragma unroll
    for (int mt=0;mt<2;mt++)
        #pragma unroll
        for (int nt=0;nt<4;nt++)
            #pragma unroll
            for (int i=0;i<4;i++) acc[mt][nt][i]=0.f;

    for (int i = tid; i < 64*32; i += NTHR){
        int p = i>>5, t = i&31;
        int gt = t0 + t;
        sA[p*36 + t] = (gt >= 1) ? f2tf_as_f(phasor(b, gt-1, p)) : 0.f;
    }
    __syncthreads();
    for (int i = tid; i < 32*64; i += NTHR){
        int t = i>>6, c4 = (i&63)*4;
        float gv = sg[t];
        float4 v = *(const float4*)&d_v[((size_t)(b*LL + t0 + t))*DD + c4];
        v.x = f2tf_as_f(v.x*gv); v.y = f2tf_as_f(v.y*gv);
        v.z = f2tf_as_f(v.z*gv); v.w = f2tf_as_f(v.w*gv);
        *(float4*)&sB[t*264 + c4] = v;
    }
    __syncthreads();
    const uint32_t abase = shaddr(sA) + ldsm_off(lane, wm*32, 36);
    #pragma unroll
    for (int ks = 0; ks < 32; ks += 8){
        uint32_t afr[2][4], bfr[4][2];
        #pragma unroll
        for (int mt=0; mt<2; mt++)
            ldsm4(afr[mt], abase + (mt*16*36 + ks)*4);
        #pragma unroll
        for (int nt=0; nt<4; nt++){
            int cb = wn*32 + nt*8 + grp;
            bfr[nt][0] = fb(sB[(ks + tig    )*264 + cb]);
            bfr[nt][1] = fb(sB[(ks + tig + 4)*264 + cb]);
        }
        #pragma unroll
        for (int mt=0; mt<2; mt++)
            #pragma unroll
            for (int nt=0; nt<4; nt++)
                mma_tf32(acc[mt][nt], afr[mt], bfr[nt]);
    }
    __syncthreads();
    size_t base = ((size_t)(b*64 + cc*4 + tile))*64*DD;
    #pragma unroll
    for (int mt=0; mt<2; mt++)
        #pragma unroll
        for (int nt=0; nt<4; nt++)
            #pragma unroll
            for (int half=0; half<2; half++){
                int row = wm*32 + mt*16 + grp + half*8;
                int col = wn*32 + nt*8 + 2*tig;
                *(float2*)&d_state[base + (size_t)row*DD + col] =
                    make_float2(acc[mt][nt][half*2], acc[mt][nt][half*2+1]);
            }
}

// ---------------- chunk prefix over 64 slices ----------------
__device__ void chunk_prefix_job(int b, int gs){
    int off = gs*2048 + threadIdx.x*4;
    float4 run = make_float4(0.f,0.f,0.f,0.f);
    #pragma unroll 8
    for (int c = 0; c < 64; c++){
        size_t base = ((size_t)(b*64 + c))*16384 + off;
        float4 v = *(const float4*)&d_state[base];
        if ((c & 3) == 0){
            size_t pb = ((size_t)(b*NCH + (c>>2)))*16384 + off;
            *(float4*)&d_pref[pb] = run;
        }
        run.x += v.x; run.y += v.y; run.z += v.z; run.w += v.w;
    }
}

// ---------------- chunk out ----------------
__device__ void chunk_out_job(int cc, int ds, int b, float* sm){
    float* sQ  = sm;
    float* sKT = sQ + 128*68;
    float* sS  = sKT + 64*136;
    float* sV  = sS + 128*132;
    float* sP  = sV + 128*72;
    const int tid = threadIdx.x;
    const int wid = tid >> 5, lane = tid & 31;
    const int grp = lane >> 2, tig = lane & 3;

    for (int i = tid; i < CH*64; i += NTHR){
        int r = i>>6, c = i&63;
        sQ[r*68 + c] = f2tf_as_f(phasor(b, cc*CH + r, c));
    }
    for (int i = tid; i < CH*64; i += NTHR){
        int t = i>>6, c = i&63;
        int gt = cc*CH + t;
        sKT[c*136 + t] = (gt >= 1) ? f2tf_as_f(phasor(b, gt-1, c)) : 0.f;
    }
    for (int i = tid; i < 128*16; i += NTHR){
        int t = i>>4, c4 = (i&15)*4;
        float gv = d_g[b*LL + cc*CH + t];
        float4 v = *(const float4*)&d_v[((size_t)(b*LL + cc*CH + t))*DD + ds*64 + c4];
        v.x = f2tf_as_f(v.x*gv); v.y = f2tf_as_f(v.y*gv);
        v.z = f2tf_as_f(v.z*gv); v.w = f2tf_as_f(v.w*gv);
        *(float4*)&sV[t*72 + c4] = v;
    }
    size_t pbase = ((size_t)(b*NCH + cc))*64*DD;
    for (int i = tid; i < 64*16; i += NTHR){
        int p = i>>4, c4 = (i&15)*4;
        float4 v = *(const float4*)&d_pref[pbase + (size_t)p*DD + ds*64 + c4];
        v.x = f2tf_as_f(v.x); v.y = f2tf_as_f(v.y);
        v.z = f2tf_as_f(v.z); v.w = f2tf_as_f(v.w);
        *(float4*)&sP[p*72 + c4] = v;
    }
    __syncthreads();

    // scores: 16 warps, 4x4 layout
    {
        const int wm = wid >> 2;
        const int wn = wid & 3;
        float acc2[2][4][4];
        #pragma unroll
        for (int mt=0;mt<2;mt++)
            #pragma unroll
            for (int nt=0;nt<4;nt++)
                #pragma unroll
                for (int i=0;i<4;i++) acc2[mt][nt][i]=0.f;
        const uint32_t qbase = shaddr(sQ) + ldsm_off(lane, wm*32, 68);
        #pragma unroll
        for (int ks = 0; ks < 64; ks += 8){
            uint32_t afr[2][4], bfr[4][2];
            #pragma unroll
            for (int mt=0; mt<2; mt++)
                ldsm4(afr[mt], qbase + (mt*16*68 + ks)*4);
            #pragma unroll
            for (int nt=0; nt<4; nt++){
                int cb = wn*32 + nt*8 + grp;
                bfr[nt][0] = fb(sKT[(ks + tig    )*136 + cb]);
                bfr[nt][1] = fb(sKT[(ks + tig + 4)*136 + cb]);
            }
            #pragma unroll
            for (int mt=0; mt<2; mt++)
                #pragma unroll
                for (int nt=0; nt<4; nt++)
                    mma_tf32(acc2[mt][nt], afr[mt], bfr[nt]);
        }
        #pragma unroll
        for (int mt=0; mt<2; mt++)
            #pragma unroll
            for (int nt=0; nt<4; nt++)
                #pragma unroll
                for (int half=0; half<2; half++){
                    int row = wm*32 + mt*16 + grp + half*8;
                    int col = wn*32 + nt*8 + 2*tig;
                    sS[row*132 + col    ] = (col   <= row) ? acc2[mt][nt][half*2  ] : 0.f;
                    sS[row*132 + col + 1] = (col+1 <= row) ? acc2[mt][nt][half*2+1] : 0.f;
                }
    }
    __syncthreads();

    // out: 16 warps, 8x2 layout
    const int wm = wid >> 1;
    const int wn = wid & 1;
    float acc[4][4];
    #pragma unroll
    for (int nt=0;nt<4;nt++)
        #pragma unroll
        for (int i=0;i<4;i++) acc[nt][i]=0.f;

    const uint32_t sbase = shaddr(sS) + ldsm_off(lane, wm*16, 132);
    #pragma unroll 4
    for (int ks = 0; ks < 128; ks += 8){
        uint32_t afr[4], bfr[4][2];
        ldsm4(afr, sbase + ks*4);
        #pragma unroll
        for (int nt=0; nt<4; nt++){
            int cb = wn*32 + nt*8 + grp;
            bfr[nt][0] = fb(sV[(ks + tig    )*72 + cb]);
            bfr[nt][1] = fb(sV[(ks + tig + 4)*72 + cb]);
        }
        #pragma unroll
        for (int nt=0; nt<4; nt++)
            mma_tf32(acc[nt], afr, bfr[nt]);
    }
    const uint32_t qb2 = shaddr(sQ) + ldsm_off(lane, wm*16, 68);
    #pragma unroll
    for (int ks = 0; ks < 64; ks += 8){
        uint32_t afr[4], bfr[4][2];
        ldsm4(afr, qb2 + ks*4);
        #pragma unroll
        for (int nt=0; nt<4; nt++){
            int cb = wn*32 + nt*8 + grp;
            bfr[nt][0] = fb(sP[(ks + tig    )*72 + cb]);
            bfr[nt][1] = fb(sP[(ks + tig + 4)*72 + cb]);
        }
        #pragma unroll
        for (int nt=0; nt<4; nt++)
            mma_tf32(acc[nt], afr, bfr[nt]);
    }

    int slot = ds*2 + wn;
    #pragma unroll
    for (int half=0; half<2; half++){
        int rloc = wm*16 + grp + half*8;
        int gtok = b*LL + cc*CH + rloc;
        float sc = rsqrtf(fmaxf(d_gc[gtok], 1.f)) * 0.17677669529663687f;
        float s = 0.f, ss = 0.f;
        #pragma unroll
        for (int nt=0; nt<4; nt++){
            int col = wn*32 + nt*8 + 2*tig;
            float v0 = acc[nt][half*2+0]*sc;
            float v1 = acc[nt][half*2+1]*sc;
            *(float2*)&d_ret[(size_t)gtok*DD + ds*64 + col] = make_float2(v0, v1);
            s += v0 + v1; ss += v0*v0 + v1*v1;
        }
        s  += __shfl_xor_sync(0xffffffffu, s, 1);
        s  += __shfl_xor_sync(0xffffffffu, s, 2);
        ss += __shfl_xor_sync(0xffffffffu, ss, 1);
        ss += __shfl_xor_sync(0xffffffffu, ss, 2);
        if (tig == 0){
            d_s1[slot*NTOK + gtok] = s;
            d_s2[slot*NTOK + gtok] = ss;
        }
    }
}

// ---------------- mega kernel ----------------
#define MEGA_SMEM ((128*68 + 64*136 + 128*132 + 128*72 + 64*72)*(int)sizeof(float))

__global__ void __launch_bounds__(NTHR, 1)
mega_kernel(const float* __restrict__ x,
            const float* __restrict__ Wk,  const float* __restrict__ bk,
            const float* __restrict__ Wv,  const float* __restrict__ bv,
            const float* __restrict__ Wg1, const float* __restrict__ bg1,
            const float* __restrict__ Wg2, const float* __restrict__ bg2,
            const float* __restrict__ ln1g,const float* __restrict__ ln1b,
            const float* __restrict__ Wr1, const float* __restrict__ br1,
            const float* __restrict__ Wr2, const float* __restrict__ br2,
            const float* __restrict__ ln2g,const float* __restrict__ ln2b,
            const float* __restrict__ Wo,  const float* __restrict__ bo,
            float* __restrict__ out)
{
    extern __shared__ __align__(16) float smem[];
    const int blk = blockIdx.x;
    const int m0 = (blk & 31)*128;
    const int n0 = (blk >> 5)*64;

    // Phase A: fused gate + value GEMM, then phases
    gemm_tile_a(smem, x, Wg1, bg1, Wg2, d_gpart, Wv, bv, d_v, m0, n0);
    phases_job(blk, x, Wk, bk, smem);
    gbar();

    // Phase B||C: blocks 0-1 run the scan; all blocks compute states with local g
    if (blk < BB) cumsum_job(blk, bg2, smem);
    __syncthreads();
    chunk_state_job((blk >> 2) & 15, blk >> 6, blk & 3, bg2, smem);
    gbar();

    // Phase D
    if (blk < 16) chunk_prefix_job(blk >> 3, blk & 7);
    gbar();

    // Phase E
    chunk_out_job((blk >> 2) & 15, blk & 3, blk >> 6, smem);
    gbar();

    // Phase F: dual-N fused (one K pass, A LN'd once)
    gemm_tile_f(smem, d_ret, Wr1, br1, d_t1,
        d_s1, d_s2, ln1g, ln1b, m0, n0);
    gbar();

    // Phase G
    gemm_tile<A_PLAIN, E_STAT>(smem, d_t1, Wr2, br2, d_t2, nullptr,
        nullptr, nullptr, nullptr, nullptr, d_s1b, d_s2b,
        m0, n0, NTOK, DD, 2*DD);
    gbar();

    // Phase H
    gemm_tile<A_LN, E_OUT>(smem, d_t2, Wo, bo, out, x,
        d_s1b, d_s2b, ln2g, ln2b, nullptr, nullptr,
        m0, n0, NTOK, DD, DD);
}

// ---------------- launch ----------------
extern "C" void kernel_launch(void* const* d_in, const int* in_sizes, int n_in,
                              void* d_out, int out_size)
{
    const float* x    = (const float*)d_in[0];
    const float* Wk   = (const float*)d_in[1];
    const float* bk   = (const float*)d_in[2];
    const float* Wv   = (const float*)d_in[3];
    const float* bv   = (const float*)d_in[4];
    const float* Wg1  = (const float*)d_in[5];
    const float* bg1  = (const float*)d_in[6];
    const float* Wg2  = (const float*)d_in[7];
    const float* bg2  = (const float*)d_in[8];
    const float* ln1g = (const float*)d_in[9];
    const float* ln1b = (const float*)d_in[10];
    const float* Wr1  = (const float*)d_in[11];
    const float* br1  = (const float*)d_in[12];
    const float* Wr2  = (const float*)d_in[13];
    const float* br2  = (const float*)d_in[14];
    const float* ln2g = (const float*)d_in[15];
    const float* ln2b = (const float*)d_in[16];
    const float* Wo   = (const float*)d_in[17];
    const float* bo   = (const float*)d_in[18];
    float* out = (float*)d_out;

    static bool init = false;
    if (!init){
        cudaFuncSetAttribute(mega_kernel, cudaFuncAttributeMaxDynamicSharedMemorySize, MEGA_SMEM);
        init = true;
    }

    mega_kernel<<<NBLK, NTHR, MEGA_SMEM>>>(
        x, Wk, bk, Wv, bv, Wg1, bg1, Wg2, bg2,
        ln1g, ln1b, Wr1, br1, Wr2, br2, ln2g, ln2b, Wo, bo, out);
    (void)in_sizes; (void)n_in; (void)out_size;
}

// round 16
// speedup vs baseline: 3.2371x; 1.0009x over previous
#include <cuda_runtime.h>
#include <math.h>
#include <stdint.h>

#define BB 2
#define LL 2048
#define DD 256
#define PP 32
#define NTOK (BB*LL)
#define NCH 16
#define CH 128
#define NBLK 128
#define NTHR 512

// ---------------- scratch ----------------
__device__ float d_cq[NTOK*PP];
__device__ float d_sq[NTOK*PP];
__device__ float d_g [NTOK];
__device__ float d_gc[NTOK];
__device__ float d_v [NTOK*DD];
__device__ float d_ret[NTOK*DD];
__device__ float d_t1[NTOK*2*DD];
__device__ float d_t2[NTOK*DD];
__device__ float d_state[BB*64*64*DD];
__device__ float d_pref [BB*NCH*64*DD];
__device__ float d_gpart[NTOK*8];
__device__ float d_s1 [8*NTOK];
__device__ float d_s2 [8*NTOK];
__device__ float d_s1b[8*NTOK];
__device__ float d_s2b[8*NTOK];

__device__ unsigned bar_cnt = 0;
__device__ unsigned bar_gen = 0;

__device__ __forceinline__ void gbar(){
    __syncthreads();
    __threadfence();
    if (threadIdx.x == 0){
        volatile unsigned* vg = &bar_gen;
        unsigned gen = *vg;
        unsigned t = atomicAdd(&bar_cnt, 1);
        if (t == gridDim.x - 1){
            atomicExch(&bar_cnt, 0);
            __threadfence();
            atomicAdd(&bar_gen, 1);
        } else {
            while (*vg == gen) { __nanosleep(32); }
        }
    }
    __syncthreads();
}

__device__ __forceinline__ float gelu_f(float x){
    return 0.5f*x*(1.0f+erff(x*0.7071067811865476f));
}
__device__ __forceinline__ float phasor(int b, int tok, int c){
    int t = b*LL + tok;
    return (c < 32) ? d_cq[t*PP + c] : d_sq[t*PP + c - 32];
}
__device__ __forceinline__ uint32_t f2tf(float f){
    uint32_t r; asm("cvt.rna.tf32.f32 %0, %1;" : "=r"(r) : "f"(f)); return r;
}
__device__ __forceinline__ uint32_t fb(float f){ return __float_as_uint(f); }
__device__ __forceinline__ float f2tf_as_f(float f){
    uint32_t r = f2tf(f); return __uint_as_float(r);
}
__device__ __forceinline__ void mma_tf32(float* c, const uint32_t* a, const uint32_t* b){
    asm volatile(
      "mma.sync.aligned.m16n8k8.row.col.f32.tf32.tf32.f32 "
      "{%0,%1,%2,%3}, {%4,%5,%6,%7}, {%8,%9}, {%0,%1,%2,%3};\n"
      : "+f"(c[0]), "+f"(c[1]), "+f"(c[2]), "+f"(c[3])
      : "r"(a[0]), "r"(a[1]), "r"(a[2]), "r"(a[3]), "r"(b[0]), "r"(b[1]));
}
__device__ __forceinline__ void ldsm4(uint32_t* r, uint32_t addr){
    asm volatile("ldmatrix.sync.aligned.m8n8.x4.shared.b16 {%0,%1,%2,%3}, [%4];\n"
        : "=r"(r[0]), "=r"(r[1]), "=r"(r[2]), "=r"(r[3]) : "r"(addr));
}
__device__ __forceinline__ uint32_t shaddr(const void* p){
    return (uint32_t)__cvta_generic_to_shared(p);
}
__device__ __forceinline__ uint32_t ldsm_off(int lane, int row0, int P){
    int t8 = lane >> 3, r8 = lane & 7;
    return (uint32_t)(((row0 + r8 + (t8 & 1)*8)*P + (t8 >> 1)*4) * 4);
}

__device__ __forceinline__ void cp16(uint32_t dst, const void* src, int sz){
    asm volatile("cp.async.cg.shared.global [%0], [%1], 16, %2;\n"
                 :: "r"(dst), "l"(src), "r"(sz));
}
__device__ __forceinline__ void cp_commit(){ asm volatile("cp.async.commit_group;\n"); }
__device__ __forceinline__ void cp_wait1(){ asm volatile("cp.async.wait_group 1;\n"); }

#define A_PLAIN  0
#define A_CONCAT 1
#define A_LN     2
#define E_NONE 0
#define E_GELU 1
#define E_OUT  3
#define E_GATE 4
#define E_STAT 5

#define APITCH 36
#define WPITCH 72

// ---------------- generic GEMM tile (phases G, H) ----------------
template<int AMODE, int EPI>
__device__ void gemm_tile(float* smem,
                 const float* __restrict__ A,
                 const float* __restrict__ W,
                 const float* __restrict__ bias,
                 float* __restrict__ C,
                 const float* __restrict__ extra,
                 const float* __restrict__ lnS1, const float* __restrict__ lnS2,
                 const float* __restrict__ lnG,  const float* __restrict__ lnB,
                 float* __restrict__ oS1, float* __restrict__ oS2,
                 int m0, int n0, int M, int N, int K)
{
    float* Asm = smem;
    float* Wsm = smem + 3*128*APITCH;

    const int tid = threadIdx.x;
    const int wid = tid >> 5;
    const int lane = tid & 31;
    const int grp = lane >> 2;
    const int tig = lane & 3;
    const int wm = wid >> 1;
    const int wn = wid & 1;

    float acc[4][4];
    #pragma unroll
    for (int nt=0;nt<4;nt++)
        #pragma unroll
        for (int i=0;i<4;i++) acc[nt][i]=0.f;

    float4 areg[2]; float4 gv4, bv4;
    float mrow[2], rsrow[2];
    if (AMODE == A_LN){
        #pragma unroll
        for (int it=0; it<2; it++){
            int r = m0 + (tid>>3) + it*64;
            float sa = 0.f, sb = 0.f;
            #pragma unroll
            for (int s=0; s<8; s++){ sa += lnS1[s*NTOK + r]; sb += lnS2[s*NTOK + r]; }
            float mean = sa*(1.f/256.f);
            float var = fmaxf(sb*(1.f/256.f) - mean*mean, 0.f);
            mrow[it] = mean;
            rsrow[it] = rsqrtf(var + 1e-5f);
        }
    }

    auto ldA_regs = [&](int k0){
        int kq = (tid & 7)*4;
        gv4 = *(const float4*)&lnG[k0+kq];
        bv4 = *(const float4*)&lnB[k0+kq];
        #pragma unroll
        for (int it=0; it<2; it++){
            int r = m0 + (tid>>3) + it*64;
            areg[it] = *(const float4*)&A[(size_t)r*K + k0 + kq];
        }
    };
    auto stA = [&](int buf){
        float* As = Asm + buf*128*APITCH;
        int kq = (tid & 7)*4;
        #pragma unroll
        for (int it=0; it<2; it++){
            int row = (tid>>3) + it*64;
            float4 v = areg[it];
            v.x = (v.x - mrow[it])*rsrow[it]*gv4.x + bv4.x;
            v.y = (v.y - mrow[it])*rsrow[it]*gv4.y + bv4.y;
            v.z = (v.z - mrow[it])*rsrow[it]*gv4.z + bv4.z;
            v.w = (v.w - mrow[it])*rsrow[it]*gv4.w + bv4.w;
            *(float4*)&As[row*APITCH + kq] = v;
        }
    };

    auto load_tiles = [&](int buf, int k0){
        float* As = Asm + buf*128*APITCH;
        float* Ws = Wsm + buf*32*WPITCH;
        if (AMODE != A_LN){
            #pragma unroll
            for (int it = 0; it < 2; it++){
                int linear = tid + it*NTHR;
                int row = linear >> 3;
                int kq  = (linear & 7)*4;
                int m = m0 + row;
                int kg = k0 + kq;
                const float* src = A + (size_t)m*K + kg;
                cp16((uint32_t)__cvta_generic_to_shared(&As[row*APITCH + kq]), src, 16);
            }
        }
        {
            int row = tid >> 4;
            int wnq = (tid & 15)*4;
            const float* src = W + (size_t)(k0+row)*N + n0 + wnq;
            cp16((uint32_t)__cvta_generic_to_shared(&Ws[row*WPITCH + wnq]), src, 16);
        }
    };

    const uint32_t aoff = ldsm_off(lane, wm*16, APITCH);

    const int ntiles = K >> 5;
    if (AMODE == A_LN) ldA_regs(0);
    load_tiles(0, 0);
    cp_commit();
    if (AMODE == A_LN) stA(0);
    if (AMODE == A_LN) ldA_regs(32);
    load_tiles(1, 32);
    cp_commit();
    if (AMODE == A_LN) stA(1);

    for (int kt = 0; kt < ntiles; kt++){
        int buf = kt % 3;
        cp_wait1();
        __syncthreads();

        if (kt+2 < ntiles){
            if (AMODE == A_LN) ldA_regs((kt+2)*32);
            load_tiles((kt+2)%3, (kt+2)*32);
        }
        cp_commit();

        const float* Ws = Wsm + buf*32*WPITCH;
        const uint32_t abase = shaddr(Asm + buf*128*APITCH) + aoff;
        #pragma unroll
        for (int ks = 0; ks < 32; ks += 8){
            uint32_t afr[4], bfr[4][2];
            ldsm4(afr, abase + ks*4);
            #pragma unroll
            for (int nt=0; nt<4; nt++){
                int cb = wn*32 + nt*8 + grp;
                bfr[nt][0] = fb(Ws[(ks + tig    )*WPITCH + cb]);
                bfr[nt][1] = fb(Ws[(ks + tig + 4)*WPITCH + cb]);
            }
            #pragma unroll
            for (int nt=0; nt<4; nt++)
                mma_tf32(acc[nt], afr, bfr[nt]);
        }
        if (AMODE == A_LN && kt+2 < ntiles) stA((kt+2)%3);
    }

    #pragma unroll
    for (int half=0; half<2; half++){
        int r = m0 + wm*16 + grp + half*8;
        float s = 0.f, ss = 0.f;
        #pragma unroll
        for (int nt=0; nt<4; nt++){
            int cb = n0 + wn*32 + nt*8 + 2*tig;
            float v0 = acc[nt][half*2+0] + bias[cb];
            float v1 = acc[nt][half*2+1] + bias[cb+1];
            if (EPI == E_GELU){ v0 = gelu_f(v0); v1 = gelu_f(v1); }
            if (EPI == E_OUT) { v0 += extra[(size_t)r*DD + cb];
                                v1 += extra[(size_t)r*DD + cb + 1]; }
            if (EPI == E_STAT){ s += v0 + v1; ss += v0*v0 + v1*v1; }
            *(float2*)&C[(size_t)r*N + cb] = make_float2(v0, v1);
        }
        if (EPI == E_STAT){
            s  += __shfl_xor_sync(0xffffffffu, s, 1);
            s  += __shfl_xor_sync(0xffffffffu, s, 2);
            ss += __shfl_xor_sync(0xffffffffu, ss, 1);
            ss += __shfl_xor_sync(0xffffffffu, ss, 2);
            if (tig == 0){
                int slot = (n0 >> 6)*2 + wn;
                oS1[slot*NTOK + r] = s;
                oS2[slot*NTOK + r] = ss;
            }
        }
    }
}

// ---------------- phase-A fused GEMM: gate + Wv sharing A ----------------
__device__ void gemm_tile_a(float* smem,
                 const float* __restrict__ x,
                 const float* __restrict__ Wg1, const float* __restrict__ bg1,
                 const float* __restrict__ gw,  float* __restrict__ gpart,
                 const float* __restrict__ Wv,  const float* __restrict__ bv,
                 float* __restrict__ Cv,
                 int m0, int n0)
{
    const int KG = 2*DD;
    float* Asm = smem;
    float* Wsm = smem + 3*128*APITCH;

    const int tid = threadIdx.x;
    const int wid = tid >> 5;
    const int lane = tid & 31;
    const int grp = lane >> 2;
    const int tig = lane & 3;
    const int wm = wid >> 1;
    const int wn = wid & 1;

    float accg[4][4], accv[4][4];
    #pragma unroll
    for (int nt=0;nt<4;nt++)
        #pragma unroll
        for (int i=0;i<4;i++){ accg[nt][i]=0.f; accv[nt][i]=0.f; }

    auto load_tiles = [&](int buf, int k0){
        float* As = Asm + buf*128*APITCH;
        float* Ws = Wsm + buf*2*32*WPITCH;
        #pragma unroll
        for (int it = 0; it < 2; it++){
            int linear = tid + it*NTHR;
            int row = linear >> 3;
            int kq  = (linear & 7)*4;
            int m = m0 + row;
            int kg = k0 + kq;
            const float* src; int sz = 16;
            if (kg < DD) src = x + (size_t)m*DD + kg;
            else {
                int l = m & (LL-1);
                if (l == 0){ sz = 0; src = x; }
                else src = x + (size_t)(m-1)*DD + (kg-DD);
            }
            cp16((uint32_t)__cvta_generic_to_shared(&As[row*APITCH + kq]), src, sz);
        }
        {
            int row = tid >> 4;
            int wnq = (tid & 15)*4;
            const float* src = Wg1 + (size_t)(k0+row)*DD + n0 + wnq;
            cp16((uint32_t)__cvta_generic_to_shared(&Ws[row*WPITCH + wnq]), src, 16);
            if (k0 < DD){
                const float* srcv = Wv + (size_t)(k0+row)*DD + n0 + wnq;
                cp16((uint32_t)__cvta_generic_to_shared(&Ws[32*WPITCH + row*WPITCH + wnq]), srcv, 16);
            }
        }
    };

    const uint32_t aoff = ldsm_off(lane, wm*16, APITCH);
    const int ntiles = KG >> 5;
    load_tiles(0, 0);  cp_commit();
    load_tiles(1, 32); cp_commit();

    for (int kt = 0; kt < ntiles; kt++){
        int buf = kt % 3;
        cp_wait1();
        __syncthreads();
        if (kt+2 < ntiles) load_tiles((kt+2)%3, (kt+2)*32);
        cp_commit();

        const float* Ws = Wsm + buf*2*32*WPITCH;
        const uint32_t abase = shaddr(Asm + buf*128*APITCH) + aoff;
        const bool dov = (kt < 8);
        #pragma unroll
        for (int ks = 0; ks < 32; ks += 8){
            uint32_t afr[4];
            ldsm4(afr, abase + ks*4);
            #pragma unroll
            for (int nt=0; nt<4; nt++){
                uint32_t bfr[2];
                int cb = wn*32 + nt*8 + grp;
                bfr[0] = fb(Ws[(ks + tig    )*WPITCH + cb]);
                bfr[1] = fb(Ws[(ks + tig + 4)*WPITCH + cb]);
                mma_tf32(accg[nt], afr, bfr);
            }
            if (dov){
                const float* Wh = Ws + 32*WPITCH;
                #pragma unroll
                for (int nt=0; nt<4; nt++){
                    uint32_t bfr[2];
                    int cb = wn*32 + nt*8 + grp;
                    bfr[0] = fb(Wh[(ks + tig    )*WPITCH + cb]);
                    bfr[1] = fb(Wh[(ks + tig + 4)*WPITCH + cb]);
                    mma_tf32(accv[nt], afr, bfr);
                }
            }
        }
    }

    int slot = (n0 >> 6)*2 + wn;
    #pragma unroll
    for (int half=0; half<2; half++){
        int r = m0 + wm*16 + grp + half*8;
        float part = 0.f;
        #pragma unroll
        for (int nt=0; nt<4; nt++){
            int cb = n0 + wn*32 + nt*8 + 2*tig;
            float v0 = gelu_f(accg[nt][half*2+0] + bg1[cb]);
            float v1 = gelu_f(accg[nt][half*2+1] + bg1[cb+1]);
            part += v0*gw[cb] + v1*gw[cb+1];
        }
        part += __shfl_xor_sync(0xffffffffu, part, 1);
        part += __shfl_xor_sync(0xffffffffu, part, 2);
        if (tig == 0)
            gpart[(size_t)r*8 + slot] = part;
    }
    #pragma unroll
    for (int half=0; half<2; half++){
        int r = m0 + wm*16 + grp + half*8;
        #pragma unroll
        for (int nt=0; nt<4; nt++){
            int cb = n0 + wn*32 + nt*8 + 2*tig;
            float v0 = accv[nt][half*2+0] + bv[cb];
            float v1 = accv[nt][half*2+1] + bv[cb+1];
            *(float2*)&Cv[(size_t)r*DD + cb] = make_float2(v0, v1);
        }
    }
}

// ---------------- dual-N GEMM for phase F ----------------
__device__ void gemm_tile_f(float* smem,
                 const float* __restrict__ A,
                 const float* __restrict__ W,
                 const float* __restrict__ bias,
                 float* __restrict__ C,
                 const float* __restrict__ lnS1, const float* __restrict__ lnS2,
                 const float* __restrict__ lnG,  const float* __restrict__ lnB,
                 int m0, int n0)
{
    const int N = 2*DD, K = DD;
    float* Asm = smem;
    float* Wsm = smem + 3*128*APITCH;

    const int tid = threadIdx.x;
    const int wid = tid >> 5;
    const int lane = tid & 31;
    const int grp = lane >> 2;
    const int tig = lane & 3;
    const int wm = wid >> 1;
    const int wn = wid & 1;

    float acc[2][4][4];
    #pragma unroll
    for (int h=0;h<2;h++)
        #pragma unroll
        for (int nt=0;nt<4;nt++)
            #pragma unroll
            for (int i=0;i<4;i++) acc[h][nt][i]=0.f;

    float4 areg[2]; float4 gv4, bv4;
    float mrow[2], rsrow[2];
    #pragma unroll
    for (int it=0; it<2; it++){
        int r = m0 + (tid>>3) + it*64;
        float sa = 0.f, sb = 0.f;
        #pragma unroll
        for (int s=0; s<8; s++){ sa += lnS1[s*NTOK + r]; sb += lnS2[s*NTOK + r]; }
        float mean = sa*(1.f/256.f);
        float var = fmaxf(sb*(1.f/256.f) - mean*mean, 0.f);
        mrow[it] = mean;
        rsrow[it] = rsqrtf(var + 1e-5f);
    }

    auto ldA_regs = [&](int k0){
        int kq = (tid & 7)*4;
        gv4 = *(const float4*)&lnG[k0+kq];
        bv4 = *(const float4*)&lnB[k0+kq];
        #pragma unroll
        for (int it=0; it<2; it++){
            int r = m0 + (tid>>3) + it*64;
            areg[it] = *(const float4*)&A[(size_t)r*K + k0 + kq];
        }
    };
    auto stA = [&](int buf){
        float* As = Asm + buf*128*APITCH;
        int kq = (tid & 7)*4;
        #pragma unroll
        for (int it=0; it<2; it++){
            int row = (tid>>3) + it*64;
            float4 v = areg[it];
            v.x = (v.x - mrow[it])*rsrow[it]*gv4.x + bv4.x;
            v.y = (v.y - mrow[it])*rsrow[it]*gv4.y + bv4.y;
            v.z = (v.z - mrow[it])*rsrow[it]*gv4.z + bv4.z;
            v.w = (v.w - mrow[it])*rsrow[it]*gv4.w + bv4.w;
            *(float4*)&As[row*APITCH + kq] = v;
        }
    };
    auto load_W = [&](int buf, int k0){
        float* Ws = Wsm + buf*2*32*WPITCH;
        int row = tid >> 4;
        int wnq = (tid & 15)*4;
        #pragma unroll
        for (int h = 0; h < 2; h++){
            const float* src = W + (size_t)(k0+row)*N + n0 + h*256 + wnq;
            cp16((uint32_t)__cvta_generic_to_shared(&Ws[h*32*WPITCH + row*WPITCH + wnq]), src, 16);
        }
    };

    const uint32_t aoff = ldsm_off(lane, wm*16, APITCH);
    const int ntiles = K >> 5;
    ldA_regs(0); load_W(0, 0); cp_commit(); stA(0);
    ldA_regs(32); load_W(1, 32); cp_commit(); stA(1);

    for (int kt = 0; kt < ntiles; kt++){
        int buf = kt % 3;
        cp_wait1();
        __syncthreads();
        if (kt+2 < ntiles){ ldA_regs((kt+2)*32); load_W((kt+2)%3, (kt+2)*32); }
        cp_commit();

        const float* Ws = Wsm + buf*2*32*WPITCH;
        const uint32_t abase = shaddr(Asm + buf*128*APITCH) + aoff;
        #pragma unroll
        for (int ks = 0; ks < 32; ks += 8){
            uint32_t afr[4];
            ldsm4(afr, abase + ks*4);
            #pragma unroll
            for (int h=0; h<2; h++){
                const float* Wh = Ws + h*32*WPITCH;
                #pragma unroll
                for (int nt=0; nt<4; nt++){
                    uint32_t bfr[2];
                    int cb = wn*32 + nt*8 + grp;
                    bfr[0] = fb(Wh[(ks + tig    )*WPITCH + cb]);
                    bfr[1] = fb(Wh[(ks + tig + 4)*WPITCH + cb]);
                    mma_tf32(acc[h][nt], afr, bfr);
                }
            }
        }
        if (kt+2 < ntiles) stA((kt+2)%3);
    }

    #pragma unroll
    for (int h=0; h<2; h++){
        #pragma unroll
        for (int half=0; half<2; half++){
            int r = m0 + wm*16 + grp + half*8;
            #pragma unroll
            for (int nt=0; nt<4; nt++){
                int cb = n0 + h*256 + wn*32 + nt*8 + 2*tig;
                float v0 = gelu_f(acc[h][nt][half*2+0] + bias[cb]);
                float v1 = gelu_f(acc[h][nt][half*2+1] + bias[cb+1]);
                *(float2*)&C[(size_t)r*N + cb] = make_float2(v0, v1);
            }
        }
    }
}

// ---------------- phases job: smem-staged ----------------
__device__ void phases_job(int blk, const float* __restrict__ x,
                           const float* __restrict__ Wk,
                           const float* __restrict__ bk,
                           float* smem){
    __syncthreads();
    float* xs = smem;
    float* wk = smem + 32*256;
    const int tid = threadIdx.x;
    const int rowbase = blk*32;
    for (int i = tid; i < 32*64; i += NTHR){
        int r = i >> 6, c4 = (i & 63)*4;
        *(float4*)&xs[r*256 + c4] = *(const float4*)&x[(size_t)(rowbase+r)*DD + c4];
    }
    for (int i = tid; i < 2048; i += NTHR){
        *(float4*)&wk[i*4] = *(const float4*)&Wk[i*4];
    }
    __syncthreads();
    int w = tid >> 5, p = tid & 31;
    int t0 = 2*w;
    float bkp = bk[p];
    float s0 = bkp, s1 = bkp;
    #pragma unroll 16
    for (int k = 0; k < 256; k++){
        float wv = wk[k*32 + p];
        s0 += xs[t0*256 + k]*wv;
        s1 += xs[(t0+1)*256 + k]*wv;
    }
    const float PI = 3.14159265358979323846f;
    float sn, cs;
    sincosf(tanhf(s0)*PI, &sn, &cs); d_cq[(rowbase+t0  )*PP+p]=cs; d_sq[(rowbase+t0  )*PP+p]=sn;
    sincosf(tanhf(s1)*PI, &sn, &cs); d_cq[(rowbase+t0+1)*PP+p]=cs; d_sq[(rowbase+t0+1)*PP+p]=sn;
}

// ---------------- gate finalize + scan ----------------
__device__ void cumsum_job(int b, const float* __restrict__ bg2, float* smem){
    int tid = threadIdx.x;
    int lane = tid & 31, warp = tid >> 5;
    float* wtot = smem;
    float bv = bg2[0];
    float v[4]; float run = 0.f;
    #pragma unroll
    for (int i=0;i<4;i++){
        int tok = b*LL + tid*4 + i;
        float4 a = *(const float4*)&d_gpart[(size_t)tok*8];
        float4 c = *(const float4*)&d_gpart[(size_t)tok*8 + 4];
        float s = bv + a.x+a.y+a.z+a.w + c.x+c.y+c.z+c.w;
        float g = 1.f/(1.f + expf(-s));
        d_g[tok] = g;
        run += g; v[i] = run;
    }
    float x = run;
    #pragma unroll
    for (int o=1;o<32;o<<=1){
        float y = __shfl_up_sync(0xffffffffu, x, o);
        if (lane >= o) x += y;
    }
    if (lane == 31) wtot[warp] = x;
    __syncthreads();
    if (warp == 0 && lane < 16){
        float t = wtot[lane];
        #pragma unroll
        for (int o=1;o<16;o<<=1){
            float z = __shfl_up_sync(0xffffu, t, o);
            if (lane >= o) t += z;
        }
        wtot[lane] = t;
    }
    __syncthreads();
    float off = (x - run) + (warp ? wtot[warp-1] : 0.f);
    float* gc = d_gc + b*LL + tid*4;
    #pragma unroll
    for (int i=0;i<4;i++) gc[i] = v[i] + off;
}

// ---------------- chunk state slice ----------------
__device__ void chunk_state_job(int cc, int b, int tile, const float* __restrict__ bg2,
                                float* smem){
    float* sA = smem;
    float* sB = sA + 64*36;
    float* sg = sB + 32*264;
    const int tid = threadIdx.x;
    const int wid = tid >> 5, lane = tid & 31;
    const int grp = lane >> 2, tig = lane & 3;
    const int wm = wid >> 3;
    const int wn = wid & 7;

    int t0 = cc*CH + tile*32;
    if (tid < 32){
        int tok = b*LL + t0 + tid;
        float4 a = *(const float4*)&d_gpart[(size_t)tok*8];
        float4 c = *(const float4*)&d_gpart[(size_t)tok*8 + 4];
        float s = bg2[0] + a.x+a.y+a.z+a.w + c.x+c.y+c.z+c.w;
        sg[tid] = 1.f/(1.f + expf(-s));
    }

    float acc[2][4][4];
    #pragma unroll
    for (int mt=0;mt<2;mt++)
        #pragma unroll
        for (int nt=0;nt<4;nt++)
            #pragma unroll
            for (int i=0;i<4;i++) acc[mt][nt][i]=0.f;

    for (int i = tid; i < 64*32; i += NTHR){
        int p = i>>5, t = i&31;
        int gt = t0 + t;
        sA[p*36 + t] = (gt >= 1) ? f2tf_as_f(phasor(b, gt-1, p)) : 0.f;
    }
    __syncthreads();
    for (int i = tid; i < 32*64; i += NTHR){
        int t = i>>6, c4 = (i&63)*4;
        float gv = sg[t];
        float4 v = *(const float4*)&d_v[((size_t)(b*LL + t0 + t))*DD + c4];
        v.x = f2tf_as_f(v.x*gv); v.y = f2tf_as_f(v.y*gv);
        v.z = f2tf_as_f(v.z*gv); v.w = f2tf_as_f(v.w*gv);
        *(float4*)&sB[t*264 + c4] = v;
    }
    __syncthreads();
    const uint32_t abase = shaddr(sA) + ldsm_off(lane, wm*32, 36);
    #pragma unroll
    for (int ks = 0; ks < 32; ks += 8){
        uint32_t afr[2][4], bfr[4][2];
        #pragma unroll
        for (int mt=0; mt<2; mt++)
            ldsm4(afr[mt], abase + (mt*16*36 + ks)*4);
        #pragma unroll
        for (int nt=0; nt<4; nt++){
            int cb = wn*32 + nt*8 + grp;
            bfr[nt][0] = fb(sB[(ks + tig    )*264 + cb]);
            bfr[nt][1] = fb(sB[(ks + tig + 4)*264 + cb]);
        }
        #pragma unroll
        for (int mt=0; mt<2; mt++)
            #pragma unroll
            for (int nt=0; nt<4; nt++)
                mma_tf32(acc[mt][nt], afr[mt], bfr[nt]);
    }
    __syncthreads();
    size_t base = ((size_t)(b*64 + cc*4 + tile))*64*DD;
    #pragma unroll
    for (int mt=0; mt<2; mt++)
        #pragma unroll
        for (int nt=0; nt<4; nt++)
            #pragma unroll
            for (int half=0; half<2; half++){
                int row = wm*32 + mt*16 + grp + half*8;
                int col = wn*32 + nt*8 + 2*tig;
                *(float2*)&d_state[base + (size_t)row*DD + col] =
                    make_float2(acc[mt][nt][half*2], acc[mt][nt][half*2+1]);
            }
}

// ---------------- chunk prefix over 64 slices ----------------
__device__ void chunk_prefix_job(int b, int gs){
    int off = gs*2048 + threadIdx.x*4;
    float4 run = make_float4(0.f,0.f,0.f,0.f);
    #pragma unroll 8
    for (int c = 0; c < 64; c++){
        size_t base = ((size_t)(b*64 + c))*16384 + off;
        float4 v = *(const float4*)&d_state[base];
        if ((c & 3) == 0){
            size_t pb = ((size_t)(b*NCH + (c>>2)))*16384 + off;
            *(float4*)&d_pref[pb] = run;
        }
        run.x += v.x; run.y += v.y; run.z += v.z; run.w += v.w;
    }
}

// ---------------- chunk out part 1: load tiles + masked scores ----------------
__device__ void chunk_out_scores(int cc, int ds, int b, float* sm){
    float* sQ  = sm;
    float* sKT = sQ + 128*68;
    float* sS  = sKT + 64*136;
    float* sV  = sS + 128*132;
    const int tid = threadIdx.x;
    const int wid = tid >> 5, lane = tid & 31;
    const int grp = lane >> 2, tig = lane & 3;

    for (int i = tid; i < CH*64; i += NTHR){
        int r = i>>6, c = i&63;
        sQ[r*68 + c] = f2tf_as_f(phasor(b, cc*CH + r, c));
    }
    for (int i = tid; i < CH*64; i += NTHR){
        int t = i>>6, c = i&63;
        int gt = cc*CH + t;
        sKT[c*136 + t] = (gt >= 1) ? f2tf_as_f(phasor(b, gt-1, c)) : 0.f;
    }
    for (int i = tid; i < 128*16; i += NTHR){
        int t = i>>4, c4 = (i&15)*4;
        float gv = d_g[b*LL + cc*CH + t];
        float4 v = *(const float4*)&d_v[((size_t)(b*LL + cc*CH + t))*DD + ds*64 + c4];
        v.x = f2tf_as_f(v.x*gv); v.y = f2tf_as_f(v.y*gv);
        v.z = f2tf_as_f(v.z*gv); v.w = f2tf_as_f(v.w*gv);
        *(float4*)&sV[t*72 + c4] = v;
    }
    __syncthreads();

    // scores: 16 warps, 4x4 layout; warps with wn > wm are fully masked
    const int wm = wid >> 2;
    const int wn = wid & 3;
    if (wn > wm){
        #pragma unroll
        for (int mt=0; mt<2; mt++)
            #pragma unroll
            for (int nt=0; nt<4; nt++)
                #pragma unroll
                for (int half=0; half<2; half++){
                    int row = wm*32 + mt*16 + grp + half*8;
                    int col = wn*32 + nt*8 + 2*tig;
                    *(float2*)&sS[row*132 + col] = make_float2(0.f, 0.f);
                }
        return;
    }
    float acc2[2][4][4];
    #pragma unroll
    for (int mt=0;mt<2;mt++)
        #pragma unroll
        for (int nt=0;nt<4;nt++)
            #pragma unroll
            for (int i=0;i<4;i++) acc2[mt][nt][i]=0.f;
    const uint32_t qbase = shaddr(sQ) + ldsm_off(lane, wm*32, 68);
    #pragma unroll
    for (int ks = 0; ks < 64; ks += 8){
        uint32_t afr[2][4], bfr[4][2];
        #pragma unroll
        for (int mt=0; mt<2; mt++)
            ldsm4(afr[mt], qbase + (mt*16*68 + ks)*4);
        #pragma unroll
        for (int nt=0; nt<4; nt++){
            int cb = wn*32 + nt*8 + grp;
            bfr[nt][0] = fb(sKT[(ks + tig    )*136 + cb]);
            bfr[nt][1] = fb(sKT[(ks + tig + 4)*136 + cb]);
        }
        #pragma unroll
        for (int mt=0; mt<2; mt++)
            #pragma unroll
            for (int nt=0; nt<4; nt++)
                mma_tf32(acc2[mt][nt], afr[mt], bfr[nt]);
    }
    #pragma unroll
    for (int mt=0; mt<2; mt++)
        #pragma unroll
        for (int nt=0; nt<4; nt++)
            #pragma unroll
            for (int half=0; half<2; half++){
                int row = wm*32 + mt*16 + grp + half*8;
                int col = wn*32 + nt*8 + 2*tig;
                sS[row*132 + col    ] = (col   <= row) ? acc2[mt][nt][half*2  ] : 0.f;
                sS[row*132 + col + 1] = (col+1 <= row) ? acc2[mt][nt][half*2+1] : 0.f;
            }
}

// ---------------- chunk out part 2: load prefix + causal-bounded S@V + Q@P ----------------
__device__ void chunk_out_av(int cc, int ds, int b, float* sm){
    float* sQ  = sm;
    float* sKT = sQ + 128*68;
    float* sS  = sKT + 64*136;
    float* sV  = sS + 128*132;
    float* sP  = sV + 128*72;
    const int tid = threadIdx.x;
    const int wid = tid >> 5, lane = tid & 31;
    const int grp = lane >> 2, tig = lane & 3;

    size_t pbase = ((size_t)(b*NCH + cc))*64*DD;
    for (int i = tid; i < 64*16; i += NTHR){
        int p = i>>4, c4 = (i&15)*4;
        float4 v = *(const float4*)&d_pref[pbase + (size_t)p*DD + ds*64 + c4];
        v.x = f2tf_as_f(v.x); v.y = f2tf_as_f(v.y);
        v.z = f2tf_as_f(v.z); v.w = f2tf_as_f(v.w);
        *(float4*)&sP[p*72 + c4] = v;
    }
    __syncthreads();

    const int wm = wid >> 1;
    const int wn = wid & 1;
    float acc[4][4];
    #pragma unroll
    for (int nt=0;nt<4;nt++)
        #pragma unroll
        for (int i=0;i<4;i++) acc[nt][i]=0.f;

    // S@V with causal bound: rows of warp wm have zero S beyond col wm*16+15
    const uint32_t sbase = shaddr(sS) + ldsm_off(lane, wm*16, 132);
    const int kmax = (wm+1)*16;
    #pragma unroll 2
    for (int ks = 0; ks < kmax; ks += 8){
        uint32_t afr[4], bfr[4][2];
        ldsm4(afr, sbase + ks*4);
        #pragma unroll
        for (int nt=0; nt<4; nt++){
            int cb = wn*32 + nt*8 + grp;
            bfr[nt][0] = fb(sV[(ks + tig    )*72 + cb]);
            bfr[nt][1] = fb(sV[(ks + tig + 4)*72 + cb]);
        }
        #pragma unroll
        for (int nt=0; nt<4; nt++)
            mma_tf32(acc[nt], afr, bfr[nt]);
    }
    const uint32_t qb2 = shaddr(sQ) + ldsm_off(lane, wm*16, 68);
    #pragma unroll
    for (int ks = 0; ks < 64; ks += 8){
        uint32_t afr[4], bfr[4][2];
        ldsm4(afr, qb2 + ks*4);
        #pragma unroll
        for (int nt=0; nt<4; nt++){
            int cb = wn*32 + nt*8 + grp;
            bfr[nt][0] = fb(sP[(ks + tig    )*72 + cb]);
            bfr[nt][1] = fb(sP[(ks + tig + 4)*72 + cb]);
        }
        #pragma unroll
        for (int nt=0; nt<4; nt++)
            mma_tf32(acc[nt], afr, bfr[nt]);
    }

    int slot = ds*2 + wn;
    #pragma unroll
    for (int half=0; half<2; half++){
        int rloc = wm*16 + grp + half*8;
        int gtok = b*LL + cc*CH + rloc;
        float sc = rsqrtf(fmaxf(d_gc[gtok], 1.f)) * 0.17677669529663687f;
        float s = 0.f, ss = 0.f;
        #pragma unroll
        for (int nt=0; nt<4; nt++){
            int col = wn*32 + nt*8 + 2*tig;
            float v0 = acc[nt][half*2+0]*sc;
            float v1 = acc[nt][half*2+1]*sc;
            *(float2*)&d_ret[(size_t)gtok*DD + ds*64 + col] = make_float2(v0, v1);
            s += v0 + v1; ss += v0*v0 + v1*v1;
        }
        s  += __shfl_xor_sync(0xffffffffu, s, 1);
        s  += __shfl_xor_sync(0xffffffffu, s, 2);
        ss += __shfl_xor_sync(0xffffffffu, ss, 1);
        ss += __shfl_xor_sync(0xffffffffu, ss, 2);
        if (tig == 0){
            d_s1[slot*NTOK + gtok] = s;
            d_s2[slot*NTOK + gtok] = ss;
        }
    }
}

// ---------------- mega kernel ----------------
#define MEGA_SMEM ((128*68 + 64*136 + 128*132 + 128*72 + 64*72)*(int)sizeof(float))

__global__ void __launch_bounds__(NTHR, 1)
mega_kernel(const float* __restrict__ x,
            const float* __restrict__ Wk,  const float* __restrict__ bk,
            const float* __restrict__ Wv,  const float* __restrict__ bv,
            const float* __restrict__ Wg1, const float* __restrict__ bg1,
            const float* __restrict__ Wg2, const float* __restrict__ bg2,
            const float* __restrict__ ln1g,const float* __restrict__ ln1b,
            const float* __restrict__ Wr1, const float* __restrict__ br1,
            const float* __restrict__ Wr2, const float* __restrict__ br2,
            const float* __restrict__ ln2g,const float* __restrict__ ln2b,
            const float* __restrict__ Wo,  const float* __restrict__ bo,
            float* __restrict__ out)
{
    extern __shared__ __align__(16) float smem[];
    const int blk = blockIdx.x;
    const int m0 = (blk & 31)*128;
    const int n0 = (blk >> 5)*64;

    // Phase A: fused gate + value GEMM, then phases
    gemm_tile_a(smem, x, Wg1, bg1, Wg2, d_gpart, Wv, bv, d_v, m0, n0);
    phases_job(blk, x, Wk, bk, smem);
    gbar();

    // Phase B||C: blocks 0-1 run the scan; all blocks compute states with local g
    if (blk < BB) cumsum_job(blk, bg2, smem);
    __syncthreads();
    chunk_state_job((blk >> 2) & 15, blk >> 6, blk & 3, bg2, smem);
    gbar();

    // Phase D||E part 1: blocks 0-15 do the prefix; all blocks load tiles + scores
    if (blk < 16) chunk_prefix_job(blk >> 3, blk & 7);
    chunk_out_scores((blk >> 2) & 15, blk & 3, blk >> 6, smem);
    gbar();   // prefix + scores complete everywhere

    // Phase E part 2: prefix load + causal-bounded AV
    chunk_out_av((blk >> 2) & 15, blk & 3, blk >> 6, smem);
    gbar();

    // Phase F: dual-N fused (one K pass, A LN'd once)
    gemm_tile_f(smem, d_ret, Wr1, br1, d_t1,
        d_s1, d_s2, ln1g, ln1b, m0, n0);
    gbar();

    // Phase G
    gemm_tile<A_PLAIN, E_STAT>(smem, d_t1, Wr2, br2, d_t2, nullptr,
        nullptr, nullptr, nullptr, nullptr, d_s1b, d_s2b,
        m0, n0, NTOK, DD, 2*DD);
    gbar();

    // Phase H
    gemm_tile<A_LN, E_OUT>(smem, d_t2, Wo, bo, out, x,
        d_s1b, d_s2b, ln2g, ln2b, nullptr, nullptr,
        m0, n0, NTOK, DD, DD);
}

// ---------------- launch ----------------
extern "C" void kernel_launch(void* const* d_in, const int* in_sizes, int n_in,
                              void* d_out, int out_size)
{
    const float* x    = (const float*)d_in[0];
    const float* Wk   = (const float*)d_in[1];
    const float* bk   = (const float*)d_in[2];
    const float* Wv   = (const float*)d_in[3];
    const float* bv   = (const float*)d_in[4];
    const float* Wg1  = (const float*)d_in[5];
    const float* bg1  = (const float*)d_in[6];
    const float* Wg2  = (const float*)d_in[7];
    const float* bg2  = (const float*)d_in[8];
    const float* ln1g = (const float*)d_in[9];
    const float* ln1b = (const float*)d_in[10];
    const float* Wr1  = (const float*)d_in[11];
    const float* br1  = (const float*)d_in[12];
    const float* Wr2  = (const float*)d_in[13];
    const float* br2  = (const float*)d_in[14];
    const float* ln2g = (const float*)d_in[15];
    const float* ln2b = (const float*)d_in[16];
    const float* Wo   = (const float*)d_in[17];
    const float* bo   = (const float*)d_in[18];
    float* out = (float*)d_out;

    static bool init = false;
    if (!init){
        cudaFuncSetAttribute(mega_kernel, cudaFuncAttributeMaxDynamicSharedMemorySize, MEGA_SMEM);
        init = true;
    }

    mega_kernel<<<NBLK, NTHR, MEGA_SMEM>>>(
        x, Wk, bk, Wv, bv, Wg1, bg1, Wg2, bg2,
        ln1g, ln1b, Wr1, br1, Wr2, br2, ln2g, ln2b, Wo, bo, out);
    (void)in_sizes; (void)n_in; (void)out_size;
}